// round 4
// baseline (speedup 1.0000x reference)
#include <cuda_runtime.h>

typedef unsigned long long u64;
typedef unsigned int u32;

#define T_FRAMES 5
#define WS 8
#define HEADS 6
#define DIM 192
#define HDIM 32
#define NTOK 320
#define KROW 36   // padded row (floats) for K/V smem tiles

// scratch: per-window attention output, [wb][n][DIM], sized for B=2
__device__ float g_scratch[2 * 64 * NTOK * DIM];

// ---------------- f32x2 helpers (sm_100+ packed fp32) ----------------
__device__ __forceinline__ u64 pack2(float lo, float hi) {
    u64 r; asm("mov.b64 %0,{%1,%2};" : "=l"(r) : "f"(lo), "f"(hi)); return r;
}
__device__ __forceinline__ void unpack2(u64 v, float &lo, float &hi) {
    asm("mov.b64 {%0,%1},%2;" : "=f"(lo), "=f"(hi) : "l"(v));
}
__device__ __forceinline__ u64 add2(u64 a, u64 b) {
    u64 r; asm("add.rn.f32x2 %0,%1,%2;" : "=l"(r) : "l"(a), "l"(b)); return r;
}
__device__ __forceinline__ void fma2(u64 &d, u64 a, u64 b) {
    asm("fma.rn.f32x2 %0,%1,%2,%0;" : "+l"(d) : "l"(a), "l"(b));
}
__device__ __forceinline__ void lds2(u64 &a, u64 &b, u32 sa) {
    asm("ld.shared.v2.b64 {%0,%1},[%2];" : "=l"(a), "=l"(b) : "r"(sa) : "memory");
}
__device__ __forceinline__ u64 lds64(u32 sa) {
    u64 r; asm("ld.shared.b64 %0,[%1];" : "=l"(r) : "r"(sa) : "memory"); return r;
}

// ---------------- attention kernel ----------------
// 640 threads: 2 threads per query, each owns 16 of the 32 head dims.
// smem layout (floats): K tile | V tile | bias column | token meta
#define SM_V    (NTOK * KROW)
#define SM_BIAS (2 * NTOK * KROW)
#define SM_META (SM_BIAS + 1185)
#define ATTN_SMEM ((SM_META + NTOK) * 4)

__global__ void __launch_bounds__(640)
attn_kernel(const float* __restrict__ qkv, const float* __restrict__ bias_table)
{
    extern __shared__ float sm[];
    float* k_s    = sm;
    float* v_s    = sm + SM_V;
    float* bias_s = sm + SM_BIAS;
    int*   meta_s = (int*)(sm + SM_META);

    const int head = blockIdx.y;
    const int wb   = blockIdx.x;          // b*64 + widx
    const int b    = wb >> 6;
    const int widx = wb & 63;
    const int hw = widx >> 3, ww = widx & 7;

    const int tid = threadIdx.x;
    const int qi  = tid >> 1;             // query token 0..319
    const int hf  = tid & 1;              // half: dims [hf*16, hf*16+16)
    const int t   = qi >> 6;
    const int hs  = (qi >> 3) & 7;
    const int wsv = qi & 7;
    const int Hp = hw * 8 + hs;           // shifted-frame coords
    const int Wp = ww * 8 + wsv;
    const int h = (Hp + 4) & 63;          // un-shift: roll(-4) gather
    const int w = (Wp + 4) & 63;
    // Swin shift mask regions (computed, not loaded)
    const int rh = (Hp < 56) ? 0 : ((Hp < 60) ? 1 : 2);
    const int rw = (Wp < 56) ? 0 : ((Wp < 60) ? 1 : 2);
    const int r_i = rh * 3 + rw;
    const int bj  = t * 15 + hs + wsv;    // rel-bias component
    meta_s[qi] = bj | (r_i << 8);         // both halves write same value

    const int row = ((b * T_FRAMES + t) << 12) + (h << 6) + w;
    const float* qp = qkv + (size_t)row * (3 * DIM) + head * HDIM;

    // K, V rows into smem — cooperative, coalesced: 16 consecutive threads
    // stage one token row (8 K float4s + 8 V float4s).
    {
        const int bT = b * T_FRAMES;
        #pragma unroll
        for (int it = 0; it < 8; ++it) {
            const int lin = it * 640 + tid;    // 0..5119
            const int r   = lin >> 4;
            const int g   = lin & 15;
            const int rt  = r >> 6;
            const int rhs = (r >> 3) & 7;
            const int rws = r & 7;
            const int rh_ = (hw * 8 + rhs + 4) & 63;
            const int rw_ = (ww * 8 + rws + 4) & 63;
            const float* rowp = qkv + (size_t)(((bT + rt) << 12) + (rh_ << 6) + rw_) * (3 * DIM)
                                + head * HDIM;
            const int gg = g & 7;
            const float4 val = ((const float4*)(rowp + DIM + ((g >= 8) ? DIM : 0)))[gg];
            float* dst = ((g >= 8) ? v_s : k_s) + r * KROW;
            ((float4*)dst)[gg] = val;
        }
    }
    const float LOG2E = 1.4426950408889634f;
    for (int idx = tid; idx < 1185; idx += 640)
        bias_s[idx] = bias_table[idx * HEADS + head] * LOG2E;

    // q half into registers, pre-scaled by SCALE * log2(e)
    const float qs_f = 0.17677669529663687f * LOG2E;
    u64 q[8];
    {
        const float4* qv = (const float4*)(qp + hf * 16);
        #pragma unroll
        for (int m = 0; m < 4; ++m) {
            float4 f = qv[m];
            q[2 * m]     = pack2(f.x * qs_f, f.y * qs_f);
            q[2 * m + 1] = pack2(f.z * qs_f, f.w * qs_f);
        }
    }
    __syncthreads();

    const u32 kbase = (u32)__cvta_generic_to_shared(k_s) + hf * 64;

    u64 acc[8];
    #pragma unroll
    for (int m = 0; m < 8; ++m) acc[m] = 0ULL;
    float l = 0.f;
    const int a_i = bj + 112;

    #pragma unroll 1
    for (int j = 0; j < NTOK; ++j) {
        const u32 ka = kbase + j * (KROW * 4);
        const u32 va = ka + SM_V * 4;
        // K half-row
        u64 kr[8];
        lds2(kr[0], kr[1], ka);
        lds2(kr[2], kr[3], ka + 16);
        lds2(kr[4], kr[5], ka + 32);
        lds2(kr[6], kr[7], ka + 48);
        const int mj = meta_s[j];
        u64 d0 = 0, d1 = 0;
        fma2(d0, q[0], kr[0]); fma2(d1, q[1], kr[1]);
        fma2(d0, q[2], kr[2]); fma2(d1, q[3], kr[3]);
        fma2(d0, q[4], kr[4]); fma2(d1, q[5], kr[5]);
        fma2(d0, q[6], kr[6]); fma2(d1, q[7], kr[7]);
        // V half-row (independent of dot; overlaps shfl latency)
        u64 vr[8];
        lds2(vr[0], vr[1], va);
        lds2(vr[2], vr[3], va + 16);
        lds2(vr[4], vr[5], va + 32);
        lds2(vr[6], vr[7], va + 48);
        u64 e = add2(d0, d1);
        float sx, sy; unpack2(e, sx, sy);
        const float sh_ = sx + sy;                     // this half's partial
        const float so_ = __shfl_xor_sync(0xffffffffu, sh_, 1);
        const float s = sh_ + so_ + bias_s[a_i - (mj & 255)];
        float p; asm("ex2.approx.ftz.f32 %0,%1;" : "=f"(p) : "f"(s));
        p = ((mj >> 8) == r_i) ? p : 0.f;   // mask: exclude cross-region keys
        l += p;
        const u64 pp = pack2(p, p);
        fma2(acc[0], vr[0], pp); fma2(acc[1], vr[1], pp);
        fma2(acc[2], vr[2], pp); fma2(acc[3], vr[3], pp);
        fma2(acc[4], vr[4], pp); fma2(acc[5], vr[5], pp);
        fma2(acc[6], vr[6], pp); fma2(acc[7], vr[7], pp);
    }

    const float inv = 1.0f / l;
    float4* op = (float4*)(g_scratch + ((size_t)(wb * NTOK + qi)) * DIM
                           + head * HDIM + hf * 16);
    #pragma unroll
    for (int m = 0; m < 4; ++m) {
        float x0, x1, x2, x3;
        unpack2(acc[2 * m],     x0, x1);
        unpack2(acc[2 * m + 1], x2, x3);
        op[m] = make_float4(x0 * inv, x1 * inv, x2 * inv, x3 * inv);
    }
}

// ---------------- projection + window-reverse kernel ----------------
// 512 threads (16 warps, 4/SMSP). Warp w owns output channels [w*12, w*12+12).
// W staged ONCE per persistent CTA: [192][WPAD] c-major. W reads are
// warp-uniform broadcasts; o reads lane-strided conflict-free (194 words).
#define WPAD 194
#define PROJ_SMEM ((DIM * WPAD + 64 * WPAD) * 4)

__global__ void __launch_bounds__(512)
proj_kernel(const float* __restrict__ pw, const float* __restrict__ pb,
            float* __restrict__ out, int nchunks)
{
    extern __shared__ float sm[];
    float* Wsh = sm;                 // [192][WPAD]
    float* o_s = sm + DIM * WPAD;    // [64][WPAD]
    const int tid = threadIdx.x, tx = tid & 31, wid = tid >> 5;
    const int c0 = wid * 12;

    // stage full W once (float2, coalesced)
    for (int idx = tid; idx < DIM * 96; idx += 512) {
        const int c = idx / 96, kk = idx % 96;
        float2 v = *(const float2*)(pw + c * DIM + kk * 2);
        *(float2*)(Wsh + c * WPAD + kk * 2) = v;
    }
    float pbv[12];
    #pragma unroll
    for (int j = 0; j < 12; ++j) pbv[j] = pb[c0 + j];

    const u32 wbase = (u32)__cvta_generic_to_shared(Wsh) + c0 * (WPAD * 4);
    const u32 obase = (u32)__cvta_generic_to_shared(o_s) + tx * (WPAD * 4);

    for (int ci = blockIdx.x; ci < nchunks; ci += gridDim.x) {
        __syncthreads();   // W staged (first iter) / previous chunk consumed
        // stage o chunk [64 tokens][192 k] as float2
        const float* src = g_scratch + (size_t)ci * (64 * DIM);  // ci = wb*5 + t
        #pragma unroll
        for (int it = 0; it < 12; ++it) {
            const int idx = tid + it * 512;
            const int tok = idx / 96, kk = idx % 96;
            float2 v = *(const float2*)(src + tok * DIM + kk * 2);
            *(float2*)(o_s + tok * WPAD + kk * 2) = v;
        }
        __syncthreads();

        u64 acc0[12], acc1[12];
        #pragma unroll
        for (int j = 0; j < 12; ++j) { acc0[j] = 0ULL; acc1[j] = 0ULL; }

        #pragma unroll 1
        for (int k2 = 0; k2 < 96; ++k2) {
            u64 w2[12];
            #pragma unroll
            for (int j = 0; j < 12; ++j)
                w2[j] = lds64(wbase + (u32)(j * WPAD * 4) + k2 * 8);  // broadcast
            const u64 o0 = lds64(obase + k2 * 8);
            const u64 o1 = lds64(obase + 32 * (WPAD * 4) + k2 * 8);
            #pragma unroll
            for (int j = 0; j < 12; ++j) fma2(acc0[j], o0, w2[j]);
            #pragma unroll
            for (int j = 0; j < 12; ++j) fma2(acc1[j], o1, w2[j]);
        }

        const int wbid = ci / 5, t = ci % 5;
        const int b = wbid >> 6, widx = wbid & 63;
        const int hw = widx >> 3, ww = widx & 7;
        #pragma unroll
        for (int half = 0; half < 2; ++half) {
            const int tok = tx + half * 32;
            const int hs = tok >> 3, wsv = tok & 7;
            const int h = (hw * 8 + hs + 4) & 63;
            const int w = (ww * 8 + wsv + 4) & 63;
            float* orow = out + ((size_t)((b * T_FRAMES + t) * 4096 + h * 64 + w)) * DIM + c0;
            const u64* a = half ? acc1 : acc0;
            #pragma unroll
            for (int f4 = 0; f4 < 3; ++f4) {
                float r[4];
                #pragma unroll
                for (int e = 0; e < 4; ++e) {
                    float lo, hi; unpack2(a[f4 * 4 + e], lo, hi);
                    r[e] = lo + hi + pbv[f4 * 4 + e];
                }
                *(float4*)(orow + f4 * 4) = make_float4(r[0], r[1], r[2], r[3]);
            }
        }
    }
}

// ---------------- launch ----------------
extern "C" void kernel_launch(void* const* d_in, const int* in_sizes, int n_in,
                              void* d_out, int out_size)
{
    const float* qkv        = (const float*)d_in[0];
    const float* bias_table = (const float*)d_in[1];
    const float* pw         = (const float*)d_in[2];
    const float* pb         = (const float*)d_in[3];
    float* out = (float*)d_out;

    int B = in_sizes[0] / (T_FRAMES * 64 * 64 * 3 * DIM);
    if (B < 1) B = 1;
    if (B > 2) B = 2;   // scratch sized for B=2 (problem fixed at B=2)

    cudaFuncSetAttribute(attn_kernel, cudaFuncAttributeMaxDynamicSharedMemorySize, ATTN_SMEM);
    cudaFuncSetAttribute(proj_kernel, cudaFuncAttributeMaxDynamicSharedMemorySize, PROJ_SMEM);

    dim3 ag(B * 64, HEADS);
    attn_kernel<<<ag, 640, ATTN_SMEM>>>(qkv, bias_table);

    const int nchunks = B * 64 * T_FRAMES;
    int pgrid = nchunks < 148 ? nchunks : 148;
    proj_kernel<<<pgrid, 512, PROJ_SMEM>>>(pw, pb, out, nchunks);
}

// round 5
// speedup vs baseline: 1.9532x; 1.9532x over previous
#include <cuda_runtime.h>
#include <cuda_bf16.h>

typedef unsigned long long u64;
typedef unsigned int u32;

#define T_FRAMES 5
#define WS 8
#define HEADS 6
#define DIM 192
#define HDIM 32
#define NTOK 320

// scratch: per-window attention output, [wb][n][DIM], sized for B=2
__device__ float g_scratch[2 * 64 * NTOK * DIM];

// ---------------- small helpers ----------------
__device__ __forceinline__ u64 pack2(float lo, float hi) {
    u64 r; asm("mov.b64 %0,{%1,%2};" : "=l"(r) : "f"(lo), "f"(hi)); return r;
}
__device__ __forceinline__ void unpack2(u64 v, float &lo, float &hi) {
    asm("mov.b64 {%0,%1},%2;" : "=f"(lo), "=f"(hi) : "l"(v));
}
__device__ __forceinline__ void fma2(u64 &d, u64 a, u64 b) {
    asm("fma.rn.f32x2 %0,%1,%2,%0;" : "+l"(d) : "l"(a), "l"(b));
}
__device__ __forceinline__ u32 lds32(u32 a) {
    u32 r; asm("ld.shared.b32 %0,[%1];" : "=r"(r) : "r"(a)); return r;
}
__device__ __forceinline__ float lds32f(u32 a) {
    float r; asm("ld.shared.b32 %0,[%1];" : "=f"(r) : "r"(a)); return r;
}
__device__ __forceinline__ u64 lds64(u32 sa) {
    u64 r; asm("ld.shared.b64 %0,[%1];" : "=l"(r) : "r"(sa) : "memory"); return r;
}
// pack two f32 into bf16x2: low half = lo
__device__ __forceinline__ u32 cvt2(float lo, float hi) {
    u32 r; asm("cvt.rn.bf16x2.f32 %0,%1,%2;" : "=r"(r) : "f"(hi), "f"(lo)); return r;
}
__device__ __forceinline__ void mma16816(float &c0, float &c1, float &c2, float &c3,
                                         u32 a0, u32 a1, u32 a2, u32 a3,
                                         u32 b0, u32 b1) {
    asm("mma.sync.aligned.m16n8k16.row.col.f32.bf16.bf16.f32 "
        "{%0,%1,%2,%3},{%4,%5,%6,%7},{%8,%9},{%0,%1,%2,%3};"
        : "+f"(c0), "+f"(c1), "+f"(c2), "+f"(c3)
        : "r"(a0), "r"(a1), "r"(a2), "r"(a3), "r"(b0), "r"(b1));
}
// split f32 pair into bf16x2 hi + bf16x2 lo (residual)
__device__ __forceinline__ void split_pair(float a, float b, u32 &h, u32 &l) {
    __nv_bfloat162 hv = __floats2bfloat162_rn(a, b);
    h = *(u32*)&hv;
    float ra = a - __bfloat162float(hv.x);
    float rb = b - __bfloat162float(hv.y);
    __nv_bfloat162 lv = __floats2bfloat162_rn(ra, rb);
    l = *(u32*)&lv;
}

// ---------------- attention kernel (tensor cores, bf16-split) ----------------
// smem byte offsets. Q/K rows padded to 40 bf16 (80B); Vt rows 328 bf16 (656B).
#define ROWB 80
#define VTB  656
#define OFF_QH   0
#define OFF_QL   25600
#define OFF_KH   51200
#define OFF_KL   76800
#define OFF_VTH  102400
#define OFF_VTL  123392
#define OFF_BIAS 144384
#define OFF_META 149124
#define ATTN_SMEM (150404)

__global__ void __launch_bounds__(320)
attn_kernel(const float* __restrict__ qkv, const float* __restrict__ bias_table)
{
    extern __shared__ char smc[];
    const u32 smb = (u32)__cvta_generic_to_shared(smc);
    int* meta_s = (int*)(smc + OFF_META);

    const int head = blockIdx.y;
    const int wb   = blockIdx.x;          // b*64 + widx
    const int b    = wb >> 6;
    const int widx = wb & 63;
    const int hw = widx >> 3, ww = widx & 7;

    const int tid  = threadIdx.x;         // 0..319, thread = token for staging
    const int lane = tid & 31;
    const int warp = tid >> 5;            // 0..9
    const int g    = lane >> 2;           // mma group id
    const int t4   = lane & 3;
    const int wr   = warp * 32;           // this warp's query rows

    // token coords for staging (thread tid stages token tid)
    const int t   = tid >> 6;
    const int hs  = (tid >> 3) & 7;
    const int wsv = tid & 7;
    const int Hp = hw * 8 + hs;
    const int Wp = ww * 8 + wsv;
    const int h = (Hp + 4) & 63;
    const int w = (Wp + 4) & 63;
    const int rh = (Hp < 56) ? 0 : ((Hp < 60) ? 1 : 2);
    const int rw = (Wp < 56) ? 0 : ((Wp < 60) ? 1 : 2);
    meta_s[tid] = (t * 15 + hs + wsv) | ((rh * 3 + rw) << 8);

    const int row = ((b * T_FRAMES + t) << 12) + (h << 6) + w;
    const float* qp = qkv + (size_t)row * (3 * DIM) + head * HDIM;

    const float LOG2E = 1.4426950408889634f;
    const float qs_f = 0.17677669529663687f * LOG2E;

    // ---- stage Q (scaled) and K split into smem rows ----
    {
        const float4* qv = (const float4*)qp;
        const float4* kv = (const float4*)(qp + DIM);
        const float4* vv = (const float4*)(qp + 2 * DIM);
        #pragma unroll
        for (int m = 0; m < 8; ++m) {
            float4 f = qv[m];
            u32 h0, l0, h1, l1;
            split_pair(f.x * qs_f, f.y * qs_f, h0, l0);
            split_pair(f.z * qs_f, f.w * qs_f, h1, l1);
            const int off = tid * ROWB + m * 8;
            *(u32*)(smc + OFF_QH + off) = h0;  *(u32*)(smc + OFF_QH + off + 4) = h1;
            *(u32*)(smc + OFF_QL + off) = l0;  *(u32*)(smc + OFF_QL + off + 4) = l1;
        }
        #pragma unroll
        for (int m = 0; m < 8; ++m) {
            float4 f = kv[m];
            u32 h0, l0, h1, l1;
            split_pair(f.x, f.y, h0, l0);
            split_pair(f.z, f.w, h1, l1);
            const int off = tid * ROWB + m * 8;
            *(u32*)(smc + OFF_KH + off) = h0;  *(u32*)(smc + OFF_KH + off + 4) = h1;
            *(u32*)(smc + OFF_KL + off) = l0;  *(u32*)(smc + OFF_KL + off + 4) = l1;
        }
        // V transposed: Vt[dim][token]
        #pragma unroll
        for (int m = 0; m < 8; ++m) {
            float4 f = vv[m];
            float vals[4] = {f.x, f.y, f.z, f.w};
            #pragma unroll
            for (int e = 0; e < 4; ++e) {
                const int d = m * 4 + e;
                __nv_bfloat16 vh = __float2bfloat16_rn(vals[e]);
                float rsd = vals[e] - __bfloat162float(vh);
                __nv_bfloat16 vl = __float2bfloat16_rn(rsd);
                *(__nv_bfloat16*)(smc + OFF_VTH + d * VTB + tid * 2) = vh;
                *(__nv_bfloat16*)(smc + OFF_VTL + d * VTB + tid * 2) = vl;
            }
        }
    }
    for (int idx = tid; idx < 1185; idx += 320)
        *(float*)(smc + OFF_BIAS + idx * 4) = bias_table[idx * HEADS + head] * LOG2E;

    __syncthreads();

    // per-thread row constants (4 rows this thread touches per accum layout)
    int ai[2][2], ri[2][2];
    #pragma unroll
    for (int mt = 0; mt < 2; ++mt)
        #pragma unroll
        for (int hh = 0; hh < 2; ++hh) {
            int mv = meta_s[wr + 16 * mt + g + 8 * hh];
            ai[mt][hh] = (mv & 255) + 112;
            ri[mt][hh] = mv >> 8;
        }

    // ---- Q A-fragments into registers (hi/lo × 2 mtiles × 2 ktiles × 4 regs) ----
    u32 qa[2][2][2][4];
    #pragma unroll
    for (int s = 0; s < 2; ++s) {
        const u32 base = smb + (s ? OFF_QL : OFF_QH);
        #pragma unroll
        for (int mt = 0; mt < 2; ++mt) {
            const u32 r0 = base + (wr + 16 * mt + g) * ROWB + t4 * 4;
            #pragma unroll
            for (int kt = 0; kt < 2; ++kt) {
                const u32 a = r0 + kt * 32;
                qa[s][mt][kt][0] = lds32(a);
                qa[s][mt][kt][1] = lds32(a + 8 * ROWB);
                qa[s][mt][kt][2] = lds32(a + 16);
                qa[s][mt][kt][3] = lds32(a + 8 * ROWB + 16);
            }
        }
    }

    const u32 khb = smb + OFF_KH, klb = smb + OFF_KL;
    const u32 vhb = smb + OFF_VTH, vlb = smb + OFF_VTL;
    const u32 bib = smb + OFF_BIAS;

    float oacc[2][4][4];
    #pragma unroll
    for (int mt = 0; mt < 2; ++mt)
        #pragma unroll
        for (int n = 0; n < 4; ++n)
            #pragma unroll
            for (int e = 0; e < 4; ++e) oacc[mt][n][e] = 0.f;
    float lsum[2][2] = {{0.f, 0.f}, {0.f, 0.f}};

    #pragma unroll 1
    for (int jc = 0; jc < 10; ++jc) {
        const int jb = jc * 32;
        float sacc[2][4][4];
        #pragma unroll
        for (int mt = 0; mt < 2; ++mt)
            #pragma unroll
            for (int n = 0; n < 4; ++n)
                #pragma unroll
                for (int e = 0; e < 4; ++e) sacc[mt][n][e] = 0.f;

        // ---- S = Q K^T (3-mma bf16 split) ----
        #pragma unroll
        for (int kt = 0; kt < 2; ++kt) {
            #pragma unroll
            for (int n = 0; n < 4; ++n) {
                const u32 off = (jb + 8 * n + g) * ROWB + t4 * 4 + kt * 32;
                const u32 bh0 = lds32(khb + off), bh1 = lds32(khb + off + 16);
                const u32 bl0 = lds32(klb + off), bl1 = lds32(klb + off + 16);
                #pragma unroll
                for (int mt = 0; mt < 2; ++mt) {
                    float* c = sacc[mt][n];
                    mma16816(c[0], c[1], c[2], c[3],
                             qa[0][mt][kt][0], qa[0][mt][kt][1], qa[0][mt][kt][2], qa[0][mt][kt][3],
                             bh0, bh1);
                    mma16816(c[0], c[1], c[2], c[3],
                             qa[0][mt][kt][0], qa[0][mt][kt][1], qa[0][mt][kt][2], qa[0][mt][kt][3],
                             bl0, bl1);
                    mma16816(c[0], c[1], c[2], c[3],
                             qa[1][mt][kt][0], qa[1][mt][kt][1], qa[1][mt][kt][2], qa[1][mt][kt][3],
                             bh0, bh1);
                }
            }
        }

        // ---- softmax (bias + mask + ex2), accumulate row sums ----
        #pragma unroll
        for (int n = 0; n < 4; ++n) {
            const int j0 = jb + 8 * n + 2 * t4;
            const int mj0 = meta_s[j0], mj1 = meta_s[j0 + 1];
            const int b0i = mj0 & 255, b1i = mj1 & 255;
            const int rj0 = mj0 >> 8,  rj1 = mj1 >> 8;
            #pragma unroll
            for (int mt = 0; mt < 2; ++mt) {
                float* c = sacc[mt][n];
                float s0 = c[0] + lds32f(bib + (ai[mt][0] - b0i) * 4);
                float s1 = c[1] + lds32f(bib + (ai[mt][0] - b1i) * 4);
                float s2 = c[2] + lds32f(bib + (ai[mt][1] - b0i) * 4);
                float s3 = c[3] + lds32f(bib + (ai[mt][1] - b1i) * 4);
                float p0, p1, p2, p3;
                asm("ex2.approx.ftz.f32 %0,%1;" : "=f"(p0) : "f"(s0));
                asm("ex2.approx.ftz.f32 %0,%1;" : "=f"(p1) : "f"(s1));
                asm("ex2.approx.ftz.f32 %0,%1;" : "=f"(p2) : "f"(s2));
                asm("ex2.approx.ftz.f32 %0,%1;" : "=f"(p3) : "f"(s3));
                p0 = (ri[mt][0] == rj0) ? p0 : 0.f;
                p1 = (ri[mt][0] == rj1) ? p1 : 0.f;
                p2 = (ri[mt][1] == rj0) ? p2 : 0.f;
                p3 = (ri[mt][1] == rj1) ? p3 : 0.f;
                c[0] = p0; c[1] = p1; c[2] = p2; c[3] = p3;
                lsum[mt][0] += p0 + p1;
                lsum[mt][1] += p2 + p3;
            }
        }

        // ---- P fragments (bf16 split) directly from S accumulators ----
        u32 pah[2][2][4], pal[2][2][4];
        #pragma unroll
        for (int mt = 0; mt < 2; ++mt)
            #pragma unroll
            for (int kt = 0; kt < 2; ++kt) {
                const float* cA = sacc[mt][2 * kt];
                const float* cB = sacc[mt][2 * kt + 1];
                const float px[8] = {cA[0], cA[1], cA[2], cA[3], cB[0], cB[1], cB[2], cB[3]};
                #pragma unroll
                for (int e = 0; e < 4; ++e) {
                    float x = px[2 * e], y = px[2 * e + 1];
                    u32 hh = cvt2(x, y);
                    float rx = x - __uint_as_float(hh << 16);
                    float ry = y - __uint_as_float(hh & 0xffff0000u);
                    pah[mt][kt][e] = hh;
                    pal[mt][kt][e] = cvt2(rx, ry);
                }
            }

        // ---- O += P V (3-mma bf16 split) ----
        #pragma unroll
        for (int kt = 0; kt < 2; ++kt) {
            #pragma unroll
            for (int n = 0; n < 4; ++n) {
                const u32 off = (8 * n + g) * VTB + (jb / 2 + 8 * kt + t4) * 4;
                const u32 bh0 = lds32(vhb + off), bh1 = lds32(vhb + off + 16);
                const u32 bl0 = lds32(vlb + off), bl1 = lds32(vlb + off + 16);
                #pragma unroll
                for (int mt = 0; mt < 2; ++mt) {
                    float* c = oacc[mt][n];
                    mma16816(c[0], c[1], c[2], c[3],
                             pah[mt][kt][0], pah[mt][kt][1], pah[mt][kt][2], pah[mt][kt][3],
                             bh0, bh1);
                    mma16816(c[0], c[1], c[2], c[3],
                             pah[mt][kt][0], pah[mt][kt][1], pah[mt][kt][2], pah[mt][kt][3],
                             bl0, bl1);
                    mma16816(c[0], c[1], c[2], c[3],
                             pal[mt][kt][0], pal[mt][kt][1], pal[mt][kt][2], pal[mt][kt][3],
                             bh0, bh1);
                }
            }
        }
    }

    // ---- row-sum reduce across the 4 lanes of each row group ----
    #pragma unroll
    for (int mt = 0; mt < 2; ++mt)
        #pragma unroll
        for (int hh = 0; hh < 2; ++hh) {
            float v = lsum[mt][hh];
            v += __shfl_xor_sync(0xffffffffu, v, 1);
            v += __shfl_xor_sync(0xffffffffu, v, 2);
            lsum[mt][hh] = 1.0f / v;
        }

    // ---- write O to scratch ----
    #pragma unroll
    for (int mt = 0; mt < 2; ++mt)
        #pragma unroll
        for (int hh = 0; hh < 2; ++hh) {
            const int r = wr + 16 * mt + g + 8 * hh;
            float* orow = g_scratch + ((size_t)(wb * NTOK + r)) * DIM + head * HDIM;
            const float inv = lsum[mt][hh];
            #pragma unroll
            for (int n = 0; n < 4; ++n) {
                float2 v = make_float2(oacc[mt][n][2 * hh] * inv,
                                       oacc[mt][n][2 * hh + 1] * inv);
                *(float2*)(orow + 8 * n + 2 * t4) = v;
            }
        }
}

// ---------------- projection + window-reverse kernel (unchanged R4) ----------------
#define WPAD 194
#define PROJ_SMEM ((DIM * WPAD + 64 * WPAD) * 4)

__global__ void __launch_bounds__(512)
proj_kernel(const float* __restrict__ pw, const float* __restrict__ pb,
            float* __restrict__ out, int nchunks)
{
    extern __shared__ float sm[];
    float* Wsh = sm;                 // [192][WPAD]
    float* o_s = sm + DIM * WPAD;    // [64][WPAD]
    const int tid = threadIdx.x, tx = tid & 31, wid = tid >> 5;
    const int c0 = wid * 12;

    for (int idx = tid; idx < DIM * 96; idx += 512) {
        const int c = idx / 96, kk = idx % 96;
        float2 v = *(const float2*)(pw + c * DIM + kk * 2);
        *(float2*)(Wsh + c * WPAD + kk * 2) = v;
    }
    float pbv[12];
    #pragma unroll
    for (int j = 0; j < 12; ++j) pbv[j] = pb[c0 + j];

    const u32 wbase = (u32)__cvta_generic_to_shared(Wsh) + c0 * (WPAD * 4);
    const u32 obase = (u32)__cvta_generic_to_shared(o_s) + tx * (WPAD * 4);

    for (int ci = blockIdx.x; ci < nchunks; ci += gridDim.x) {
        __syncthreads();
        const float* src = g_scratch + (size_t)ci * (64 * DIM);
        #pragma unroll
        for (int it = 0; it < 12; ++it) {
            const int idx = tid + it * 512;
            const int tok = idx / 96, kk = idx % 96;
            float2 v = *(const float2*)(src + tok * DIM + kk * 2);
            *(float2*)(o_s + tok * WPAD + kk * 2) = v;
        }
        __syncthreads();

        u64 acc0[12], acc1[12];
        #pragma unroll
        for (int j = 0; j < 12; ++j) { acc0[j] = 0ULL; acc1[j] = 0ULL; }

        #pragma unroll 1
        for (int k2 = 0; k2 < 96; ++k2) {
            u64 w2[12];
            #pragma unroll
            for (int j = 0; j < 12; ++j)
                w2[j] = lds64(wbase + (u32)(j * WPAD * 4) + k2 * 8);
            const u64 o0 = lds64(obase + k2 * 8);
            const u64 o1 = lds64(obase + 32 * (WPAD * 4) + k2 * 8);
            #pragma unroll
            for (int j = 0; j < 12; ++j) fma2(acc0[j], o0, w2[j]);
            #pragma unroll
            for (int j = 0; j < 12; ++j) fma2(acc1[j], o1, w2[j]);
        }

        const int wbid = ci / 5, t = ci % 5;
        const int b = wbid >> 6, widx = wbid & 63;
        const int hw = widx >> 3, ww = widx & 7;
        #pragma unroll
        for (int half = 0; half < 2; ++half) {
            const int tok = tx + half * 32;
            const int hs = tok >> 3, wsv = tok & 7;
            const int h = (hw * 8 + hs + 4) & 63;
            const int w = (ww * 8 + wsv + 4) & 63;
            float* orow = out + ((size_t)((b * T_FRAMES + t) * 4096 + h * 64 + w)) * DIM + c0;
            const u64* a = half ? acc1 : acc0;
            #pragma unroll
            for (int f4 = 0; f4 < 3; ++f4) {
                float r[4];
                #pragma unroll
                for (int e = 0; e < 4; ++e) {
                    float lo, hi; unpack2(a[f4 * 4 + e], lo, hi);
                    r[e] = lo + hi + pbv[f4 * 4 + e];
                }
                *(float4*)(orow + f4 * 4) = make_float4(r[0], r[1], r[2], r[3]);
            }
        }
    }
}

// ---------------- launch ----------------
extern "C" void kernel_launch(void* const* d_in, const int* in_sizes, int n_in,
                              void* d_out, int out_size)
{
    const float* qkv        = (const float*)d_in[0];
    const float* bias_table = (const float*)d_in[1];
    const float* pw         = (const float*)d_in[2];
    const float* pb         = (const float*)d_in[3];
    float* out = (float*)d_out;

    int B = in_sizes[0] / (T_FRAMES * 64 * 64 * 3 * DIM);
    if (B < 1) B = 1;
    if (B > 2) B = 2;   // scratch sized for B=2

    cudaFuncSetAttribute(attn_kernel, cudaFuncAttributeMaxDynamicSharedMemorySize, ATTN_SMEM);
    cudaFuncSetAttribute(proj_kernel, cudaFuncAttributeMaxDynamicSharedMemorySize, PROJ_SMEM);

    dim3 ag(B * 64, HEADS);
    attn_kernel<<<ag, 320, ATTN_SMEM>>>(qkv, bias_table);

    const int nchunks = B * 64 * T_FRAMES;
    int pgrid = nchunks < 148 ? nchunks : 148;
    proj_kernel<<<pgrid, 512, PROJ_SMEM>>>(pw, pb, out, nchunks);
}

// round 6
// speedup vs baseline: 2.5558x; 1.3085x over previous
#include <cuda_runtime.h>
#include <cuda_bf16.h>

typedef unsigned long long u64;
typedef unsigned int u32;

#define T_FRAMES 5
#define WS 8
#define HEADS 6
#define DIM 192
#define HDIM 32
#define NTOK 320

// scratch: per-window attention output, [wb][n][DIM], sized for B=2
__device__ float g_scratch[2 * 64 * NTOK * DIM];

// ---------------- small helpers ----------------
__device__ __forceinline__ u32 lds32(u32 a) {
    u32 r; asm("ld.shared.b32 %0,[%1];" : "=r"(r) : "r"(a)); return r;
}
__device__ __forceinline__ u32 lds32v(u32 a) {   // volatile: smem rewritten per chunk
    u32 r; asm volatile("ld.shared.b32 %0,[%1];" : "=r"(r) : "r"(a)); return r;
}
__device__ __forceinline__ float lds32f(u32 a) {
    float r; asm("ld.shared.b32 %0,[%1];" : "=f"(r) : "r"(a)); return r;
}
// pack two f32 into bf16x2: low half = first arg
__device__ __forceinline__ u32 cvt2(float lo, float hi) {
    u32 r; asm("cvt.rn.bf16x2.f32 %0,%1,%2;" : "=r"(r) : "f"(hi), "f"(lo)); return r;
}
__device__ __forceinline__ void mma16816(float &c0, float &c1, float &c2, float &c3,
                                         u32 a0, u32 a1, u32 a2, u32 a3,
                                         u32 b0, u32 b1) {
    asm("mma.sync.aligned.m16n8k16.row.col.f32.bf16.bf16.f32 "
        "{%0,%1,%2,%3},{%4,%5,%6,%7},{%8,%9},{%0,%1,%2,%3};"
        : "+f"(c0), "+f"(c1), "+f"(c2), "+f"(c3)
        : "r"(a0), "r"(a1), "r"(a2), "r"(a3), "r"(b0), "r"(b1));
}
// split f32 pair into bf16x2 hi + bf16x2 lo (residual)
__device__ __forceinline__ void split_pair(float a, float b, u32 &h, u32 &l) {
    __nv_bfloat162 hv = __floats2bfloat162_rn(a, b);
    h = *(u32*)&hv;
    float ra = a - __bfloat162float(hv.x);
    float rb = b - __bfloat162float(hv.y);
    __nv_bfloat162 lv = __floats2bfloat162_rn(ra, rb);
    l = *(u32*)&lv;
}

// ---------------- attention kernel (tensor cores, bf16-split) ----------------
// smem byte offsets. Q/K rows padded to 40 bf16 (80B); Vt rows 328 bf16 (656B).
#define ROWB 80
#define VTB  656
#define OFF_QH   0
#define OFF_QL   25600
#define OFF_KH   51200
#define OFF_KL   76800
#define OFF_VTH  102400
#define OFF_VTL  123392
#define OFF_BIAS 144384
#define OFF_META 149124
#define ATTN_SMEM (150404)

__global__ void __launch_bounds__(320)
attn_kernel(const float* __restrict__ qkv, const float* __restrict__ bias_table)
{
    extern __shared__ char smc[];
    const u32 smb = (u32)__cvta_generic_to_shared(smc);
    int* meta_s = (int*)(smc + OFF_META);

    const int head = blockIdx.y;
    const int wb   = blockIdx.x;          // b*64 + widx
    const int b    = wb >> 6;
    const int widx = wb & 63;
    const int hw = widx >> 3, ww = widx & 7;

    const int tid  = threadIdx.x;         // 0..319, thread = token for staging
    const int lane = tid & 31;
    const int warp = tid >> 5;            // 0..9
    const int g    = lane >> 2;           // mma group id
    const int t4   = lane & 3;
    const int wr   = warp * 32;           // this warp's query rows

    const int t   = tid >> 6;
    const int hs  = (tid >> 3) & 7;
    const int wsv = tid & 7;
    const int Hp = hw * 8 + hs;
    const int Wp = ww * 8 + wsv;
    const int h = (Hp + 4) & 63;
    const int w = (Wp + 4) & 63;
    const int rh = (Hp < 56) ? 0 : ((Hp < 60) ? 1 : 2);
    const int rw = (Wp < 56) ? 0 : ((Wp < 60) ? 1 : 2);
    meta_s[tid] = (t * 15 + hs + wsv) | ((rh * 3 + rw) << 8);

    const int row = ((b * T_FRAMES + t) << 12) + (h << 6) + w;
    const float* qp = qkv + (size_t)row * (3 * DIM) + head * HDIM;

    const float LOG2E = 1.4426950408889634f;
    const float qs_f = 0.17677669529663687f * LOG2E;

    // ---- stage Q (scaled), K split, V^T split into smem ----
    {
        const float4* qv = (const float4*)qp;
        const float4* kv = (const float4*)(qp + DIM);
        const float4* vv = (const float4*)(qp + 2 * DIM);
        #pragma unroll
        for (int m = 0; m < 8; ++m) {
            float4 f = qv[m];
            u32 h0, l0, h1, l1;
            split_pair(f.x * qs_f, f.y * qs_f, h0, l0);
            split_pair(f.z * qs_f, f.w * qs_f, h1, l1);
            const int off = tid * ROWB + m * 8;
            *(u32*)(smc + OFF_QH + off) = h0;  *(u32*)(smc + OFF_QH + off + 4) = h1;
            *(u32*)(smc + OFF_QL + off) = l0;  *(u32*)(smc + OFF_QL + off + 4) = l1;
        }
        #pragma unroll
        for (int m = 0; m < 8; ++m) {
            float4 f = kv[m];
            u32 h0, l0, h1, l1;
            split_pair(f.x, f.y, h0, l0);
            split_pair(f.z, f.w, h1, l1);
            const int off = tid * ROWB + m * 8;
            *(u32*)(smc + OFF_KH + off) = h0;  *(u32*)(smc + OFF_KH + off + 4) = h1;
            *(u32*)(smc + OFF_KL + off) = l0;  *(u32*)(smc + OFF_KL + off + 4) = l1;
        }
        #pragma unroll
        for (int m = 0; m < 8; ++m) {
            float4 f = vv[m];
            float vals[4] = {f.x, f.y, f.z, f.w};
            #pragma unroll
            for (int e = 0; e < 4; ++e) {
                const int d = m * 4 + e;
                __nv_bfloat16 vh = __float2bfloat16_rn(vals[e]);
                float rsd = vals[e] - __bfloat162float(vh);
                __nv_bfloat16 vl = __float2bfloat16_rn(rsd);
                *(__nv_bfloat16*)(smc + OFF_VTH + d * VTB + tid * 2) = vh;
                *(__nv_bfloat16*)(smc + OFF_VTL + d * VTB + tid * 2) = vl;
            }
        }
    }
    for (int idx = tid; idx < 1185; idx += 320)
        *(float*)(smc + OFF_BIAS + idx * 4) = bias_table[idx * HEADS + head] * LOG2E;

    __syncthreads();

    int ai[2][2], ri[2][2];
    #pragma unroll
    for (int mt = 0; mt < 2; ++mt)
        #pragma unroll
        for (int hh = 0; hh < 2; ++hh) {
            int mv = meta_s[wr + 16 * mt + g + 8 * hh];
            ai[mt][hh] = (mv & 255) + 112;
            ri[mt][hh] = mv >> 8;
        }

    u32 qa[2][2][2][4];
    #pragma unroll
    for (int s = 0; s < 2; ++s) {
        const u32 base = smb + (s ? OFF_QL : OFF_QH);
        #pragma unroll
        for (int mt = 0; mt < 2; ++mt) {
            const u32 r0 = base + (wr + 16 * mt + g) * ROWB + t4 * 4;
            #pragma unroll
            for (int kt = 0; kt < 2; ++kt) {
                const u32 a = r0 + kt * 32;
                qa[s][mt][kt][0] = lds32(a);
                qa[s][mt][kt][1] = lds32(a + 8 * ROWB);
                qa[s][mt][kt][2] = lds32(a + 16);
                qa[s][mt][kt][3] = lds32(a + 8 * ROWB + 16);
            }
        }
    }

    const u32 khb = smb + OFF_KH, klb = smb + OFF_KL;
    const u32 vhb = smb + OFF_VTH, vlb = smb + OFF_VTL;
    const u32 bib = smb + OFF_BIAS;

    float oacc[2][4][4];
    #pragma unroll
    for (int mt = 0; mt < 2; ++mt)
        #pragma unroll
        for (int n = 0; n < 4; ++n)
            #pragma unroll
            for (int e = 0; e < 4; ++e) oacc[mt][n][e] = 0.f;
    float lsum[2][2] = {{0.f, 0.f}, {0.f, 0.f}};

    #pragma unroll 1
    for (int jc = 0; jc < 10; ++jc) {
        const int jb = jc * 32;
        float sacc[2][4][4];
        #pragma unroll
        for (int mt = 0; mt < 2; ++mt)
            #pragma unroll
            for (int n = 0; n < 4; ++n)
                #pragma unroll
                for (int e = 0; e < 4; ++e) sacc[mt][n][e] = 0.f;

        #pragma unroll
        for (int kt = 0; kt < 2; ++kt) {
            #pragma unroll
            for (int n = 0; n < 4; ++n) {
                const u32 off = (jb + 8 * n + g) * ROWB + t4 * 4 + kt * 32;
                const u32 bh0 = lds32(khb + off), bh1 = lds32(khb + off + 16);
                const u32 bl0 = lds32(klb + off), bl1 = lds32(klb + off + 16);
                #pragma unroll
                for (int mt = 0; mt < 2; ++mt) {
                    float* c = sacc[mt][n];
                    mma16816(c[0], c[1], c[2], c[3],
                             qa[0][mt][kt][0], qa[0][mt][kt][1], qa[0][mt][kt][2], qa[0][mt][kt][3],
                             bh0, bh1);
                    mma16816(c[0], c[1], c[2], c[3],
                             qa[0][mt][kt][0], qa[0][mt][kt][1], qa[0][mt][kt][2], qa[0][mt][kt][3],
                             bl0, bl1);
                    mma16816(c[0], c[1], c[2], c[3],
                             qa[1][mt][kt][0], qa[1][mt][kt][1], qa[1][mt][kt][2], qa[1][mt][kt][3],
                             bh0, bh1);
                }
            }
        }

        #pragma unroll
        for (int n = 0; n < 4; ++n) {
            const int j0 = jb + 8 * n + 2 * t4;
            const int mj0 = meta_s[j0], mj1 = meta_s[j0 + 1];
            const int b0i = mj0 & 255, b1i = mj1 & 255;
            const int rj0 = mj0 >> 8,  rj1 = mj1 >> 8;
            #pragma unroll
            for (int mt = 0; mt < 2; ++mt) {
                float* c = sacc[mt][n];
                float s0 = c[0] + lds32f(bib + (ai[mt][0] - b0i) * 4);
                float s1 = c[1] + lds32f(bib + (ai[mt][0] - b1i) * 4);
                float s2 = c[2] + lds32f(bib + (ai[mt][1] - b0i) * 4);
                float s3 = c[3] + lds32f(bib + (ai[mt][1] - b1i) * 4);
                float p0, p1, p2, p3;
                asm("ex2.approx.ftz.f32 %0,%1;" : "=f"(p0) : "f"(s0));
                asm("ex2.approx.ftz.f32 %0,%1;" : "=f"(p1) : "f"(s1));
                asm("ex2.approx.ftz.f32 %0,%1;" : "=f"(p2) : "f"(s2));
                asm("ex2.approx.ftz.f32 %0,%1;" : "=f"(p3) : "f"(s3));
                p0 = (ri[mt][0] == rj0) ? p0 : 0.f;
                p1 = (ri[mt][0] == rj1) ? p1 : 0.f;
                p2 = (ri[mt][1] == rj0) ? p2 : 0.f;
                p3 = (ri[mt][1] == rj1) ? p3 : 0.f;
                c[0] = p0; c[1] = p1; c[2] = p2; c[3] = p3;
                lsum[mt][0] += p0 + p1;
                lsum[mt][1] += p2 + p3;
            }
        }

        u32 pah[2][2][4], pal[2][2][4];
        #pragma unroll
        for (int mt = 0; mt < 2; ++mt)
            #pragma unroll
            for (int kt = 0; kt < 2; ++kt) {
                const float* cA = sacc[mt][2 * kt];
                const float* cB = sacc[mt][2 * kt + 1];
                const float px[8] = {cA[0], cA[1], cA[2], cA[3], cB[0], cB[1], cB[2], cB[3]};
                #pragma unroll
                for (int e = 0; e < 4; ++e) {
                    float x = px[2 * e], y = px[2 * e + 1];
                    u32 hh = cvt2(x, y);
                    float rx = x - __uint_as_float(hh << 16);
                    float ry = y - __uint_as_float(hh & 0xffff0000u);
                    pah[mt][kt][e] = hh;
                    pal[mt][kt][e] = cvt2(rx, ry);
                }
            }

        #pragma unroll
        for (int kt = 0; kt < 2; ++kt) {
            #pragma unroll
            for (int n = 0; n < 4; ++n) {
                const u32 off = (8 * n + g) * VTB + (jb / 2 + 8 * kt + t4) * 4;
                const u32 bh0 = lds32(vhb + off), bh1 = lds32(vhb + off + 16);
                const u32 bl0 = lds32(vlb + off), bl1 = lds32(vlb + off + 16);
                #pragma unroll
                for (int mt = 0; mt < 2; ++mt) {
                    float* c = oacc[mt][n];
                    mma16816(c[0], c[1], c[2], c[3],
                             pah[mt][kt][0], pah[mt][kt][1], pah[mt][kt][2], pah[mt][kt][3],
                             bh0, bh1);
                    mma16816(c[0], c[1], c[2], c[3],
                             pah[mt][kt][0], pah[mt][kt][1], pah[mt][kt][2], pah[mt][kt][3],
                             bl0, bl1);
                    mma16816(c[0], c[1], c[2], c[3],
                             pal[mt][kt][0], pal[mt][kt][1], pal[mt][kt][2], pal[mt][kt][3],
                             bh0, bh1);
                }
            }
        }
    }

    #pragma unroll
    for (int mt = 0; mt < 2; ++mt)
        #pragma unroll
        for (int hh = 0; hh < 2; ++hh) {
            float v = lsum[mt][hh];
            v += __shfl_xor_sync(0xffffffffu, v, 1);
            v += __shfl_xor_sync(0xffffffffu, v, 2);
            lsum[mt][hh] = 1.0f / v;
        }

    #pragma unroll
    for (int mt = 0; mt < 2; ++mt)
        #pragma unroll
        for (int hh = 0; hh < 2; ++hh) {
            const int r = wr + 16 * mt + g + 8 * hh;
            float* orow = g_scratch + ((size_t)(wb * NTOK + r)) * DIM + head * HDIM;
            const float inv = lsum[mt][hh];
            #pragma unroll
            for (int n = 0; n < 4; ++n) {
                float2 v = make_float2(oacc[mt][n][2 * hh] * inv,
                                       oacc[mt][n][2 * hh + 1] * inv);
                *(float2*)(orow + 8 * n + 2 * t4) = v;
            }
        }
}

// ---------------- projection kernel (tensor cores, bf16-split) ----------------
// Persistent CTAs. W split staged ONCE (bf16 hi/lo, [192 c][200 bf16 pad]);
// per chunk the 64x192 o tile is split into bf16 hi/lo. GEMM M=64,N=192,K=192.
// 8 warps as 2(m) x 4(n): warp tile 32 rows x 48 cols.
#define PWROW 400                      // padded W/o row bytes (200 bf16)
#define OFF_PWH 0
#define OFF_PWL 76800
#define OFF_POH 153600
#define OFF_POL 179200
#define PROJ_SMEM 204800

__global__ void __launch_bounds__(256)
proj_kernel(const float* __restrict__ pw, const float* __restrict__ pb,
            float* __restrict__ out, int nchunks)
{
    extern __shared__ char smc[];
    const u32 smb = (u32)__cvta_generic_to_shared(smc);
    const int tid = threadIdx.x, lane = tid & 31, warp = tid >> 5;
    const int g = lane >> 2, t4 = lane & 3;
    const int wm = warp >> 2, wn = warp & 3;   // 2 x 4
    const int m0 = wm * 32, n0 = wn * 48;

    // ---- stage W split once ----
    for (int idx = tid; idx < DIM * 96; idx += 256) {
        const int c = idx / 96, kp = idx % 96;
        float2 v = *(const float2*)(pw + c * DIM + kp * 2);
        u32 hi, lo; split_pair(v.x, v.y, hi, lo);
        *(u32*)(smc + OFF_PWH + c * PWROW + kp * 4) = hi;
        *(u32*)(smc + OFF_PWL + c * PWROW + kp * 4) = lo;
    }
    float pbv[6][2];
    #pragma unroll
    for (int nt = 0; nt < 6; ++nt) {
        float2 v = *(const float2*)(pb + n0 + nt * 8 + 2 * t4);
        pbv[nt][0] = v.x; pbv[nt][1] = v.y;
    }

    const u32 whb = smb + OFF_PWH, wlb = smb + OFF_PWL;
    const u32 ohb = smb + OFF_POH, olb = smb + OFF_POL;

    for (int ci = blockIdx.x; ci < nchunks; ci += gridDim.x) {
        __syncthreads();   // W staged (first) / previous chunk consumed
        // stage o chunk split into bf16 hi/lo
        const float* src = g_scratch + (size_t)ci * (64 * DIM);
        #pragma unroll
        for (int it = 0; it < 24; ++it) {
            const int idx = tid + it * 256;       // 0..6143 float2s
            const int tok = idx / 96, kp = idx % 96;
            float2 v = *(const float2*)(src + tok * DIM + kp * 2);
            u32 hi, lo; split_pair(v.x, v.y, hi, lo);
            *(u32*)(smc + OFF_POH + tok * PWROW + kp * 4) = hi;
            *(u32*)(smc + OFF_POL + tok * PWROW + kp * 4) = lo;
        }
        __syncthreads();

        float acc[2][6][4];
        #pragma unroll
        for (int mt = 0; mt < 2; ++mt)
            #pragma unroll
            for (int nt = 0; nt < 6; ++nt)
                #pragma unroll
                for (int e = 0; e < 4; ++e) acc[mt][nt][e] = 0.f;

        #pragma unroll 1
        for (int ki = 0; ki < 12; ++ki) {
            u32 ah[2][4], al[2][4];
            #pragma unroll
            for (int mt = 0; mt < 2; ++mt) {
                const u32 ab = (u32)((m0 + 16 * mt + g) * PWROW + 4 * t4 + ki * 32);
                ah[mt][0] = lds32v(ohb + ab);
                ah[mt][1] = lds32v(ohb + ab + 8 * PWROW);
                ah[mt][2] = lds32v(ohb + ab + 16);
                ah[mt][3] = lds32v(ohb + ab + 8 * PWROW + 16);
                al[mt][0] = lds32v(olb + ab);
                al[mt][1] = lds32v(olb + ab + 8 * PWROW);
                al[mt][2] = lds32v(olb + ab + 16);
                al[mt][3] = lds32v(olb + ab + 8 * PWROW + 16);
            }
            #pragma unroll
            for (int nt = 0; nt < 6; ++nt) {
                const u32 wo = (u32)((n0 + 8 * nt + g) * PWROW + 4 * t4 + ki * 32);
                const u32 bh0 = lds32(whb + wo), bh1 = lds32(whb + wo + 16);
                const u32 bl0 = lds32(wlb + wo), bl1 = lds32(wlb + wo + 16);
                #pragma unroll
                for (int mt = 0; mt < 2; ++mt) {
                    float* c = acc[mt][nt];
                    mma16816(c[0], c[1], c[2], c[3],
                             ah[mt][0], ah[mt][1], ah[mt][2], ah[mt][3], bh0, bh1);
                    mma16816(c[0], c[1], c[2], c[3],
                             ah[mt][0], ah[mt][1], ah[mt][2], ah[mt][3], bl0, bl1);
                    mma16816(c[0], c[1], c[2], c[3],
                             al[mt][0], al[mt][1], al[mt][2], al[mt][3], bh0, bh1);
                }
            }
        }

        // ---- epilogue: bias + window-reverse scatter ----
        const int wbid = ci / 5, t = ci % 5;
        const int b = wbid >> 6, widx = wbid & 63;
        const int hw = widx >> 3, ww = widx & 7;
        #pragma unroll
        for (int mt = 0; mt < 2; ++mt)
            #pragma unroll
            for (int hh = 0; hh < 2; ++hh) {
                const int s = m0 + 16 * mt + g + 8 * hh;   // token 0..63
                const int hs = s >> 3, wsv = s & 7;
                const int h = (hw * 8 + hs + 4) & 63;
                const int w = (ww * 8 + wsv + 4) & 63;
                float* orow = out + ((size_t)((b * T_FRAMES + t) * 4096 + h * 64 + w)) * DIM;
                #pragma unroll
                for (int nt = 0; nt < 6; ++nt) {
                    float2 v = make_float2(acc[mt][nt][2 * hh]     + pbv[nt][0],
                                           acc[mt][nt][2 * hh + 1] + pbv[nt][1]);
                    *(float2*)(orow + n0 + nt * 8 + 2 * t4) = v;
                }
            }
    }
}

// ---------------- launch ----------------
extern "C" void kernel_launch(void* const* d_in, const int* in_sizes, int n_in,
                              void* d_out, int out_size)
{
    const float* qkv        = (const float*)d_in[0];
    const float* bias_table = (const float*)d_in[1];
    const float* pw         = (const float*)d_in[2];
    const float* pb         = (const float*)d_in[3];
    float* out = (float*)d_out;

    int B = in_sizes[0] / (T_FRAMES * 64 * 64 * 3 * DIM);
    if (B < 1) B = 1;
    if (B > 2) B = 2;   // scratch sized for B=2

    cudaFuncSetAttribute(attn_kernel, cudaFuncAttributeMaxDynamicSharedMemorySize, ATTN_SMEM);
    cudaFuncSetAttribute(proj_kernel, cudaFuncAttributeMaxDynamicSharedMemorySize, PROJ_SMEM);

    dim3 ag(B * 64, HEADS);
    attn_kernel<<<ag, 320, ATTN_SMEM>>>(qkv, bias_table);

    const int nchunks = B * 64 * T_FRAMES;
    int pgrid = nchunks < 148 ? nchunks : 148;
    proj_kernel<<<pgrid, 256, PROJ_SMEM>>>(pw, pb, out, nchunks);
}

// round 7
// speedup vs baseline: 2.7580x; 1.0791x over previous
#include <cuda_runtime.h>
#include <cuda_bf16.h>

typedef unsigned long long u64;
typedef unsigned int u32;

#define T_FRAMES 5
#define WS 8
#define HEADS 6
#define DIM 192
#define HDIM 32
#define NTOK 320

// scratch: per-window attention output, [wb][n][DIM], sized for B=2
__device__ float g_scratch[2 * 64 * NTOK * DIM];

// ---------------- small helpers ----------------
__device__ __forceinline__ u32 lds32(u32 a) {
    u32 r; asm("ld.shared.b32 %0,[%1];" : "=r"(r) : "r"(a)); return r;
}
__device__ __forceinline__ u32 lds32v(u32 a) {   // volatile: smem rewritten per chunk
    u32 r; asm volatile("ld.shared.b32 %0,[%1];" : "=r"(r) : "r"(a)); return r;
}
__device__ __forceinline__ float lds32f(u32 a) {
    float r; asm("ld.shared.b32 %0,[%1];" : "=f"(r) : "r"(a)); return r;
}
// pack two f32 into bf16x2: low half = first arg
__device__ __forceinline__ u32 cvt2(float lo, float hi) {
    u32 r; asm("cvt.rn.bf16x2.f32 %0,%1,%2;" : "=r"(r) : "f"(hi), "f"(lo)); return r;
}
__device__ __forceinline__ void mma16816(float &c0, float &c1, float &c2, float &c3,
                                         u32 a0, u32 a1, u32 a2, u32 a3,
                                         u32 b0, u32 b1) {
    asm("mma.sync.aligned.m16n8k16.row.col.f32.bf16.bf16.f32 "
        "{%0,%1,%2,%3},{%4,%5,%6,%7},{%8,%9},{%0,%1,%2,%3};"
        : "+f"(c0), "+f"(c1), "+f"(c2), "+f"(c3)
        : "r"(a0), "r"(a1), "r"(a2), "r"(a3), "r"(b0), "r"(b1));
}
// split f32 pair into bf16x2 hi + bf16x2 lo (residual)
__device__ __forceinline__ void split_pair(float a, float b, u32 &h, u32 &l) {
    __nv_bfloat162 hv = __floats2bfloat162_rn(a, b);
    h = *(u32*)&hv;
    float ra = a - __bfloat162float(hv.x);
    float rb = b - __bfloat162float(hv.y);
    __nv_bfloat162 lv = __floats2bfloat162_rn(ra, rb);
    l = *(u32*)&lv;
}

// ---------------- attention kernel (tensor cores, bf16-split) ----------------
// 640 threads / 20 warps; warp owns 16 query rows.
// smem byte offsets. Q/K rows padded to 40 bf16 (80B); Vt rows 328 bf16 (656B).
#define ROWB 80
#define VTB  656
#define OFF_QH   0
#define OFF_QL   25600
#define OFF_KH   51200
#define OFF_KL   76800
#define OFF_VTH  102400
#define OFF_VTL  123392
#define OFF_BIAS 144384
#define OFF_META 149124
#define ATTN_SMEM (150404)

__global__ void __launch_bounds__(640)
attn_kernel(const float* __restrict__ qkv, const float* __restrict__ bias_table)
{
    extern __shared__ char smc[];
    const u32 smb = (u32)__cvta_generic_to_shared(smc);
    int* meta_s = (int*)(smc + OFF_META);

    const int head = blockIdx.y;
    const int wb   = blockIdx.x;          // b*64 + widx
    const int b    = wb >> 6;
    const int widx = wb & 63;
    const int hw = widx >> 3, ww = widx & 7;

    const int tid  = threadIdx.x;         // 0..639
    const int lane = tid & 31;
    const int warp = tid >> 5;            // 0..19
    const int g    = lane >> 2;
    const int t4   = lane & 3;
    const int wr   = warp * 16;           // this warp's 16 query rows

    // staging: threads 0..319 handle Q+K of token tid; 320..639 handle V^T
    const bool qk_half = tid < 320;
    const int tok = qk_half ? tid : tid - 320;
    const int t   = tok >> 6;
    const int hs  = (tok >> 3) & 7;
    const int wsv = tok & 7;
    const int Hp = hw * 8 + hs;
    const int Wp = ww * 8 + wsv;
    const int h = (Hp + 4) & 63;
    const int w = (Wp + 4) & 63;
    const int rh = (Hp < 56) ? 0 : ((Hp < 60) ? 1 : 2);
    const int rw = (Wp < 56) ? 0 : ((Wp < 60) ? 1 : 2);
    if (qk_half)
        meta_s[tok] = (t * 15 + hs + wsv) | ((rh * 3 + rw) << 8);

    const int row = ((b * T_FRAMES + t) << 12) + (h << 6) + w;
    const float* qp = qkv + (size_t)row * (3 * DIM) + head * HDIM;

    const float LOG2E = 1.4426950408889634f;
    const float qs_f = 0.17677669529663687f * LOG2E;

    if (qk_half) {
        const float4* qv = (const float4*)qp;
        const float4* kv = (const float4*)(qp + DIM);
        #pragma unroll
        for (int m = 0; m < 8; ++m) {
            float4 f = qv[m];
            u32 h0, l0, h1, l1;
            split_pair(f.x * qs_f, f.y * qs_f, h0, l0);
            split_pair(f.z * qs_f, f.w * qs_f, h1, l1);
            const int off = tok * ROWB + m * 8;
            *(u32*)(smc + OFF_QH + off) = h0;  *(u32*)(smc + OFF_QH + off + 4) = h1;
            *(u32*)(smc + OFF_QL + off) = l0;  *(u32*)(smc + OFF_QL + off + 4) = l1;
        }
        #pragma unroll
        for (int m = 0; m < 8; ++m) {
            float4 f = kv[m];
            u32 h0, l0, h1, l1;
            split_pair(f.x, f.y, h0, l0);
            split_pair(f.z, f.w, h1, l1);
            const int off = tok * ROWB + m * 8;
            *(u32*)(smc + OFF_KH + off) = h0;  *(u32*)(smc + OFF_KH + off + 4) = h1;
            *(u32*)(smc + OFF_KL + off) = l0;  *(u32*)(smc + OFF_KL + off + 4) = l1;
        }
    } else {
        const float4* vv = (const float4*)(qp + 2 * DIM);
        #pragma unroll
        for (int m = 0; m < 8; ++m) {
            float4 f = vv[m];
            float vals[4] = {f.x, f.y, f.z, f.w};
            #pragma unroll
            for (int e = 0; e < 4; ++e) {
                const int d = m * 4 + e;
                __nv_bfloat16 vh = __float2bfloat16_rn(vals[e]);
                float rsd = vals[e] - __bfloat162float(vh);
                __nv_bfloat16 vl = __float2bfloat16_rn(rsd);
                *(__nv_bfloat16*)(smc + OFF_VTH + d * VTB + tok * 2) = vh;
                *(__nv_bfloat16*)(smc + OFF_VTL + d * VTB + tok * 2) = vl;
            }
        }
    }
    for (int idx = tid; idx < 1185; idx += 640)
        *(float*)(smc + OFF_BIAS + idx * 4) = bias_table[idx * HEADS + head] * LOG2E;

    __syncthreads();

    int ai[2], ri[2];
    #pragma unroll
    for (int hh = 0; hh < 2; ++hh) {
        int mv = meta_s[wr + g + 8 * hh];
        ai[hh] = (mv & 255) + 112;
        ri[hh] = mv >> 8;
    }

    // Q A-fragments: [hi/lo][kt][4]
    u32 qa[2][2][4];
    #pragma unroll
    for (int s = 0; s < 2; ++s) {
        const u32 r0 = smb + (s ? OFF_QL : OFF_QH) + (wr + g) * ROWB + t4 * 4;
        #pragma unroll
        for (int kt = 0; kt < 2; ++kt) {
            const u32 a = r0 + kt * 32;
            qa[s][kt][0] = lds32(a);
            qa[s][kt][1] = lds32(a + 8 * ROWB);
            qa[s][kt][2] = lds32(a + 16);
            qa[s][kt][3] = lds32(a + 8 * ROWB + 16);
        }
    }

    const u32 khb = smb + OFF_KH, klb = smb + OFF_KL;
    const u32 vhb = smb + OFF_VTH, vlb = smb + OFF_VTL;
    const u32 bib = smb + OFF_BIAS;

    float oacc[4][4];
    #pragma unroll
    for (int n = 0; n < 4; ++n)
        #pragma unroll
        for (int e = 0; e < 4; ++e) oacc[n][e] = 0.f;
    float lsum[2] = {0.f, 0.f};

    #pragma unroll 1
    for (int jc = 0; jc < 10; ++jc) {
        const int jb = jc * 32;
        float sacc[4][4];
        #pragma unroll
        for (int n = 0; n < 4; ++n)
            #pragma unroll
            for (int e = 0; e < 4; ++e) sacc[n][e] = 0.f;

        // ---- S = Q K^T ----
        #pragma unroll
        for (int kt = 0; kt < 2; ++kt) {
            #pragma unroll
            for (int n = 0; n < 4; ++n) {
                const u32 off = (jb + 8 * n + g) * ROWB + t4 * 4 + kt * 32;
                const u32 bh0 = lds32(khb + off), bh1 = lds32(khb + off + 16);
                const u32 bl0 = lds32(klb + off), bl1 = lds32(klb + off + 16);
                float* c = sacc[n];
                mma16816(c[0], c[1], c[2], c[3],
                         qa[0][kt][0], qa[0][kt][1], qa[0][kt][2], qa[0][kt][3], bh0, bh1);
                mma16816(c[0], c[1], c[2], c[3],
                         qa[0][kt][0], qa[0][kt][1], qa[0][kt][2], qa[0][kt][3], bl0, bl1);
                mma16816(c[0], c[1], c[2], c[3],
                         qa[1][kt][0], qa[1][kt][1], qa[1][kt][2], qa[1][kt][3], bh0, bh1);
            }
        }

        // ---- softmax ----
        #pragma unroll
        for (int n = 0; n < 4; ++n) {
            const int j0 = jb + 8 * n + 2 * t4;
            const int mj0 = meta_s[j0], mj1 = meta_s[j0 + 1];
            const int b0i = mj0 & 255, b1i = mj1 & 255;
            const int rj0 = mj0 >> 8,  rj1 = mj1 >> 8;
            float* c = sacc[n];
            float s0 = c[0] + lds32f(bib + (ai[0] - b0i) * 4);
            float s1 = c[1] + lds32f(bib + (ai[0] - b1i) * 4);
            float s2 = c[2] + lds32f(bib + (ai[1] - b0i) * 4);
            float s3 = c[3] + lds32f(bib + (ai[1] - b1i) * 4);
            float p0, p1, p2, p3;
            asm("ex2.approx.ftz.f32 %0,%1;" : "=f"(p0) : "f"(s0));
            asm("ex2.approx.ftz.f32 %0,%1;" : "=f"(p1) : "f"(s1));
            asm("ex2.approx.ftz.f32 %0,%1;" : "=f"(p2) : "f"(s2));
            asm("ex2.approx.ftz.f32 %0,%1;" : "=f"(p3) : "f"(s3));
            p0 = (ri[0] == rj0) ? p0 : 0.f;
            p1 = (ri[0] == rj1) ? p1 : 0.f;
            p2 = (ri[1] == rj0) ? p2 : 0.f;
            p3 = (ri[1] == rj1) ? p3 : 0.f;
            c[0] = p0; c[1] = p1; c[2] = p2; c[3] = p3;
            lsum[0] += p0 + p1;
            lsum[1] += p2 + p3;
        }

        // ---- P fragments (bf16 split) ----
        u32 pah[2][4], pal[2][4];
        #pragma unroll
        for (int kt = 0; kt < 2; ++kt) {
            const float* cA = sacc[2 * kt];
            const float* cB = sacc[2 * kt + 1];
            const float px[8] = {cA[0], cA[1], cA[2], cA[3], cB[0], cB[1], cB[2], cB[3]};
            #pragma unroll
            for (int e = 0; e < 4; ++e) {
                float x = px[2 * e], y = px[2 * e + 1];
                u32 hh = cvt2(x, y);
                float rx = x - __uint_as_float(hh << 16);
                float ry = y - __uint_as_float(hh & 0xffff0000u);
                pah[kt][e] = hh;
                pal[kt][e] = cvt2(rx, ry);
            }
        }

        // ---- O += P V ----
        #pragma unroll
        for (int kt = 0; kt < 2; ++kt) {
            #pragma unroll
            for (int n = 0; n < 4; ++n) {
                const u32 off = (8 * n + g) * VTB + (jb / 2 + 8 * kt + t4) * 4;
                const u32 bh0 = lds32(vhb + off), bh1 = lds32(vhb + off + 16);
                const u32 bl0 = lds32(vlb + off), bl1 = lds32(vlb + off + 16);
                float* c = oacc[n];
                mma16816(c[0], c[1], c[2], c[3],
                         pah[kt][0], pah[kt][1], pah[kt][2], pah[kt][3], bh0, bh1);
                mma16816(c[0], c[1], c[2], c[3],
                         pah[kt][0], pah[kt][1], pah[kt][2], pah[kt][3], bl0, bl1);
                mma16816(c[0], c[1], c[2], c[3],
                         pal[kt][0], pal[kt][1], pal[kt][2], pal[kt][3], bh0, bh1);
            }
        }
    }

    #pragma unroll
    for (int hh = 0; hh < 2; ++hh) {
        float v = lsum[hh];
        v += __shfl_xor_sync(0xffffffffu, v, 1);
        v += __shfl_xor_sync(0xffffffffu, v, 2);
        lsum[hh] = 1.0f / v;
    }

    #pragma unroll
    for (int hh = 0; hh < 2; ++hh) {
        const int r = wr + g + 8 * hh;
        float* orow = g_scratch + ((size_t)(wb * NTOK + r)) * DIM + head * HDIM;
        const float inv = lsum[hh];
        #pragma unroll
        for (int n = 0; n < 4; ++n) {
            float2 v = make_float2(oacc[n][2 * hh] * inv, oacc[n][2 * hh + 1] * inv);
            *(float2*)(orow + 8 * n + 2 * t4) = v;
        }
    }
}

// ---------------- projection kernel (tensor cores, bf16-split) ----------------
// 512 threads / 16 warps as 4(m) x 4(n): warp tile 16 rows x 48 cols.
#define PWROW 400                      // padded W/o row bytes (200 bf16)
#define OFF_PWH 0
#define OFF_PWL 76800
#define OFF_POH 153600
#define OFF_POL 179200
#define PROJ_SMEM 204800

__global__ void __launch_bounds__(512)
proj_kernel(const float* __restrict__ pw, const float* __restrict__ pb,
            float* __restrict__ out, int nchunks)
{
    extern __shared__ char smc[];
    const u32 smb = (u32)__cvta_generic_to_shared(smc);
    const int tid = threadIdx.x, lane = tid & 31, warp = tid >> 5;
    const int g = lane >> 2, t4 = lane & 3;
    const int wm = warp >> 2, wn = warp & 3;   // 4 x 4
    const int m0 = wm * 16, n0 = wn * 48;

    // ---- stage W split once ----
    for (int idx = tid; idx < DIM * 96; idx += 512) {
        const int c = idx / 96, kp = idx % 96;
        float2 v = *(const float2*)(pw + c * DIM + kp * 2);
        u32 hi, lo; split_pair(v.x, v.y, hi, lo);
        *(u32*)(smc + OFF_PWH + c * PWROW + kp * 4) = hi;
        *(u32*)(smc + OFF_PWL + c * PWROW + kp * 4) = lo;
    }
    float pbv[6][2];
    #pragma unroll
    for (int nt = 0; nt < 6; ++nt) {
        float2 v = *(const float2*)(pb + n0 + nt * 8 + 2 * t4);
        pbv[nt][0] = v.x; pbv[nt][1] = v.y;
    }

    const u32 whb = smb + OFF_PWH, wlb = smb + OFF_PWL;
    const u32 ohb = smb + OFF_POH, olb = smb + OFF_POL;

    for (int ci = blockIdx.x; ci < nchunks; ci += gridDim.x) {
        __syncthreads();   // W staged (first) / previous chunk consumed
        const float* src = g_scratch + (size_t)ci * (64 * DIM);
        #pragma unroll
        for (int it = 0; it < 12; ++it) {
            const int idx = tid + it * 512;       // 0..6143 float2s
            const int tok = idx / 96, kp = idx % 96;
            float2 v = *(const float2*)(src + tok * DIM + kp * 2);
            u32 hi, lo; split_pair(v.x, v.y, hi, lo);
            *(u32*)(smc + OFF_POH + tok * PWROW + kp * 4) = hi;
            *(u32*)(smc + OFF_POL + tok * PWROW + kp * 4) = lo;
        }
        __syncthreads();

        float acc[6][4];
        #pragma unroll
        for (int nt = 0; nt < 6; ++nt)
            #pragma unroll
            for (int e = 0; e < 4; ++e) acc[nt][e] = 0.f;

        #pragma unroll 1
        for (int ki = 0; ki < 12; ++ki) {
            u32 ah[4], al[4];
            const u32 ab = (u32)((m0 + g) * PWROW + 4 * t4 + ki * 32);
            ah[0] = lds32v(ohb + ab);
            ah[1] = lds32v(ohb + ab + 8 * PWROW);
            ah[2] = lds32v(ohb + ab + 16);
            ah[3] = lds32v(ohb + ab + 8 * PWROW + 16);
            al[0] = lds32v(olb + ab);
            al[1] = lds32v(olb + ab + 8 * PWROW);
            al[2] = lds32v(olb + ab + 16);
            al[3] = lds32v(olb + ab + 8 * PWROW + 16);
            #pragma unroll
            for (int nt = 0; nt < 6; ++nt) {
                const u32 wo = (u32)((n0 + 8 * nt + g) * PWROW + 4 * t4 + ki * 32);
                const u32 bh0 = lds32(whb + wo), bh1 = lds32(whb + wo + 16);
                const u32 bl0 = lds32(wlb + wo), bl1 = lds32(wlb + wo + 16);
                float* c = acc[nt];
                mma16816(c[0], c[1], c[2], c[3], ah[0], ah[1], ah[2], ah[3], bh0, bh1);
                mma16816(c[0], c[1], c[2], c[3], ah[0], ah[1], ah[2], ah[3], bl0, bl1);
                mma16816(c[0], c[1], c[2], c[3], al[0], al[1], al[2], al[3], bh0, bh1);
            }
        }

        // ---- epilogue: bias + window-reverse scatter ----
        const int wbid = ci / 5, t = ci % 5;
        const int b = wbid >> 6, widx = wbid & 63;
        const int hw = widx >> 3, ww = widx & 7;
        #pragma unroll
        for (int hh = 0; hh < 2; ++hh) {
            const int s = m0 + g + 8 * hh;   // token 0..63
            const int hs = s >> 3, wsv = s & 7;
            const int h = (hw * 8 + hs + 4) & 63;
            const int w = (ww * 8 + wsv + 4) & 63;
            float* orow = out + ((size_t)((b * T_FRAMES + t) * 4096 + h * 64 + w)) * DIM;
            #pragma unroll
            for (int nt = 0; nt < 6; ++nt) {
                float2 v = make_float2(acc[nt][2 * hh]     + pbv[nt][0],
                                       acc[nt][2 * hh + 1] + pbv[nt][1]);
                *(float2*)(orow + n0 + nt * 8 + 2 * t4) = v;
            }
        }
    }
}

// ---------------- launch ----------------
extern "C" void kernel_launch(void* const* d_in, const int* in_sizes, int n_in,
                              void* d_out, int out_size)
{
    const float* qkv        = (const float*)d_in[0];
    const float* bias_table = (const float*)d_in[1];
    const float* pw         = (const float*)d_in[2];
    const float* pb         = (const float*)d_in[3];
    float* out = (float*)d_out;

    int B = in_sizes[0] / (T_FRAMES * 64 * 64 * 3 * DIM);
    if (B < 1) B = 1;
    if (B > 2) B = 2;   // scratch sized for B=2

    cudaFuncSetAttribute(attn_kernel, cudaFuncAttributeMaxDynamicSharedMemorySize, ATTN_SMEM);
    cudaFuncSetAttribute(proj_kernel, cudaFuncAttributeMaxDynamicSharedMemorySize, PROJ_SMEM);

    dim3 ag(B * 64, HEADS);
    attn_kernel<<<ag, 640, ATTN_SMEM>>>(qkv, bias_table);

    const int nchunks = B * 64 * T_FRAMES;
    int pgrid = nchunks < 148 ? nchunks : 148;
    proj_kernel<<<pgrid, 512, PROJ_SMEM>>>(pw, pb, out, nchunks);
}

// round 8
// speedup vs baseline: 2.9142x; 1.0566x over previous
#include <cuda_runtime.h>
#include <cuda_bf16.h>

typedef unsigned long long u64;
typedef unsigned int u32;

#define T_FRAMES 5
#define WS 8
#define HEADS 6
#define DIM 192
#define HDIM 32
#define NTOK 320

// scratch: per-window attention output, [wb][n][DIM], sized for B=2
__device__ float g_scratch[2 * 64 * NTOK * DIM];

// ---------------- small helpers ----------------
__device__ __forceinline__ u32 lds32(u32 a) {
    u32 r; asm("ld.shared.b32 %0,[%1];" : "=r"(r) : "r"(a)); return r;
}
__device__ __forceinline__ float lds32f(u32 a) {
    float r; asm("ld.shared.b32 %0,[%1];" : "=f"(r) : "r"(a)); return r;
}
// ldmatrix x4: four 8x8 bf16 fragments in one instruction
__device__ __forceinline__ void ldsm4(u32 &r0, u32 &r1, u32 &r2, u32 &r3, u32 a) {
    asm("ldmatrix.sync.aligned.m8n8.x4.shared.b16 {%0,%1,%2,%3},[%4];"
        : "=r"(r0), "=r"(r1), "=r"(r2), "=r"(r3) : "r"(a));
}
__device__ __forceinline__ void ldsm4v(u32 &r0, u32 &r1, u32 &r2, u32 &r3, u32 a) {
    asm volatile("ldmatrix.sync.aligned.m8n8.x4.shared.b16 {%0,%1,%2,%3},[%4];"
        : "=r"(r0), "=r"(r1), "=r"(r2), "=r"(r3) : "r"(a));
}
// pack two f32 into bf16x2: low half = first arg
__device__ __forceinline__ u32 cvt2(float lo, float hi) {
    u32 r; asm("cvt.rn.bf16x2.f32 %0,%1,%2;" : "=r"(r) : "f"(hi), "f"(lo)); return r;
}
__device__ __forceinline__ void mma16816(float &c0, float &c1, float &c2, float &c3,
                                         u32 a0, u32 a1, u32 a2, u32 a3,
                                         u32 b0, u32 b1) {
    asm("mma.sync.aligned.m16n8k16.row.col.f32.bf16.bf16.f32 "
        "{%0,%1,%2,%3},{%4,%5,%6,%7},{%8,%9},{%0,%1,%2,%3};"
        : "+f"(c0), "+f"(c1), "+f"(c2), "+f"(c3)
        : "r"(a0), "r"(a1), "r"(a2), "r"(a3), "r"(b0), "r"(b1));
}
// split f32 pair into bf16x2 hi + bf16x2 lo (residual)
__device__ __forceinline__ void split_pair(float a, float b, u32 &h, u32 &l) {
    __nv_bfloat162 hv = __floats2bfloat162_rn(a, b);
    h = *(u32*)&hv;
    float ra = a - __bfloat162float(hv.x);
    float rb = b - __bfloat162float(hv.y);
    __nv_bfloat162 lv = __floats2bfloat162_rn(ra, rb);
    l = *(u32*)&lv;
}

// ---------------- attention kernel (tensor cores, bf16-split, ldmatrix) ----------------
// 640 threads / 20 warps; warp owns 16 query rows.
// Q/K rows padded to 40 bf16 (80B); Vt rows 328 bf16 (656B). All 16B-aligned,
// row strides ≡ 16 (mod 128) → every LDSM 8-row phase covers all 32 banks.
#define ROWB 80
#define VTB  656
#define OFF_QH   0
#define OFF_QL   25600
#define OFF_KH   51200
#define OFF_KL   76800
#define OFF_VTH  102400
#define OFF_VTL  123392
#define OFF_BIAS 144384
#define OFF_META 149124
#define ATTN_SMEM (150404)

__global__ void __launch_bounds__(640)
attn_kernel(const float* __restrict__ qkv, const float* __restrict__ bias_table)
{
    extern __shared__ char smc[];
    const u32 smb = (u32)__cvta_generic_to_shared(smc);
    int* meta_s = (int*)(smc + OFF_META);

    const int head = blockIdx.y;
    const int wb   = blockIdx.x;          // b*64 + widx
    const int b    = wb >> 6;
    const int widx = wb & 63;
    const int hw = widx >> 3, ww = widx & 7;

    const int tid  = threadIdx.x;         // 0..639
    const int lane = tid & 31;
    const int warp = tid >> 5;            // 0..19
    const int g    = lane >> 2;
    const int t4   = lane & 3;
    const int wr   = warp * 16;           // this warp's 16 query rows

    // staging: threads 0..319 handle Q+K of token tid; 320..639 handle V^T
    const bool qk_half = tid < 320;
    const int tok = qk_half ? tid : tid - 320;
    const int t   = tok >> 6;
    const int hs  = (tok >> 3) & 7;
    const int wsv = tok & 7;
    const int Hp = hw * 8 + hs;
    const int Wp = ww * 8 + wsv;
    const int h = (Hp + 4) & 63;
    const int w = (Wp + 4) & 63;
    const int rh = (Hp < 56) ? 0 : ((Hp < 60) ? 1 : 2);
    const int rw = (Wp < 56) ? 0 : ((Wp < 60) ? 1 : 2);
    if (qk_half)
        meta_s[tok] = (t * 15 + hs + wsv) | ((rh * 3 + rw) << 8);

    const int row = ((b * T_FRAMES + t) << 12) + (h << 6) + w;
    const float* qp = qkv + (size_t)row * (3 * DIM) + head * HDIM;

    const float LOG2E = 1.4426950408889634f;
    const float qs_f = 0.17677669529663687f * LOG2E;

    if (qk_half) {
        const float4* qv = (const float4*)qp;
        const float4* kv = (const float4*)(qp + DIM);
        #pragma unroll
        for (int m = 0; m < 8; ++m) {
            float4 f = qv[m];
            u32 h0, l0, h1, l1;
            split_pair(f.x * qs_f, f.y * qs_f, h0, l0);
            split_pair(f.z * qs_f, f.w * qs_f, h1, l1);
            const int off = tok * ROWB + m * 8;
            *(u32*)(smc + OFF_QH + off) = h0;  *(u32*)(smc + OFF_QH + off + 4) = h1;
            *(u32*)(smc + OFF_QL + off) = l0;  *(u32*)(smc + OFF_QL + off + 4) = l1;
        }
        #pragma unroll
        for (int m = 0; m < 8; ++m) {
            float4 f = kv[m];
            u32 h0, l0, h1, l1;
            split_pair(f.x, f.y, h0, l0);
            split_pair(f.z, f.w, h1, l1);
            const int off = tok * ROWB + m * 8;
            *(u32*)(smc + OFF_KH + off) = h0;  *(u32*)(smc + OFF_KH + off + 4) = h1;
            *(u32*)(smc + OFF_KL + off) = l0;  *(u32*)(smc + OFF_KL + off + 4) = l1;
        }
    } else {
        const float4* vv = (const float4*)(qp + 2 * DIM);
        #pragma unroll
        for (int m = 0; m < 8; ++m) {
            float4 f = vv[m];
            float vals[4] = {f.x, f.y, f.z, f.w};
            #pragma unroll
            for (int e = 0; e < 4; ++e) {
                const int d = m * 4 + e;
                __nv_bfloat16 vh = __float2bfloat16_rn(vals[e]);
                float rsd = vals[e] - __bfloat162float(vh);
                __nv_bfloat16 vl = __float2bfloat16_rn(rsd);
                *(__nv_bfloat16*)(smc + OFF_VTH + d * VTB + tok * 2) = vh;
                *(__nv_bfloat16*)(smc + OFF_VTL + d * VTB + tok * 2) = vl;
            }
        }
    }
    for (int idx = tid; idx < 1185; idx += 640)
        *(float*)(smc + OFF_BIAS + idx * 4) = bias_table[idx * HEADS + head] * LOG2E;

    __syncthreads();

    int ai[2], ri[2];
    #pragma unroll
    for (int hh = 0; hh < 2; ++hh) {
        int mv = meta_s[wr + g + 8 * hh];
        ai[hh] = (mv & 255) + 112;
        ri[hh] = mv >> 8;
    }

    // ldmatrix per-lane address components
    const int l8  = lane & 7;
    const u32 krb = (u32)(l8 * ROWB + (lane >> 3) * 16);              // K: 4 tiles = kt0 b0,b1, kt1 b0,b1
    const u32 vrb = (u32)(l8 * VTB + (lane >> 3) * 16);               // V: same pattern
    const u32 qrb = (u32)((wr + l8 + ((lane >> 3) & 1) * 8) * ROWB + (lane >> 4) * 16); // A-tile

    // Q A-fragments: [hi/lo][kt][4] — one LDSM.x4 per (s,kt)
    u32 qa[2][2][4];
    #pragma unroll
    for (int s = 0; s < 2; ++s) {
        const u32 base = smb + (s ? OFF_QL : OFF_QH) + qrb;
        #pragma unroll
        for (int kt = 0; kt < 2; ++kt)
            ldsm4(qa[s][kt][0], qa[s][kt][1], qa[s][kt][2], qa[s][kt][3], base + kt * 32);
    }

    const u32 khb = smb + OFF_KH + krb, klb = smb + OFF_KL + krb;
    const u32 vhb = smb + OFF_VTH + vrb, vlb = smb + OFF_VTL + vrb;
    const u32 bib = smb + OFF_BIAS;

    float oacc[4][4];
    #pragma unroll
    for (int n = 0; n < 4; ++n)
        #pragma unroll
        for (int e = 0; e < 4; ++e) oacc[n][e] = 0.f;
    float lsum[2] = {0.f, 0.f};

    #pragma unroll 1
    for (int jc = 0; jc < 10; ++jc) {
        const int jb = jc * 32;
        float sacc[4][4];
        #pragma unroll
        for (int n = 0; n < 4; ++n)
            #pragma unroll
            for (int e = 0; e < 4; ++e) sacc[n][e] = 0.f;

        // ---- S = Q K^T : one hi + one lo LDSM.x4 per 8-key group ----
        #pragma unroll
        for (int n = 0; n < 4; ++n) {
            u32 kh[4], kl[4];
            ldsm4(kh[0], kh[1], kh[2], kh[3], khb + (jb + 8 * n) * ROWB);
            ldsm4(kl[0], kl[1], kl[2], kl[3], klb + (jb + 8 * n) * ROWB);
            float* c = sacc[n];
            mma16816(c[0], c[1], c[2], c[3],
                     qa[0][0][0], qa[0][0][1], qa[0][0][2], qa[0][0][3], kh[0], kh[1]);
            mma16816(c[0], c[1], c[2], c[3],
                     qa[0][0][0], qa[0][0][1], qa[0][0][2], qa[0][0][3], kl[0], kl[1]);
            mma16816(c[0], c[1], c[2], c[3],
                     qa[1][0][0], qa[1][0][1], qa[1][0][2], qa[1][0][3], kh[0], kh[1]);
            mma16816(c[0], c[1], c[2], c[3],
                     qa[0][1][0], qa[0][1][1], qa[0][1][2], qa[0][1][3], kh[2], kh[3]);
            mma16816(c[0], c[1], c[2], c[3],
                     qa[0][1][0], qa[0][1][1], qa[0][1][2], qa[0][1][3], kl[2], kl[3]);
            mma16816(c[0], c[1], c[2], c[3],
                     qa[1][1][0], qa[1][1][1], qa[1][1][2], qa[1][1][3], kh[2], kh[3]);
        }

        // ---- softmax ----
        #pragma unroll
        for (int n = 0; n < 4; ++n) {
            const int j0 = jb + 8 * n + 2 * t4;
            const int mj0 = meta_s[j0], mj1 = meta_s[j0 + 1];
            const int b0i = mj0 & 255, b1i = mj1 & 255;
            const int rj0 = mj0 >> 8,  rj1 = mj1 >> 8;
            float* c = sacc[n];
            float s0 = c[0] + lds32f(bib + (ai[0] - b0i) * 4);
            float s1 = c[1] + lds32f(bib + (ai[0] - b1i) * 4);
            float s2 = c[2] + lds32f(bib + (ai[1] - b0i) * 4);
            float s3 = c[3] + lds32f(bib + (ai[1] - b1i) * 4);
            float p0, p1, p2, p3;
            asm("ex2.approx.ftz.f32 %0,%1;" : "=f"(p0) : "f"(s0));
            asm("ex2.approx.ftz.f32 %0,%1;" : "=f"(p1) : "f"(s1));
            asm("ex2.approx.ftz.f32 %0,%1;" : "=f"(p2) : "f"(s2));
            asm("ex2.approx.ftz.f32 %0,%1;" : "=f"(p3) : "f"(s3));
            p0 = (ri[0] == rj0) ? p0 : 0.f;
            p1 = (ri[0] == rj1) ? p1 : 0.f;
            p2 = (ri[1] == rj0) ? p2 : 0.f;
            p3 = (ri[1] == rj1) ? p3 : 0.f;
            c[0] = p0; c[1] = p1; c[2] = p2; c[3] = p3;
            lsum[0] += p0 + p1;
            lsum[1] += p2 + p3;
        }

        // ---- P fragments (bf16 split) ----
        u32 pah[2][4], pal[2][4];
        #pragma unroll
        for (int kt = 0; kt < 2; ++kt) {
            const float* cA = sacc[2 * kt];
            const float* cB = sacc[2 * kt + 1];
            const float px[8] = {cA[0], cA[1], cA[2], cA[3], cB[0], cB[1], cB[2], cB[3]};
            #pragma unroll
            for (int e = 0; e < 4; ++e) {
                float x = px[2 * e], y = px[2 * e + 1];
                u32 hh = cvt2(x, y);
                float rx = x - __uint_as_float(hh << 16);
                float ry = y - __uint_as_float(hh & 0xffff0000u);
                pah[kt][e] = hh;
                pal[kt][e] = cvt2(rx, ry);
            }
        }

        // ---- O += P V : one hi + one lo LDSM.x4 per 8-dim group ----
        #pragma unroll
        for (int n = 0; n < 4; ++n) {
            u32 vh[4], vl[4];
            ldsm4(vh[0], vh[1], vh[2], vh[3], vhb + (8 * n) * VTB + jb * 2);
            ldsm4(vl[0], vl[1], vl[2], vl[3], vlb + (8 * n) * VTB + jb * 2);
            float* c = oacc[n];
            mma16816(c[0], c[1], c[2], c[3],
                     pah[0][0], pah[0][1], pah[0][2], pah[0][3], vh[0], vh[1]);
            mma16816(c[0], c[1], c[2], c[3],
                     pah[0][0], pah[0][1], pah[0][2], pah[0][3], vl[0], vl[1]);
            mma16816(c[0], c[1], c[2], c[3],
                     pal[0][0], pal[0][1], pal[0][2], pal[0][3], vh[0], vh[1]);
            mma16816(c[0], c[1], c[2], c[3],
                     pah[1][0], pah[1][1], pah[1][2], pah[1][3], vh[2], vh[3]);
            mma16816(c[0], c[1], c[2], c[3],
                     pah[1][0], pah[1][1], pah[1][2], pah[1][3], vl[2], vl[3]);
            mma16816(c[0], c[1], c[2], c[3],
                     pal[1][0], pal[1][1], pal[1][2], pal[1][3], vh[2], vh[3]);
        }
    }

    #pragma unroll
    for (int hh = 0; hh < 2; ++hh) {
        float v = lsum[hh];
        v += __shfl_xor_sync(0xffffffffu, v, 1);
        v += __shfl_xor_sync(0xffffffffu, v, 2);
        lsum[hh] = 1.0f / v;
    }

    #pragma unroll
    for (int hh = 0; hh < 2; ++hh) {
        const int r = wr + g + 8 * hh;
        float* orow = g_scratch + ((size_t)(wb * NTOK + r)) * DIM + head * HDIM;
        const float inv = lsum[hh];
        #pragma unroll
        for (int n = 0; n < 4; ++n) {
            float2 v = make_float2(oacc[n][2 * hh] * inv, oacc[n][2 * hh + 1] * inv);
            *(float2*)(orow + 8 * n + 2 * t4) = v;
        }
    }
}

// ---------------- projection kernel (tensor cores, bf16-split, ldmatrix) ----------------
// 512 threads / 16 warps as 4(m) x 4(n): warp tile 16 rows x 48 cols.
#define PWROW 400                      // padded W/o row bytes (200 bf16)
#define OFF_PWH 0
#define OFF_PWL 76800
#define OFF_POH 153600
#define OFF_POL 179200
#define PROJ_SMEM 204800

__global__ void __launch_bounds__(512)
proj_kernel(const float* __restrict__ pw, const float* __restrict__ pb,
            float* __restrict__ out, int nchunks)
{
    extern __shared__ char smc[];
    const u32 smb = (u32)__cvta_generic_to_shared(smc);
    const int tid = threadIdx.x, lane = tid & 31, warp = tid >> 5;
    const int g = lane >> 2, t4 = lane & 3;
    const int wm = warp >> 2, wn = warp & 3;   // 4 x 4
    const int m0 = wm * 16, n0 = wn * 48;

    // ---- stage W split once ----
    for (int idx = tid; idx < DIM * 96; idx += 512) {
        const int c = idx / 96, kp = idx % 96;
        float2 v = *(const float2*)(pw + c * DIM + kp * 2);
        u32 hi, lo; split_pair(v.x, v.y, hi, lo);
        *(u32*)(smc + OFF_PWH + c * PWROW + kp * 4) = hi;
        *(u32*)(smc + OFF_PWL + c * PWROW + kp * 4) = lo;
    }
    float pbv[6][2];
    #pragma unroll
    for (int nt = 0; nt < 6; ++nt) {
        float2 v = *(const float2*)(pb + n0 + nt * 8 + 2 * t4);
        pbv[nt][0] = v.x; pbv[nt][1] = v.y;
    }

    const int l8 = lane & 7;
    // A-tile (o chunk): rows m0.., 16x16 layout
    const u32 arb = (u32)((m0 + l8 + ((lane >> 3) & 1) * 8) * PWROW + (lane >> 4) * 16);
    // B-tile (W): pair p covers nt=2p (rows +0..7) and nt=2p+1 (rows +8..15)
    const u32 brb = (u32)((l8 + (lane >> 4) * 8) * PWROW + ((lane >> 3) & 1) * 16);

    const u32 whb = smb + OFF_PWH + brb, wlb = smb + OFF_PWL + brb;
    const u32 ohb = smb + OFF_POH + arb, olb = smb + OFF_POL + arb;

    for (int ci = blockIdx.x; ci < nchunks; ci += gridDim.x) {
        __syncthreads();   // W staged (first) / previous chunk consumed
        const float* src = g_scratch + (size_t)ci * (64 * DIM);
        #pragma unroll
        for (int it = 0; it < 12; ++it) {
            const int idx = tid + it * 512;       // 0..6143 float2s
            const int tok = idx / 96, kp = idx % 96;
            float2 v = *(const float2*)(src + tok * DIM + kp * 2);
            u32 hi, lo; split_pair(v.x, v.y, hi, lo);
            *(u32*)(smc + OFF_POH + tok * PWROW + kp * 4) = hi;
            *(u32*)(smc + OFF_POL + tok * PWROW + kp * 4) = lo;
        }
        __syncthreads();

        float acc[6][4];
        #pragma unroll
        for (int nt = 0; nt < 6; ++nt)
            #pragma unroll
            for (int e = 0; e < 4; ++e) acc[nt][e] = 0.f;

        #pragma unroll 1
        for (int ki = 0; ki < 12; ++ki) {
            u32 ah[4], al[4];
            ldsm4v(ah[0], ah[1], ah[2], ah[3], ohb + ki * 32);   // volatile: o rewritten per chunk
            ldsm4v(al[0], al[1], al[2], al[3], olb + ki * 32);
            #pragma unroll
            for (int p = 0; p < 3; ++p) {
                u32 bh[4], bl[4];
                const u32 bo = (u32)((n0 + 16 * p) * PWROW) + ki * 32;
                ldsm4(bh[0], bh[1], bh[2], bh[3], whb + bo);
                ldsm4(bl[0], bl[1], bl[2], bl[3], wlb + bo);
                float* c0 = acc[2 * p];
                float* c1 = acc[2 * p + 1];
                mma16816(c0[0], c0[1], c0[2], c0[3], ah[0], ah[1], ah[2], ah[3], bh[0], bh[1]);
                mma16816(c0[0], c0[1], c0[2], c0[3], ah[0], ah[1], ah[2], ah[3], bl[0], bl[1]);
                mma16816(c0[0], c0[1], c0[2], c0[3], al[0], al[1], al[2], al[3], bh[0], bh[1]);
                mma16816(c1[0], c1[1], c1[2], c1[3], ah[0], ah[1], ah[2], ah[3], bh[2], bh[3]);
                mma16816(c1[0], c1[1], c1[2], c1[3], ah[0], ah[1], ah[2], ah[3], bl[2], bl[3]);
                mma16816(c1[0], c1[1], c1[2], c1[3], al[0], al[1], al[2], al[3], bh[2], bh[3]);
            }
        }

        // ---- epilogue: bias + window-reverse scatter ----
        const int wbid = ci / 5, t = ci % 5;
        const int b = wbid >> 6, widx = wbid & 63;
        const int hw = widx >> 3, ww = widx & 7;
        #pragma unroll
        for (int hh = 0; hh < 2; ++hh) {
            const int s = m0 + g + 8 * hh;   // token 0..63
            const int hs = s >> 3, wsv = s & 7;
            const int h = (hw * 8 + hs + 4) & 63;
            const int w = (ww * 8 + wsv + 4) & 63;
            float* orow = out + ((size_t)((b * T_FRAMES + t) * 4096 + h * 64 + w)) * DIM;
            #pragma unroll
            for (int nt = 0; nt < 6; ++nt) {
                float2 v = make_float2(acc[nt][2 * hh]     + pbv[nt][0],
                                       acc[nt][2 * hh + 1] + pbv[nt][1]);
                *(float2*)(orow + n0 + nt * 8 + 2 * t4) = v;
            }
        }
    }
}

// ---------------- launch ----------------
extern "C" void kernel_launch(void* const* d_in, const int* in_sizes, int n_in,
                              void* d_out, int out_size)
{
    const float* qkv        = (const float*)d_in[0];
    const float* bias_table = (const float*)d_in[1];
    const float* pw         = (const float*)d_in[2];
    const float* pb         = (const float*)d_in[3];
    float* out = (float*)d_out;

    int B = in_sizes[0] / (T_FRAMES * 64 * 64 * 3 * DIM);
    if (B < 1) B = 1;
    if (B > 2) B = 2;   // scratch sized for B=2

    cudaFuncSetAttribute(attn_kernel, cudaFuncAttributeMaxDynamicSharedMemorySize, ATTN_SMEM);
    cudaFuncSetAttribute(proj_kernel, cudaFuncAttributeMaxDynamicSharedMemorySize, PROJ_SMEM);

    dim3 ag(B * 64, HEADS);
    attn_kernel<<<ag, 640, ATTN_SMEM>>>(qkv, bias_table);

    const int nchunks = B * 64 * T_FRAMES;
    int pgrid = nchunks < 148 ? nchunks : 148;
    proj_kernel<<<pgrid, 512, PROJ_SMEM>>>(pw, pb, out, nchunks);
}

// round 9
// speedup vs baseline: 2.9444x; 1.0104x over previous
#include <cuda_runtime.h>
#include <cuda_bf16.h>

typedef unsigned long long u64;
typedef unsigned int u32;

#define T_FRAMES 5
#define WS 8
#define HEADS 6
#define DIM 192
#define HDIM 32
#define NTOK 320

// scratch: per-window attention output, [wb][n][DIM], sized for B=2
__device__ float g_scratch[2 * 64 * NTOK * DIM];

// ---------------- small helpers ----------------
__device__ __forceinline__ float lds32f(u32 a) {
    float r; asm("ld.shared.b32 %0,[%1];" : "=f"(r) : "r"(a)); return r;
}
// ldmatrix x4: four 8x8 bf16 fragments in one instruction
__device__ __forceinline__ void ldsm4(u32 &r0, u32 &r1, u32 &r2, u32 &r3, u32 a) {
    asm("ldmatrix.sync.aligned.m8n8.x4.shared.b16 {%0,%1,%2,%3},[%4];"
        : "=r"(r0), "=r"(r1), "=r"(r2), "=r"(r3) : "r"(a));
}
__device__ __forceinline__ void ldsm4v(u32 &r0, u32 &r1, u32 &r2, u32 &r3, u32 a) {
    asm volatile("ldmatrix.sync.aligned.m8n8.x4.shared.b16 {%0,%1,%2,%3},[%4];"
        : "=r"(r0), "=r"(r1), "=r"(r2), "=r"(r3) : "r"(a));
}
// pack two f32 into bf16x2: low half = first arg
__device__ __forceinline__ u32 cvt2(float lo, float hi) {
    u32 r; asm("cvt.rn.bf16x2.f32 %0,%1,%2;" : "=r"(r) : "f"(hi), "f"(lo)); return r;
}
__device__ __forceinline__ void mma16816(float &c0, float &c1, float &c2, float &c3,
                                         u32 a0, u32 a1, u32 a2, u32 a3,
                                         u32 b0, u32 b1) {
    asm("mma.sync.aligned.m16n8k16.row.col.f32.bf16.bf16.f32 "
        "{%0,%1,%2,%3},{%4,%5,%6,%7},{%8,%9},{%0,%1,%2,%3};"
        : "+f"(c0), "+f"(c1), "+f"(c2), "+f"(c3)
        : "r"(a0), "r"(a1), "r"(a2), "r"(a3), "r"(b0), "r"(b1));
}
// split f32 pair into bf16x2 hi + bf16x2 lo (residual)
__device__ __forceinline__ void split_pair(float a, float b, u32 &h, u32 &l) {
    __nv_bfloat162 hv = __floats2bfloat162_rn(a, b);
    h = *(u32*)&hv;
    float ra = a - __bfloat162float(hv.x);
    float rb = b - __bfloat162float(hv.y);
    __nv_bfloat162 lv = __floats2bfloat162_rn(ra, rb);
    l = *(u32*)&lv;
}

// ---------------- attention kernel (tensor cores, bf16-split, ldmatrix) ----------------
// 640 threads / 20 warps; warp owns 16 query rows.
// Software-pipelined: body = softmax(jc); split; S(jc+1); PV(jc).
#define ROWB 80
#define VTB  656
#define OFF_QH   0
#define OFF_QL   25600
#define OFF_KH   51200
#define OFF_KL   76800
#define OFF_VTH  102400
#define OFF_VTL  123392
#define OFF_BIAS 144384
#define OFF_META 149124
#define ATTN_SMEM (150404)

__global__ void __launch_bounds__(640)
attn_kernel(const float* __restrict__ qkv, const float* __restrict__ bias_table)
{
    extern __shared__ char smc[];
    const u32 smb = (u32)__cvta_generic_to_shared(smc);
    int* meta_s = (int*)(smc + OFF_META);

    const int head = blockIdx.y;
    const int wb   = blockIdx.x;          // b*64 + widx
    const int b    = wb >> 6;
    const int widx = wb & 63;
    const int hw = widx >> 3, ww = widx & 7;

    const int tid  = threadIdx.x;         // 0..639
    const int lane = tid & 31;
    const int warp = tid >> 5;            // 0..19
    const int g    = lane >> 2;
    const int t4   = lane & 3;
    const int wr   = warp * 16;           // this warp's 16 query rows

    // staging: threads 0..319 handle Q+K of token tid; 320..639 handle V^T
    const bool qk_half = tid < 320;
    const int tok = qk_half ? tid : tid - 320;
    const int t   = tok >> 6;
    const int hs  = (tok >> 3) & 7;
    const int wsv = tok & 7;
    const int Hp = hw * 8 + hs;
    const int Wp = ww * 8 + wsv;
    const int h = (Hp + 4) & 63;
    const int w = (Wp + 4) & 63;
    const int rh = (Hp < 56) ? 0 : ((Hp < 60) ? 1 : 2);
    const int rw = (Wp < 56) ? 0 : ((Wp < 60) ? 1 : 2);
    if (qk_half)
        meta_s[tok] = (t * 15 + hs + wsv) | ((rh * 3 + rw) << 8);

    const int row = ((b * T_FRAMES + t) << 12) + (h << 6) + w;
    const float* qp = qkv + (size_t)row * (3 * DIM) + head * HDIM;

    const float LOG2E = 1.4426950408889634f;
    const float qs_f = 0.17677669529663687f * LOG2E;

    if (qk_half) {
        const float4* qv = (const float4*)qp;
        const float4* kv = (const float4*)(qp + DIM);
        #pragma unroll
        for (int m = 0; m < 8; ++m) {
            float4 f = qv[m];
            u32 h0, l0, h1, l1;
            split_pair(f.x * qs_f, f.y * qs_f, h0, l0);
            split_pair(f.z * qs_f, f.w * qs_f, h1, l1);
            const int off = tok * ROWB + m * 8;
            *(u32*)(smc + OFF_QH + off) = h0;  *(u32*)(smc + OFF_QH + off + 4) = h1;
            *(u32*)(smc + OFF_QL + off) = l0;  *(u32*)(smc + OFF_QL + off + 4) = l1;
        }
        #pragma unroll
        for (int m = 0; m < 8; ++m) {
            float4 f = kv[m];
            u32 h0, l0, h1, l1;
            split_pair(f.x, f.y, h0, l0);
            split_pair(f.z, f.w, h1, l1);
            const int off = tok * ROWB + m * 8;
            *(u32*)(smc + OFF_KH + off) = h0;  *(u32*)(smc + OFF_KH + off + 4) = h1;
            *(u32*)(smc + OFF_KL + off) = l0;  *(u32*)(smc + OFF_KL + off + 4) = l1;
        }
    } else {
        const float4* vv = (const float4*)(qp + 2 * DIM);
        #pragma unroll
        for (int m = 0; m < 8; ++m) {
            float4 f = vv[m];
            float vals[4] = {f.x, f.y, f.z, f.w};
            #pragma unroll
            for (int e = 0; e < 4; ++e) {
                const int d = m * 4 + e;
                __nv_bfloat16 vh = __float2bfloat16_rn(vals[e]);
                float rsd = vals[e] - __bfloat162float(vh);
                __nv_bfloat16 vl = __float2bfloat16_rn(rsd);
                *(__nv_bfloat16*)(smc + OFF_VTH + d * VTB + tok * 2) = vh;
                *(__nv_bfloat16*)(smc + OFF_VTL + d * VTB + tok * 2) = vl;
            }
        }
    }
    for (int idx = tid; idx < 1185; idx += 640)
        *(float*)(smc + OFF_BIAS + idx * 4) = bias_table[idx * HEADS + head] * LOG2E;

    __syncthreads();

    int ai[2], ri[2];
    #pragma unroll
    for (int hh = 0; hh < 2; ++hh) {
        int mv = meta_s[wr + g + 8 * hh];
        ai[hh] = (mv & 255) + 112;
        ri[hh] = mv >> 8;
    }

    // ldmatrix per-lane address components
    const int l8  = lane & 7;
    const u32 krb = (u32)(l8 * ROWB + (lane >> 3) * 16);
    const u32 vrb = (u32)(l8 * VTB + (lane >> 3) * 16);
    const u32 qrb = (u32)((wr + l8 + ((lane >> 3) & 1) * 8) * ROWB + (lane >> 4) * 16);

    // Q A-fragments: [hi/lo][kt][4]
    u32 qa[2][2][4];
    #pragma unroll
    for (int s = 0; s < 2; ++s) {
        const u32 base = smb + (s ? OFF_QL : OFF_QH) + qrb;
        #pragma unroll
        for (int kt = 0; kt < 2; ++kt)
            ldsm4(qa[s][kt][0], qa[s][kt][1], qa[s][kt][2], qa[s][kt][3], base + kt * 32);
    }

    const u32 khb = smb + OFF_KH + krb, klb = smb + OFF_KL + krb;
    const u32 vhb = smb + OFF_VTH + vrb, vlb = smb + OFF_VTL + vrb;
    const u32 bib = smb + OFF_BIAS;

    float oacc[4][4];
    #pragma unroll
    for (int n = 0; n < 4; ++n)
        #pragma unroll
        for (int e = 0; e < 4; ++e) oacc[n][e] = 0.f;
    float lsum[2] = {0.f, 0.f};

    float sacc[4][4];
    u32 pah[2][4], pal[2][4];

    // ---- S block: zero sacc, compute S for key block at jb2 ----
    auto s_block = [&](int jb2) {
        #pragma unroll
        for (int n = 0; n < 4; ++n)
            #pragma unroll
            for (int e = 0; e < 4; ++e) sacc[n][e] = 0.f;
        #pragma unroll
        for (int n = 0; n < 4; ++n) {
            u32 kh[4], kl[4];
            ldsm4(kh[0], kh[1], kh[2], kh[3], khb + (jb2 + 8 * n) * ROWB);
            ldsm4(kl[0], kl[1], kl[2], kl[3], klb + (jb2 + 8 * n) * ROWB);
            float* c = sacc[n];
            mma16816(c[0], c[1], c[2], c[3],
                     qa[0][0][0], qa[0][0][1], qa[0][0][2], qa[0][0][3], kh[0], kh[1]);
            mma16816(c[0], c[1], c[2], c[3],
                     qa[0][0][0], qa[0][0][1], qa[0][0][2], qa[0][0][3], kl[0], kl[1]);
            mma16816(c[0], c[1], c[2], c[3],
                     qa[1][0][0], qa[1][0][1], qa[1][0][2], qa[1][0][3], kh[0], kh[1]);
            mma16816(c[0], c[1], c[2], c[3],
                     qa[0][1][0], qa[0][1][1], qa[0][1][2], qa[0][1][3], kh[2], kh[3]);
            mma16816(c[0], c[1], c[2], c[3],
                     qa[0][1][0], qa[0][1][1], qa[0][1][2], qa[0][1][3], kl[2], kl[3]);
            mma16816(c[0], c[1], c[2], c[3],
                     qa[1][1][0], qa[1][1][1], qa[1][1][2], qa[1][1][3], kh[2], kh[3]);
        }
    };

    // ---- softmax + P-split for key block jb2 (consumes sacc -> pah/pal) ----
    auto sm_block = [&](int jb2) {
        #pragma unroll
        for (int n = 0; n < 4; ++n) {
            const int j0 = jb2 + 8 * n + 2 * t4;
            const int mj0 = meta_s[j0], mj1 = meta_s[j0 + 1];
            const int b0i = mj0 & 255, b1i = mj1 & 255;
            const int rj0 = mj0 >> 8,  rj1 = mj1 >> 8;
            float* c = sacc[n];
            float s0 = c[0] + lds32f(bib + (ai[0] - b0i) * 4);
            float s1 = c[1] + lds32f(bib + (ai[0] - b1i) * 4);
            float s2 = c[2] + lds32f(bib + (ai[1] - b0i) * 4);
            float s3 = c[3] + lds32f(bib + (ai[1] - b1i) * 4);
            float p0, p1, p2, p3;
            asm("ex2.approx.ftz.f32 %0,%1;" : "=f"(p0) : "f"(s0));
            asm("ex2.approx.ftz.f32 %0,%1;" : "=f"(p1) : "f"(s1));
            asm("ex2.approx.ftz.f32 %0,%1;" : "=f"(p2) : "f"(s2));
            asm("ex2.approx.ftz.f32 %0,%1;" : "=f"(p3) : "f"(s3));
            p0 = (ri[0] == rj0) ? p0 : 0.f;
            p1 = (ri[0] == rj1) ? p1 : 0.f;
            p2 = (ri[1] == rj0) ? p2 : 0.f;
            p3 = (ri[1] == rj1) ? p3 : 0.f;
            c[0] = p0; c[1] = p1; c[2] = p2; c[3] = p3;
            lsum[0] += p0 + p1;
            lsum[1] += p2 + p3;
        }
        #pragma unroll
        for (int kt = 0; kt < 2; ++kt) {
            const float* cA = sacc[2 * kt];
            const float* cB = sacc[2 * kt + 1];
            const float px[8] = {cA[0], cA[1], cA[2], cA[3], cB[0], cB[1], cB[2], cB[3]};
            #pragma unroll
            for (int e = 0; e < 4; ++e) {
                float x = px[2 * e], y = px[2 * e + 1];
                u32 hh = cvt2(x, y);
                float rx = x - __uint_as_float(hh << 16);
                float ry = y - __uint_as_float(hh & 0xffff0000u);
                pah[kt][e] = hh;
                pal[kt][e] = cvt2(rx, ry);
            }
        }
    };

    // ---- PV block for key block jb2 (consumes pah/pal -> oacc) ----
    auto pv_block = [&](int jb2) {
        #pragma unroll
        for (int n = 0; n < 4; ++n) {
            u32 vh[4], vl[4];
            ldsm4(vh[0], vh[1], vh[2], vh[3], vhb + (8 * n) * VTB + jb2 * 2);
            ldsm4(vl[0], vl[1], vl[2], vl[3], vlb + (8 * n) * VTB + jb2 * 2);
            float* c = oacc[n];
            mma16816(c[0], c[1], c[2], c[3],
                     pah[0][0], pah[0][1], pah[0][2], pah[0][3], vh[0], vh[1]);
            mma16816(c[0], c[1], c[2], c[3],
                     pah[0][0], pah[0][1], pah[0][2], pah[0][3], vl[0], vl[1]);
            mma16816(c[0], c[1], c[2], c[3],
                     pal[0][0], pal[0][1], pal[0][2], pal[0][3], vh[0], vh[1]);
            mma16816(c[0], c[1], c[2], c[3],
                     pah[1][0], pah[1][1], pah[1][2], pah[1][3], vh[2], vh[3]);
            mma16816(c[0], c[1], c[2], c[3],
                     pah[1][0], pah[1][1], pah[1][2], pah[1][3], vl[2], vl[3]);
            mma16816(c[0], c[1], c[2], c[3],
                     pal[1][0], pal[1][1], pal[1][2], pal[1][3], vh[2], vh[3]);
        }
    };

    // ---- software-pipelined mainloop ----
    s_block(0);
    #pragma unroll 1
    for (int jc = 0; jc < 9; ++jc) {
        const int jb = jc * 32;
        sm_block(jb);        // consumes sacc(jc)
        s_block(jb + 32);    // independent of softmax/PV -> overlaps
        pv_block(jb);        // consumes pah/pal(jc)
    }
    sm_block(288);
    pv_block(288);

    #pragma unroll
    for (int hh = 0; hh < 2; ++hh) {
        float v = lsum[hh];
        v += __shfl_xor_sync(0xffffffffu, v, 1);
        v += __shfl_xor_sync(0xffffffffu, v, 2);
        lsum[hh] = 1.0f / v;
    }

    #pragma unroll
    for (int hh = 0; hh < 2; ++hh) {
        const int r = wr + g + 8 * hh;
        float* orow = g_scratch + ((size_t)(wb * NTOK + r)) * DIM + head * HDIM;
        const float inv = lsum[hh];
        #pragma unroll
        for (int n = 0; n < 4; ++n) {
            float2 v = make_float2(oacc[n][2 * hh] * inv, oacc[n][2 * hh + 1] * inv);
            *(float2*)(orow + 8 * n + 2 * t4) = v;
        }
    }
}

// ---------------- projection kernel (tensor cores, bf16-split, ldmatrix) ----------------
// 512 threads / 16 warps as 4(m) x 4(n). Double-buffered o staging via registers.
#define PWROW 400                      // padded W/o row bytes (200 bf16)
#define OFF_PWH 0
#define OFF_PWL 76800
#define OFF_POH 153600
#define OFF_POL 179200
#define PROJ_SMEM 204800

__global__ void __launch_bounds__(512)
proj_kernel(const float* __restrict__ pw, const float* __restrict__ pb,
            float* __restrict__ out, int nchunks)
{
    extern __shared__ char smc[];
    const u32 smb = (u32)__cvta_generic_to_shared(smc);
    const int tid = threadIdx.x, lane = tid & 31, warp = tid >> 5;
    const int g = lane >> 2, t4 = lane & 3;
    const int wm = warp >> 2, wn = warp & 3;   // 4 x 4
    const int m0 = wm * 16, n0 = wn * 48;

    // ---- stage W split once ----
    for (int idx = tid; idx < DIM * 96; idx += 512) {
        const int c = idx / 96, kp = idx % 96;
        float2 v = *(const float2*)(pw + c * DIM + kp * 2);
        u32 hi, lo; split_pair(v.x, v.y, hi, lo);
        *(u32*)(smc + OFF_PWH + c * PWROW + kp * 4) = hi;
        *(u32*)(smc + OFF_PWL + c * PWROW + kp * 4) = lo;
    }
    float pbv[6][2];
    #pragma unroll
    for (int nt = 0; nt < 6; ++nt) {
        float2 v = *(const float2*)(pb + n0 + nt * 8 + 2 * t4);
        pbv[nt][0] = v.x; pbv[nt][1] = v.y;
    }

    const int l8 = lane & 7;
    const u32 arb = (u32)((m0 + l8 + ((lane >> 3) & 1) * 8) * PWROW + (lane >> 4) * 16);
    const u32 brb = (u32)((l8 + (lane >> 4) * 8) * PWROW + ((lane >> 3) & 1) * 16);

    const u32 whb = smb + OFF_PWH + brb, wlb = smb + OFF_PWL + brb;
    const u32 ohb = smb + OFF_POH + arb, olb = smb + OFF_POL + arb;

    // per-thread staging offsets (idx = tid + it*512 -> tok, kp)
    // prefetch buffer for double-buffered staging
    float2 pre[12];
    int ci = blockIdx.x;
    if (ci < nchunks) {
        const float* src = g_scratch + (size_t)ci * (64 * DIM);
        #pragma unroll
        for (int it = 0; it < 12; ++it) {
            const int idx = tid + it * 512;
            const int tok = idx / 96, kp = idx % 96;
            pre[it] = *(const float2*)(src + tok * DIM + kp * 2);
        }
    }

    #pragma unroll 1
    for (; ci < nchunks; ci += gridDim.x) {
        __syncthreads();   // W staged (first) / previous chunk's LDSMs done
        #pragma unroll
        for (int it = 0; it < 12; ++it) {
            const int idx = tid + it * 512;
            const int tok = idx / 96, kp = idx % 96;
            u32 hi, lo; split_pair(pre[it].x, pre[it].y, hi, lo);
            *(u32*)(smc + OFF_POH + tok * PWROW + kp * 4) = hi;
            *(u32*)(smc + OFF_POL + tok * PWROW + kp * 4) = lo;
        }
        __syncthreads();

        // prefetch next chunk while this chunk computes
        const int cin = ci + gridDim.x;
        if (cin < nchunks) {
            const float* srcn = g_scratch + (size_t)cin * (64 * DIM);
            #pragma unroll
            for (int it = 0; it < 12; ++it) {
                const int idx = tid + it * 512;
                const int tok = idx / 96, kp = idx % 96;
                pre[it] = *(const float2*)(srcn + tok * DIM + kp * 2);
            }
        }

        float acc[6][4];
        #pragma unroll
        for (int nt = 0; nt < 6; ++nt)
            #pragma unroll
            for (int e = 0; e < 4; ++e) acc[nt][e] = 0.f;

        #pragma unroll 1
        for (int ki = 0; ki < 12; ++ki) {
            u32 ah[4], al[4];
            ldsm4v(ah[0], ah[1], ah[2], ah[3], ohb + ki * 32);
            ldsm4v(al[0], al[1], al[2], al[3], olb + ki * 32);
            #pragma unroll
            for (int p = 0; p < 3; ++p) {
                u32 bh[4], bl[4];
                const u32 bo = (u32)((n0 + 16 * p) * PWROW) + ki * 32;
                ldsm4(bh[0], bh[1], bh[2], bh[3], whb + bo);
                ldsm4(bl[0], bl[1], bl[2], bl[3], wlb + bo);
                float* c0 = acc[2 * p];
                float* c1 = acc[2 * p + 1];
                mma16816(c0[0], c0[1], c0[2], c0[3], ah[0], ah[1], ah[2], ah[3], bh[0], bh[1]);
                mma16816(c0[0], c0[1], c0[2], c0[3], ah[0], ah[1], ah[2], ah[3], bl[0], bl[1]);
                mma16816(c0[0], c0[1], c0[2], c0[3], al[0], al[1], al[2], al[3], bh[0], bh[1]);
                mma16816(c1[0], c1[1], c1[2], c1[3], ah[0], ah[1], ah[2], ah[3], bh[2], bh[3]);
                mma16816(c1[0], c1[1], c1[2], c1[3], ah[0], ah[1], ah[2], ah[3], bl[2], bl[3]);
                mma16816(c1[0], c1[1], c1[2], c1[3], al[0], al[1], al[2], al[3], bh[2], bh[3]);
            }
        }

        // ---- epilogue: bias + window-reverse scatter ----
        const int wbid = ci / 5, t = ci % 5;
        const int b = wbid >> 6, widx = wbid & 63;
        const int hw = widx >> 3, ww = widx & 7;
        #pragma unroll
        for (int hh = 0; hh < 2; ++hh) {
            const int s = m0 + g + 8 * hh;   // token 0..63
            const int hs = s >> 3, wsv = s & 7;
            const int h = (hw * 8 + hs + 4) & 63;
            const int w = (ww * 8 + wsv + 4) & 63;
            float* orow = out + ((size_t)((b * T_FRAMES + t) * 4096 + h * 64 + w)) * DIM;
            #pragma unroll
            for (int nt = 0; nt < 6; ++nt) {
                float2 v = make_float2(acc[nt][2 * hh]     + pbv[nt][0],
                                       acc[nt][2 * hh + 1] + pbv[nt][1]);
                *(float2*)(orow + n0 + nt * 8 + 2 * t4) = v;
            }
        }
    }
}

// ---------------- launch ----------------
extern "C" void kernel_launch(void* const* d_in, const int* in_sizes, int n_in,
                              void* d_out, int out_size)
{
    const float* qkv        = (const float*)d_in[0];
    const float* bias_table = (const float*)d_in[1];
    const float* pw         = (const float*)d_in[2];
    const float* pb         = (const float*)d_in[3];
    float* out = (float*)d_out;

    int B = in_sizes[0] / (T_FRAMES * 64 * 64 * 3 * DIM);
    if (B < 1) B = 1;
    if (B > 2) B = 2;   // scratch sized for B=2

    cudaFuncSetAttribute(attn_kernel, cudaFuncAttributeMaxDynamicSharedMemorySize, ATTN_SMEM);
    cudaFuncSetAttribute(proj_kernel, cudaFuncAttributeMaxDynamicSharedMemorySize, PROJ_SMEM);

    dim3 ag(B * 64, HEADS);
    attn_kernel<<<ag, 640, ATTN_SMEM>>>(qkv, bias_table);

    const int nchunks = B * 64 * T_FRAMES;
    int pgrid = nchunks < 148 ? nchunks : 148;
    proj_kernel<<<pgrid, 512, PROJ_SMEM>>>(pw, pb, out, nchunks);
}

// round 10
// speedup vs baseline: 3.0142x; 1.0237x over previous
#include <cuda_runtime.h>
#include <cuda_bf16.h>

typedef unsigned long long u64;
typedef unsigned int u32;

#define T_FRAMES 5
#define WS 8
#define HEADS 6
#define DIM 192
#define HDIM 32
#define NTOK 320

// scratch: per-window attention output, [wb][n][DIM], sized for B=2
__device__ float g_scratch[2 * 64 * NTOK * DIM];

// ---------------- small helpers ----------------
__device__ __forceinline__ float lds32f(u32 a) {
    float r; asm("ld.shared.b32 %0,[%1];" : "=f"(r) : "r"(a)); return r;
}
__device__ __forceinline__ void ldsm4(u32 &r0, u32 &r1, u32 &r2, u32 &r3, u32 a) {
    asm("ldmatrix.sync.aligned.m8n8.x4.shared.b16 {%0,%1,%2,%3},[%4];"
        : "=r"(r0), "=r"(r1), "=r"(r2), "=r"(r3) : "r"(a));
}
__device__ __forceinline__ void ldsm4v(u32 &r0, u32 &r1, u32 &r2, u32 &r3, u32 a) {
    asm volatile("ldmatrix.sync.aligned.m8n8.x4.shared.b16 {%0,%1,%2,%3},[%4];"
        : "=r"(r0), "=r"(r1), "=r"(r2), "=r"(r3) : "r"(a));
}
__device__ __forceinline__ void ldsm2(u32 &r0, u32 &r1, u32 a) {
    asm("ldmatrix.sync.aligned.m8n8.x2.shared.b16 {%0,%1},[%2];"
        : "=r"(r0), "=r"(r1) : "r"(a));
}
// pack two f32 into bf16x2: low half = first arg
__device__ __forceinline__ u32 cvt2(float lo, float hi) {
    u32 r; asm("cvt.rn.bf16x2.f32 %0,%1,%2;" : "=r"(r) : "f"(hi), "f"(lo)); return r;
}
__device__ __forceinline__ void mma16816(float &c0, float &c1, float &c2, float &c3,
                                         u32 a0, u32 a1, u32 a2, u32 a3,
                                         u32 b0, u32 b1) {
    asm("mma.sync.aligned.m16n8k16.row.col.f32.bf16.bf16.f32 "
        "{%0,%1,%2,%3},{%4,%5,%6,%7},{%8,%9},{%0,%1,%2,%3};"
        : "+f"(c0), "+f"(c1), "+f"(c2), "+f"(c3)
        : "r"(a0), "r"(a1), "r"(a2), "r"(a3), "r"(b0), "r"(b1));
}
// split f32 pair into bf16x2 hi + bf16x2 lo (residual)
__device__ __forceinline__ void split_pair(float a, float b, u32 &h, u32 &l) {
    __nv_bfloat162 hv = __floats2bfloat162_rn(a, b);
    h = *(u32*)&hv;
    float ra = a - __bfloat162float(hv.x);
    float rb = b - __bfloat162float(hv.y);
    __nv_bfloat162 lv = __floats2bfloat162_rn(ra, rb);
    l = *(u32*)&lv;
}

// ---------------- attention kernel (tensor cores, bf16-split, ldmatrix) ----------------
// 640 threads / 20 warps; warp owns 16 query rows.
// Fine-grained interleave: sm(n01) split(kt0) PV(kt0) sm(n23) split(kt1) S(jc+1) PV(kt1).
#define ROWB 80
#define VTB  656
#define OFF_QH   0
#define OFF_QL   25600
#define OFF_KH   51200
#define OFF_KL   76800
#define OFF_VTH  102400
#define OFF_VTL  123392
#define OFF_BIAS 144384
#define OFF_META 149124
#define ATTN_SMEM (150404)

__global__ void __launch_bounds__(640)
attn_kernel(const float* __restrict__ qkv, const float* __restrict__ bias_table)
{
    extern __shared__ char smc[];
    const u32 smb = (u32)__cvta_generic_to_shared(smc);
    int* meta_s = (int*)(smc + OFF_META);

    const int head = blockIdx.y;
    const int wb   = blockIdx.x;          // b*64 + widx
    const int b    = wb >> 6;
    const int widx = wb & 63;
    const int hw = widx >> 3, ww = widx & 7;

    const int tid  = threadIdx.x;         // 0..639
    const int lane = tid & 31;
    const int warp = tid >> 5;            // 0..19
    const int g    = lane >> 2;
    const int t4   = lane & 3;
    const int wr   = warp * 16;           // this warp's 16 query rows

    // staging: threads 0..319 handle Q+K of token tid; 320..639 handle V^T
    const bool qk_half = tid < 320;
    const int tok = qk_half ? tid : tid - 320;
    const int t   = tok >> 6;
    const int hs  = (tok >> 3) & 7;
    const int wsv = tok & 7;
    const int Hp = hw * 8 + hs;
    const int Wp = ww * 8 + wsv;
    const int h = (Hp + 4) & 63;
    const int w = (Wp + 4) & 63;
    const int rh = (Hp < 56) ? 0 : ((Hp < 60) ? 1 : 2);
    const int rw = (Wp < 56) ? 0 : ((Wp < 60) ? 1 : 2);
    if (qk_half)
        meta_s[tok] = (t * 15 + hs + wsv) | ((rh * 3 + rw) << 8);

    const int row = ((b * T_FRAMES + t) << 12) + (h << 6) + w;
    const float* qp = qkv + (size_t)row * (3 * DIM) + head * HDIM;

    const float LOG2E = 1.4426950408889634f;
    const float qs_f = 0.17677669529663687f * LOG2E;

    if (qk_half) {
        const float4* qv = (const float4*)qp;
        const float4* kv = (const float4*)(qp + DIM);
        #pragma unroll
        for (int m = 0; m < 8; ++m) {
            float4 f = qv[m];
            u32 h0, l0, h1, l1;
            split_pair(f.x * qs_f, f.y * qs_f, h0, l0);
            split_pair(f.z * qs_f, f.w * qs_f, h1, l1);
            const int off = tok * ROWB + m * 8;
            *(u32*)(smc + OFF_QH + off) = h0;  *(u32*)(smc + OFF_QH + off + 4) = h1;
            *(u32*)(smc + OFF_QL + off) = l0;  *(u32*)(smc + OFF_QL + off + 4) = l1;
        }
        #pragma unroll
        for (int m = 0; m < 8; ++m) {
            float4 f = kv[m];
            u32 h0, l0, h1, l1;
            split_pair(f.x, f.y, h0, l0);
            split_pair(f.z, f.w, h1, l1);
            const int off = tok * ROWB + m * 8;
            *(u32*)(smc + OFF_KH + off) = h0;  *(u32*)(smc + OFF_KH + off + 4) = h1;
            *(u32*)(smc + OFF_KL + off) = l0;  *(u32*)(smc + OFF_KL + off + 4) = l1;
        }
    } else {
        const float4* vv = (const float4*)(qp + 2 * DIM);
        #pragma unroll
        for (int m = 0; m < 8; ++m) {
            float4 f = vv[m];
            float vals[4] = {f.x, f.y, f.z, f.w};
            #pragma unroll
            for (int e = 0; e < 4; ++e) {
                const int d = m * 4 + e;
                __nv_bfloat16 vh = __float2bfloat16_rn(vals[e]);
                float rsd = vals[e] - __bfloat162float(vh);
                __nv_bfloat16 vl = __float2bfloat16_rn(rsd);
                *(__nv_bfloat16*)(smc + OFF_VTH + d * VTB + tok * 2) = vh;
                *(__nv_bfloat16*)(smc + OFF_VTL + d * VTB + tok * 2) = vl;
            }
        }
    }
    for (int idx = tid; idx < 1185; idx += 640)
        *(float*)(smc + OFF_BIAS + idx * 4) = bias_table[idx * HEADS + head] * LOG2E;

    __syncthreads();

    int ai[2], ri[2];
    #pragma unroll
    for (int hh = 0; hh < 2; ++hh) {
        int mv = meta_s[wr + g + 8 * hh];
        ai[hh] = (mv & 255) + 112;
        ri[hh] = mv >> 8;
    }

    // ldmatrix per-lane address components
    const int l8  = lane & 7;
    const u32 krb = (u32)(l8 * ROWB + (lane >> 3) * 16);
    const u32 vrb = (u32)(l8 * VTB + (lane >> 3) * 16);
    const u32 qrb = (u32)((wr + l8 + ((lane >> 3) & 1) * 8) * ROWB + (lane >> 4) * 16);

    // Q A-fragments: [hi/lo][kt][4]
    u32 qa[2][2][4];
    #pragma unroll
    for (int s = 0; s < 2; ++s) {
        const u32 base = smb + (s ? OFF_QL : OFF_QH) + qrb;
        #pragma unroll
        for (int kt = 0; kt < 2; ++kt)
            ldsm4(qa[s][kt][0], qa[s][kt][1], qa[s][kt][2], qa[s][kt][3], base + kt * 32);
    }

    const u32 khb = smb + OFF_KH + krb, klb = smb + OFF_KL + krb;
    const u32 vhb = smb + OFF_VTH + vrb, vlb = smb + OFF_VTL + vrb;
    const u32 bib = smb + OFF_BIAS;

    float oacc[4][4];
    #pragma unroll
    for (int n = 0; n < 4; ++n)
        #pragma unroll
        for (int e = 0; e < 4; ++e) oacc[n][e] = 0.f;
    float lsum[2] = {0.f, 0.f};

    float sacc[4][4];

    // ---- S block: zero sacc, compute S for key block at jb2 ----
    auto s_block = [&](int jb2) {
        #pragma unroll
        for (int n = 0; n < 4; ++n)
            #pragma unroll
            for (int e = 0; e < 4; ++e) sacc[n][e] = 0.f;
        #pragma unroll
        for (int n = 0; n < 4; ++n) {
            u32 kh[4], kl[4];
            ldsm4(kh[0], kh[1], kh[2], kh[3], khb + (jb2 + 8 * n) * ROWB);
            ldsm4(kl[0], kl[1], kl[2], kl[3], klb + (jb2 + 8 * n) * ROWB);
            float* c = sacc[n];
            mma16816(c[0], c[1], c[2], c[3],
                     qa[0][0][0], qa[0][0][1], qa[0][0][2], qa[0][0][3], kh[0], kh[1]);
            mma16816(c[0], c[1], c[2], c[3],
                     qa[0][0][0], qa[0][0][1], qa[0][0][2], qa[0][0][3], kl[0], kl[1]);
            mma16816(c[0], c[1], c[2], c[3],
                     qa[1][0][0], qa[1][0][1], qa[1][0][2], qa[1][0][3], kh[0], kh[1]);
            mma16816(c[0], c[1], c[2], c[3],
                     qa[0][1][0], qa[0][1][1], qa[0][1][2], qa[0][1][3], kh[2], kh[3]);
            mma16816(c[0], c[1], c[2], c[3],
                     qa[0][1][0], qa[0][1][1], qa[0][1][2], qa[0][1][3], kl[2], kl[3]);
            mma16816(c[0], c[1], c[2], c[3],
                     qa[1][1][0], qa[1][1][1], qa[1][1][2], qa[1][1][3], kh[2], kh[3]);
        }
    };

    // ---- softmax for one 8-key group n of block jb2 ----
    auto sm_n = [&](int jb2, int n) {
        const int j0 = jb2 + 8 * n + 2 * t4;
        const int mj0 = meta_s[j0], mj1 = meta_s[j0 + 1];
        const int b0i = mj0 & 255, b1i = mj1 & 255;
        const int rj0 = mj0 >> 8,  rj1 = mj1 >> 8;
        float* c = sacc[n];
        float s0 = c[0] + lds32f(bib + (ai[0] - b0i) * 4);
        float s1 = c[1] + lds32f(bib + (ai[0] - b1i) * 4);
        float s2 = c[2] + lds32f(bib + (ai[1] - b0i) * 4);
        float s3 = c[3] + lds32f(bib + (ai[1] - b1i) * 4);
        float p0, p1, p2, p3;
        asm("ex2.approx.ftz.f32 %0,%1;" : "=f"(p0) : "f"(s0));
        asm("ex2.approx.ftz.f32 %0,%1;" : "=f"(p1) : "f"(s1));
        asm("ex2.approx.ftz.f32 %0,%1;" : "=f"(p2) : "f"(s2));
        asm("ex2.approx.ftz.f32 %0,%1;" : "=f"(p3) : "f"(s3));
        p0 = (ri[0] == rj0) ? p0 : 0.f;
        p1 = (ri[0] == rj1) ? p1 : 0.f;
        p2 = (ri[1] == rj0) ? p2 : 0.f;
        p3 = (ri[1] == rj1) ? p3 : 0.f;
        c[0] = p0; c[1] = p1; c[2] = p2; c[3] = p3;
        lsum[0] += p0 + p1;
        lsum[1] += p2 + p3;
    };

    // ---- split P fragments for one kt half (consumes sacc[2kt],[2kt+1]) ----
    auto split_kt = [&](int kt, u32* ph, u32* pl) {
        const float* cA = sacc[2 * kt];
        const float* cB = sacc[2 * kt + 1];
        const float px[8] = {cA[0], cA[1], cA[2], cA[3], cB[0], cB[1], cB[2], cB[3]};
        #pragma unroll
        for (int e = 0; e < 4; ++e) {
            float x = px[2 * e], y = px[2 * e + 1];
            u32 hh = cvt2(x, y);
            float rx = x - __uint_as_float(hh << 16);
            float ry = y - __uint_as_float(hh & 0xffff0000u);
            ph[e] = hh;
            pl[e] = cvt2(rx, ry);
        }
    };

    // ---- PV for one kt half ----
    auto pv_kt = [&](int jb2, int kt, const u32* ph, const u32* pl) {
        #pragma unroll
        for (int n = 0; n < 4; ++n) {
            u32 vh0, vh1, vl0, vl1;
            const u32 off = (8 * n) * VTB + jb2 * 2 + kt * 32;
            ldsm2(vh0, vh1, vhb + off);
            ldsm2(vl0, vl1, vlb + off);
            float* c = oacc[n];
            mma16816(c[0], c[1], c[2], c[3], ph[0], ph[1], ph[2], ph[3], vh0, vh1);
            mma16816(c[0], c[1], c[2], c[3], ph[0], ph[1], ph[2], ph[3], vl0, vl1);
            mma16816(c[0], c[1], c[2], c[3], pl[0], pl[1], pl[2], pl[3], vh0, vh1);
        }
    };

    // ---- software-pipelined mainloop, half-jc interleave ----
    s_block(0);
    #pragma unroll 1
    for (int jc = 0; jc < 9; ++jc) {
        const int jb = jc * 32;
        sm_n(jb, 0);
        sm_n(jb, 1);
        u32 ph0[4], pl0[4];
        split_kt(0, ph0, pl0);
        pv_kt(jb, 0, ph0, pl0);       // tensor work behind softmax latency
        sm_n(jb, 2);
        sm_n(jb, 3);
        u32 ph1[4], pl1[4];
        split_kt(1, ph1, pl1);        // sacc fully consumed after this
        s_block(jb + 32);             // next-S tensor work covers split latency
        pv_kt(jb, 1, ph1, pl1);
    }
    {
        const int jb = 288;
        sm_n(jb, 0); sm_n(jb, 1);
        u32 ph0[4], pl0[4];
        split_kt(0, ph0, pl0);
        pv_kt(jb, 0, ph0, pl0);
        sm_n(jb, 2); sm_n(jb, 3);
        u32 ph1[4], pl1[4];
        split_kt(1, ph1, pl1);
        pv_kt(jb, 1, ph1, pl1);
    }

    #pragma unroll
    for (int hh = 0; hh < 2; ++hh) {
        float v = lsum[hh];
        v += __shfl_xor_sync(0xffffffffu, v, 1);
        v += __shfl_xor_sync(0xffffffffu, v, 2);
        lsum[hh] = 1.0f / v;
    }

    #pragma unroll
    for (int hh = 0; hh < 2; ++hh) {
        const int r = wr + g + 8 * hh;
        float* orow = g_scratch + ((size_t)(wb * NTOK + r)) * DIM + head * HDIM;
        const float inv = lsum[hh];
        #pragma unroll
        for (int n = 0; n < 4; ++n) {
            float2 v = make_float2(oacc[n][2 * hh] * inv, oacc[n][2 * hh + 1] * inv);
            *(float2*)(orow + 8 * n + 2 * t4) = v;
        }
    }
}

// ---------------- projection kernel (tensor cores, bf16-split, ldmatrix) ----------------
// 512 threads / 16 warps as 4(m) x 4(n). Double-buffered o staging via registers.
// ki loop fully unrolled -> ptxas software-pipelines LDSM/MMA.
#define PWROW 400                      // padded W/o row bytes (200 bf16)
#define OFF_PWH 0
#define OFF_PWL 76800
#define OFF_POH 153600
#define OFF_POL 179200
#define PROJ_SMEM 204800

__global__ void __launch_bounds__(512)
proj_kernel(const float* __restrict__ pw, const float* __restrict__ pb,
            float* __restrict__ out, int nchunks)
{
    extern __shared__ char smc[];
    const u32 smb = (u32)__cvta_generic_to_shared(smc);
    const int tid = threadIdx.x, lane = tid & 31, warp = tid >> 5;
    const int g = lane >> 2, t4 = lane & 3;
    const int wm = warp >> 2, wn = warp & 3;   // 4 x 4
    const int m0 = wm * 16, n0 = wn * 48;

    // ---- stage W split once ----
    for (int idx = tid; idx < DIM * 96; idx += 512) {
        const int c = idx / 96, kp = idx % 96;
        float2 v = *(const float2*)(pw + c * DIM + kp * 2);
        u32 hi, lo; split_pair(v.x, v.y, hi, lo);
        *(u32*)(smc + OFF_PWH + c * PWROW + kp * 4) = hi;
        *(u32*)(smc + OFF_PWL + c * PWROW + kp * 4) = lo;
    }
    float pbv[6][2];
    #pragma unroll
    for (int nt = 0; nt < 6; ++nt) {
        float2 v = *(const float2*)(pb + n0 + nt * 8 + 2 * t4);
        pbv[nt][0] = v.x; pbv[nt][1] = v.y;
    }

    const int l8 = lane & 7;
    const u32 arb = (u32)((m0 + l8 + ((lane >> 3) & 1) * 8) * PWROW + (lane >> 4) * 16);
    const u32 brb = (u32)((l8 + (lane >> 4) * 8) * PWROW + ((lane >> 3) & 1) * 16);

    const u32 whb = smb + OFF_PWH + brb, wlb = smb + OFF_PWL + brb;
    const u32 ohb = smb + OFF_POH + arb, olb = smb + OFF_POL + arb;

    // prefetch buffer for double-buffered staging
    float2 pre[12];
    int ci = blockIdx.x;
    if (ci < nchunks) {
        const float* src = g_scratch + (size_t)ci * (64 * DIM);
        #pragma unroll
        for (int it = 0; it < 12; ++it) {
            const int idx = tid + it * 512;
            const int tok = idx / 96, kp = idx % 96;
            pre[it] = *(const float2*)(src + tok * DIM + kp * 2);
        }
    }

    #pragma unroll 1
    for (; ci < nchunks; ci += gridDim.x) {
        __syncthreads();   // W staged (first) / previous chunk's LDSMs done
        #pragma unroll
        for (int it = 0; it < 12; ++it) {
            const int idx = tid + it * 512;
            const int tok = idx / 96, kp = idx % 96;
            u32 hi, lo; split_pair(pre[it].x, pre[it].y, hi, lo);
            *(u32*)(smc + OFF_POH + tok * PWROW + kp * 4) = hi;
            *(u32*)(smc + OFF_POL + tok * PWROW + kp * 4) = lo;
        }
        __syncthreads();

        // prefetch next chunk while this chunk computes
        const int cin = ci + gridDim.x;
        if (cin < nchunks) {
            const float* srcn = g_scratch + (size_t)cin * (64 * DIM);
            #pragma unroll
            for (int it = 0; it < 12; ++it) {
                const int idx = tid + it * 512;
                const int tok = idx / 96, kp = idx % 96;
                pre[it] = *(const float2*)(srcn + tok * DIM + kp * 2);
            }
        }

        float acc[6][4];
        #pragma unroll
        for (int nt = 0; nt < 6; ++nt)
            #pragma unroll
            for (int e = 0; e < 4; ++e) acc[nt][e] = 0.f;

        #pragma unroll
        for (int ki = 0; ki < 12; ++ki) {
            u32 ah[4], al[4];
            ldsm4v(ah[0], ah[1], ah[2], ah[3], ohb + ki * 32);
            ldsm4v(al[0], al[1], al[2], al[3], olb + ki * 32);
            #pragma unroll
            for (int p = 0; p < 3; ++p) {
                u32 bh[4], bl[4];
                const u32 bo = (u32)((n0 + 16 * p) * PWROW) + ki * 32;
                ldsm4(bh[0], bh[1], bh[2], bh[3], whb + bo);
                ldsm4(bl[0], bl[1], bl[2], bl[3], wlb + bo);
                float* c0 = acc[2 * p];
                float* c1 = acc[2 * p + 1];
                mma16816(c0[0], c0[1], c0[2], c0[3], ah[0], ah[1], ah[2], ah[3], bh[0], bh[1]);
                mma16816(c0[0], c0[1], c0[2], c0[3], ah[0], ah[1], ah[2], ah[3], bl[0], bl[1]);
                mma16816(c0[0], c0[1], c0[2], c0[3], al[0], al[1], al[2], al[3], bh[0], bh[1]);
                mma16816(c1[0], c1[1], c1[2], c1[3], ah[0], ah[1], ah[2], ah[3], bh[2], bh[3]);
                mma16816(c1[0], c1[1], c1[2], c1[3], ah[0], ah[1], ah[2], ah[3], bl[2], bl[3]);
                mma16816(c1[0], c1[1], c1[2], c1[3], al[0], al[1], al[2], al[3], bh[2], bh[3]);
            }
        }

        // ---- epilogue: bias + window-reverse scatter ----
        const int wbid = ci / 5, t = ci % 5;
        const int b = wbid >> 6, widx = wbid & 63;
        const int hw = widx >> 3, ww = widx & 7;
        #pragma unroll
        for (int hh = 0; hh < 2; ++hh) {
            const int s = m0 + g + 8 * hh;   // token 0..63
            const int hs = s >> 3, wsv = s & 7;
            const int h = (hw * 8 + hs + 4) & 63;
            const int w = (ww * 8 + wsv + 4) & 63;
            float* orow = out + ((size_t)((b * T_FRAMES + t) * 4096 + h * 64 + w)) * DIM;
            #pragma unroll
            for (int nt = 0; nt < 6; ++nt) {
                float2 v = make_float2(acc[nt][2 * hh]     + pbv[nt][0],
                                       acc[nt][2 * hh + 1] + pbv[nt][1]);
                *(float2*)(orow + n0 + nt * 8 + 2 * t4) = v;
            }
        }
    }
}

// ---------------- launch ----------------
extern "C" void kernel_launch(void* const* d_in, const int* in_sizes, int n_in,
                              void* d_out, int out_size)
{
    const float* qkv        = (const float*)d_in[0];
    const float* bias_table = (const float*)d_in[1];
    const float* pw         = (const float*)d_in[2];
    const float* pb         = (const float*)d_in[3];
    float* out = (float*)d_out;

    int B = in_sizes[0] / (T_FRAMES * 64 * 64 * 3 * DIM);
    if (B < 1) B = 1;
    if (B > 2) B = 2;   // scratch sized for B=2

    cudaFuncSetAttribute(attn_kernel, cudaFuncAttributeMaxDynamicSharedMemorySize, ATTN_SMEM);
    cudaFuncSetAttribute(proj_kernel, cudaFuncAttributeMaxDynamicSharedMemorySize, PROJ_SMEM);

    dim3 ag(B * 64, HEADS);
    attn_kernel<<<ag, 640, ATTN_SMEM>>>(qkv, bias_table);

    const int nchunks = B * 64 * T_FRAMES;
    int pgrid = nchunks < 148 ? nchunks : 148;
    proj_kernel<<<pgrid, 512, PROJ_SMEM>>>(pw, pb, out, nchunks);
}

// round 11
// speedup vs baseline: 3.6394x; 1.2074x over previous
#include <cuda_runtime.h>
#include <cuda_fp16.h>

typedef unsigned long long u64;
typedef unsigned int u32;

#define T_FRAMES 5
#define WS 8
#define HEADS 6
#define DIM 192
#define HDIM 32
#define NTOK 320

// scratch: per-window attention output, [wb][n][DIM], sized for B=2
__device__ float g_scratch[2 * 64 * NTOK * DIM];

// ---------------- small helpers ----------------
__device__ __forceinline__ float lds32f(u32 a) {
    float r; asm("ld.shared.b32 %0,[%1];" : "=f"(r) : "r"(a)); return r;
}
__device__ __forceinline__ void ldsm4(u32 &r0, u32 &r1, u32 &r2, u32 &r3, u32 a) {
    asm("ldmatrix.sync.aligned.m8n8.x4.shared.b16 {%0,%1,%2,%3},[%4];"
        : "=r"(r0), "=r"(r1), "=r"(r2), "=r"(r3) : "r"(a));
}
__device__ __forceinline__ void ldsm4v(u32 &r0, u32 &r1, u32 &r2, u32 &r3, u32 a) {
    asm volatile("ldmatrix.sync.aligned.m8n8.x4.shared.b16 {%0,%1,%2,%3},[%4];"
        : "=r"(r0), "=r"(r1), "=r"(r2), "=r"(r3) : "r"(a));
}
__device__ __forceinline__ void ldsm2(u32 &r0, u32 &r1, u32 a) {
    asm("ldmatrix.sync.aligned.m8n8.x2.shared.b16 {%0,%1},[%2];"
        : "=r"(r0), "=r"(r1) : "r"(a));
}
// fp16 mma m16n8k16, fp32 accumulate
__device__ __forceinline__ void mma16816(float &c0, float &c1, float &c2, float &c3,
                                         u32 a0, u32 a1, u32 a2, u32 a3,
                                         u32 b0, u32 b1) {
    asm("mma.sync.aligned.m16n8k16.row.col.f32.f16.f16.f32 "
        "{%0,%1,%2,%3},{%4,%5,%6,%7},{%8,%9},{%0,%1,%2,%3};"
        : "+f"(c0), "+f"(c1), "+f"(c2), "+f"(c3)
        : "r"(a0), "r"(a1), "r"(a2), "r"(a3), "r"(b0), "r"(b1));
}
// split f32 pair into f16x2 hi + f16x2 lo (residual)
__device__ __forceinline__ void split_pairh(float a, float b, u32 &h, u32 &l) {
    __half2 hv = __floats2half2_rn(a, b);
    h = *(u32*)&hv;
    float ra = a - __half2float(hv.x);
    float rb = b - __half2float(hv.y);
    __half2 lv = __floats2half2_rn(ra, rb);
    l = *(u32*)&lv;
}
__device__ __forceinline__ u32 packh2(float a, float b) {
    __half2 hv = __floats2half2_rn(a, b);
    return *(u32*)&hv;
}

// ---------------- attention kernel (fp16 2-term split, ldmatrix) ----------------
// 640 threads / 20 warps; warp owns 16 query rows.
// S = Qh·Kh + Ql·Kh ; PV = Ph·Vh + Pl·Vh  (K and V stored hi-only fp16)
#define ROWB 80
#define VTB  656
#define OFF_QH   0
#define OFF_QL   25600
#define OFF_KH   51200
#define OFF_VTH  76800
#define OFF_BIAS 97792
#define OFF_META 102532
#define ATTN_SMEM (103816)

__global__ void __launch_bounds__(640)
attn_kernel(const float* __restrict__ qkv, const float* __restrict__ bias_table)
{
    extern __shared__ char smc[];
    const u32 smb = (u32)__cvta_generic_to_shared(smc);
    int* meta_s = (int*)(smc + OFF_META);

    const int head = blockIdx.y;
    const int wb   = blockIdx.x;          // b*64 + widx
    const int b    = wb >> 6;
    const int widx = wb & 63;
    const int hw = widx >> 3, ww = widx & 7;

    const int tid  = threadIdx.x;         // 0..639
    const int lane = tid & 31;
    const int warp = tid >> 5;            // 0..19
    const int g    = lane >> 2;
    const int t4   = lane & 3;
    const int wr   = warp * 16;           // this warp's 16 query rows

    // staging: threads 0..319 handle Q+K of token tid; 320..639 handle V^T
    const bool qk_half = tid < 320;
    const int tok = qk_half ? tid : tid - 320;
    const int t   = tok >> 6;
    const int hs  = (tok >> 3) & 7;
    const int wsv = tok & 7;
    const int Hp = hw * 8 + hs;
    const int Wp = ww * 8 + wsv;
    const int h = (Hp + 4) & 63;
    const int w = (Wp + 4) & 63;
    const int rh = (Hp < 56) ? 0 : ((Hp < 60) ? 1 : 2);
    const int rw = (Wp < 56) ? 0 : ((Wp < 60) ? 1 : 2);
    if (qk_half)
        meta_s[tok] = (t * 15 + hs + wsv) | ((rh * 3 + rw) << 8);

    const int row = ((b * T_FRAMES + t) << 12) + (h << 6) + w;
    const float* qp = qkv + (size_t)row * (3 * DIM) + head * HDIM;

    const float LOG2E = 1.4426950408889634f;
    const float qs_f = 0.17677669529663687f * LOG2E;

    if (qk_half) {
        const float4* qv = (const float4*)qp;
        const float4* kv = (const float4*)(qp + DIM);
        #pragma unroll
        for (int m = 0; m < 8; ++m) {
            float4 f = qv[m];
            u32 h0, l0, h1, l1;
            split_pairh(f.x * qs_f, f.y * qs_f, h0, l0);
            split_pairh(f.z * qs_f, f.w * qs_f, h1, l1);
            const int off = tok * ROWB + m * 8;
            *(u32*)(smc + OFF_QH + off) = h0;  *(u32*)(smc + OFF_QH + off + 4) = h1;
            *(u32*)(smc + OFF_QL + off) = l0;  *(u32*)(smc + OFF_QL + off + 4) = l1;
        }
        #pragma unroll
        for (int m = 0; m < 8; ++m) {
            float4 f = kv[m];
            const int off = tok * ROWB + m * 8;
            *(u32*)(smc + OFF_KH + off)     = packh2(f.x, f.y);
            *(u32*)(smc + OFF_KH + off + 4) = packh2(f.z, f.w);
        }
    } else {
        const float4* vv = (const float4*)(qp + 2 * DIM);
        #pragma unroll
        for (int m = 0; m < 8; ++m) {
            float4 f = vv[m];
            float vals[4] = {f.x, f.y, f.z, f.w};
            #pragma unroll
            for (int e = 0; e < 4; ++e) {
                const int d = m * 4 + e;
                *(__half*)(smc + OFF_VTH + d * VTB + tok * 2) = __float2half_rn(vals[e]);
            }
        }
    }
    for (int idx = tid; idx < 1185; idx += 640)
        *(float*)(smc + OFF_BIAS + idx * 4) = bias_table[idx * HEADS + head] * LOG2E;

    __syncthreads();

    int ai[2], ri[2];
    #pragma unroll
    for (int hh = 0; hh < 2; ++hh) {
        int mv = meta_s[wr + g + 8 * hh];
        ai[hh] = (mv & 255) + 112;
        ri[hh] = mv >> 8;
    }

    // ldmatrix per-lane address components
    const int l8  = lane & 7;
    const u32 krb = (u32)(l8 * ROWB + (lane >> 3) * 16);
    const u32 vrb = (u32)(l8 * VTB + (lane >> 3) * 16);
    const u32 qrb = (u32)((wr + l8 + ((lane >> 3) & 1) * 8) * ROWB + (lane >> 4) * 16);

    // Q A-fragments: [hi/lo][kt][4]
    u32 qa[2][2][4];
    #pragma unroll
    for (int s = 0; s < 2; ++s) {
        const u32 base = smb + (s ? OFF_QL : OFF_QH) + qrb;
        #pragma unroll
        for (int kt = 0; kt < 2; ++kt)
            ldsm4(qa[s][kt][0], qa[s][kt][1], qa[s][kt][2], qa[s][kt][3], base + kt * 32);
    }

    const u32 khb = smb + OFF_KH + krb;
    const u32 vhb = smb + OFF_VTH + vrb;
    const u32 bib = smb + OFF_BIAS;

    float oacc[4][4];
    #pragma unroll
    for (int n = 0; n < 4; ++n)
        #pragma unroll
        for (int e = 0; e < 4; ++e) oacc[n][e] = 0.f;
    float lsum[2] = {0.f, 0.f};

    float sacc[4][4];

    // ---- S block: S = (Qh + Ql)·Kh ----
    auto s_block = [&](int jb2) {
        #pragma unroll
        for (int n = 0; n < 4; ++n)
            #pragma unroll
            for (int e = 0; e < 4; ++e) sacc[n][e] = 0.f;
        #pragma unroll
        for (int n = 0; n < 4; ++n) {
            u32 kh[4];
            ldsm4(kh[0], kh[1], kh[2], kh[3], khb + (jb2 + 8 * n) * ROWB);
            float* c = sacc[n];
            mma16816(c[0], c[1], c[2], c[3],
                     qa[0][0][0], qa[0][0][1], qa[0][0][2], qa[0][0][3], kh[0], kh[1]);
            mma16816(c[0], c[1], c[2], c[3],
                     qa[1][0][0], qa[1][0][1], qa[1][0][2], qa[1][0][3], kh[0], kh[1]);
            mma16816(c[0], c[1], c[2], c[3],
                     qa[0][1][0], qa[0][1][1], qa[0][1][2], qa[0][1][3], kh[2], kh[3]);
            mma16816(c[0], c[1], c[2], c[3],
                     qa[1][1][0], qa[1][1][1], qa[1][1][2], qa[1][1][3], kh[2], kh[3]);
        }
    };

    // ---- softmax for one 8-key group n of block jb2 ----
    auto sm_n = [&](int jb2, int n) {
        const int j0 = jb2 + 8 * n + 2 * t4;
        const int mj0 = meta_s[j0], mj1 = meta_s[j0 + 1];
        const int b0i = mj0 & 255, b1i = mj1 & 255;
        const int rj0 = mj0 >> 8,  rj1 = mj1 >> 8;
        float* c = sacc[n];
        float s0 = c[0] + lds32f(bib + (ai[0] - b0i) * 4);
        float s1 = c[1] + lds32f(bib + (ai[0] - b1i) * 4);
        float s2 = c[2] + lds32f(bib + (ai[1] - b0i) * 4);
        float s3 = c[3] + lds32f(bib + (ai[1] - b1i) * 4);
        float p0, p1, p2, p3;
        asm("ex2.approx.ftz.f32 %0,%1;" : "=f"(p0) : "f"(s0));
        asm("ex2.approx.ftz.f32 %0,%1;" : "=f"(p1) : "f"(s1));
        asm("ex2.approx.ftz.f32 %0,%1;" : "=f"(p2) : "f"(s2));
        asm("ex2.approx.ftz.f32 %0,%1;" : "=f"(p3) : "f"(s3));
        p0 = (ri[0] == rj0) ? p0 : 0.f;
        p1 = (ri[0] == rj1) ? p1 : 0.f;
        p2 = (ri[1] == rj0) ? p2 : 0.f;
        p3 = (ri[1] == rj1) ? p3 : 0.f;
        c[0] = p0; c[1] = p1; c[2] = p2; c[3] = p3;
        lsum[0] += p0 + p1;
        lsum[1] += p2 + p3;
    };

    // ---- split P fragments (fp16 hi + residual lo) for one kt half ----
    auto split_kt = [&](int kt, u32* ph, u32* pl) {
        const float* cA = sacc[2 * kt];
        const float* cB = sacc[2 * kt + 1];
        const float px[8] = {cA[0], cA[1], cA[2], cA[3], cB[0], cB[1], cB[2], cB[3]};
        #pragma unroll
        for (int e = 0; e < 4; ++e)
            split_pairh(px[2 * e], px[2 * e + 1], ph[e], pl[e]);
    };

    // ---- PV for one kt half: O += (Ph + Pl)·Vh ----
    auto pv_kt = [&](int jb2, int kt, const u32* ph, const u32* pl) {
        #pragma unroll
        for (int n = 0; n < 4; ++n) {
            u32 vh0, vh1;
            const u32 off = (8 * n) * VTB + jb2 * 2 + kt * 32;
            ldsm2(vh0, vh1, vhb + off);
            float* c = oacc[n];
            mma16816(c[0], c[1], c[2], c[3], ph[0], ph[1], ph[2], ph[3], vh0, vh1);
            mma16816(c[0], c[1], c[2], c[3], pl[0], pl[1], pl[2], pl[3], vh0, vh1);
        }
    };

    // ---- software-pipelined mainloop, half-jc interleave ----
    s_block(0);
    #pragma unroll 1
    for (int jc = 0; jc < 9; ++jc) {
        const int jb = jc * 32;
        sm_n(jb, 0);
        sm_n(jb, 1);
        u32 ph0[4], pl0[4];
        split_kt(0, ph0, pl0);
        pv_kt(jb, 0, ph0, pl0);
        sm_n(jb, 2);
        sm_n(jb, 3);
        u32 ph1[4], pl1[4];
        split_kt(1, ph1, pl1);
        s_block(jb + 32);
        pv_kt(jb, 1, ph1, pl1);
    }
    {
        const int jb = 288;
        sm_n(jb, 0); sm_n(jb, 1);
        u32 ph0[4], pl0[4];
        split_kt(0, ph0, pl0);
        pv_kt(jb, 0, ph0, pl0);
        sm_n(jb, 2); sm_n(jb, 3);
        u32 ph1[4], pl1[4];
        split_kt(1, ph1, pl1);
        pv_kt(jb, 1, ph1, pl1);
    }

    #pragma unroll
    for (int hh = 0; hh < 2; ++hh) {
        float v = lsum[hh];
        v += __shfl_xor_sync(0xffffffffu, v, 1);
        v += __shfl_xor_sync(0xffffffffu, v, 2);
        lsum[hh] = 1.0f / v;
    }

    #pragma unroll
    for (int hh = 0; hh < 2; ++hh) {
        const int r = wr + g + 8 * hh;
        float* orow = g_scratch + ((size_t)(wb * NTOK + r)) * DIM + head * HDIM;
        const float inv = lsum[hh];
        #pragma unroll
        for (int n = 0; n < 4; ++n) {
            float2 v = make_float2(oacc[n][2 * hh] * inv, oacc[n][2 * hh + 1] * inv);
            *(float2*)(orow + 8 * n + 2 * t4) = v;
        }
    }
}

// ---------------- projection kernel (fp16 2-term split, ldmatrix) ----------------
// 512 threads / 16 warps as 4(m) x 4(n). out = (Oh + Ol)·Wh. W stored hi-only.
#define PWROW 400                      // padded W/o row bytes (200 fp16)
#define OFF_PWH 0
#define OFF_POH 76800
#define OFF_POL 102400
#define PROJ_SMEM 128000

__global__ void __launch_bounds__(512)
proj_kernel(const float* __restrict__ pw, const float* __restrict__ pb,
            float* __restrict__ out, int nchunks)
{
    extern __shared__ char smc[];
    const u32 smb = (u32)__cvta_generic_to_shared(smc);
    const int tid = threadIdx.x, lane = tid & 31, warp = tid >> 5;
    const int g = lane >> 2, t4 = lane & 3;
    const int wm = warp >> 2, wn = warp & 3;   // 4 x 4
    const int m0 = wm * 16, n0 = wn * 48;

    // ---- stage W (fp16 hi only) once ----
    for (int idx = tid; idx < DIM * 96; idx += 512) {
        const int c = idx / 96, kp = idx % 96;
        float2 v = *(const float2*)(pw + c * DIM + kp * 2);
        *(u32*)(smc + OFF_PWH + c * PWROW + kp * 4) = packh2(v.x, v.y);
    }
    float pbv[6][2];
    #pragma unroll
    for (int nt = 0; nt < 6; ++nt) {
        float2 v = *(const float2*)(pb + n0 + nt * 8 + 2 * t4);
        pbv[nt][0] = v.x; pbv[nt][1] = v.y;
    }

    const int l8 = lane & 7;
    const u32 arb = (u32)((m0 + l8 + ((lane >> 3) & 1) * 8) * PWROW + (lane >> 4) * 16);
    const u32 brb = (u32)((l8 + (lane >> 4) * 8) * PWROW + ((lane >> 3) & 1) * 16);

    const u32 whb = smb + OFF_PWH + brb;
    const u32 ohb = smb + OFF_POH + arb, olb = smb + OFF_POL + arb;

    // prefetch buffer for double-buffered staging
    float2 pre[12];
    int ci = blockIdx.x;
    if (ci < nchunks) {
        const float* src = g_scratch + (size_t)ci * (64 * DIM);
        #pragma unroll
        for (int it = 0; it < 12; ++it) {
            const int idx = tid + it * 512;
            const int tok = idx / 96, kp = idx % 96;
            pre[it] = *(const float2*)(src + tok * DIM + kp * 2);
        }
    }

    #pragma unroll 1
    for (; ci < nchunks; ci += gridDim.x) {
        __syncthreads();   // W staged (first) / previous chunk's LDSMs done
        #pragma unroll
        for (int it = 0; it < 12; ++it) {
            const int idx = tid + it * 512;
            const int tok = idx / 96, kp = idx % 96;
            u32 hi, lo; split_pairh(pre[it].x, pre[it].y, hi, lo);
            *(u32*)(smc + OFF_POH + tok * PWROW + kp * 4) = hi;
            *(u32*)(smc + OFF_POL + tok * PWROW + kp * 4) = lo;
        }
        __syncthreads();

        // prefetch next chunk while this chunk computes
        const int cin = ci + gridDim.x;
        if (cin < nchunks) {
            const float* srcn = g_scratch + (size_t)cin * (64 * DIM);
            #pragma unroll
            for (int it = 0; it < 12; ++it) {
                const int idx = tid + it * 512;
                const int tok = idx / 96, kp = idx % 96;
                pre[it] = *(const float2*)(srcn + tok * DIM + kp * 2);
            }
        }

        float acc[6][4];
        #pragma unroll
        for (int nt = 0; nt < 6; ++nt)
            #pragma unroll
            for (int e = 0; e < 4; ++e) acc[nt][e] = 0.f;

        #pragma unroll
        for (int ki = 0; ki < 12; ++ki) {
            u32 ah[4], al[4];
            ldsm4v(ah[0], ah[1], ah[2], ah[3], ohb + ki * 32);
            ldsm4v(al[0], al[1], al[2], al[3], olb + ki * 32);
            #pragma unroll
            for (int p = 0; p < 3; ++p) {
                u32 bh[4];
                const u32 bo = (u32)((n0 + 16 * p) * PWROW) + ki * 32;
                ldsm4(bh[0], bh[1], bh[2], bh[3], whb + bo);
                float* c0 = acc[2 * p];
                float* c1 = acc[2 * p + 1];
                mma16816(c0[0], c0[1], c0[2], c0[3], ah[0], ah[1], ah[2], ah[3], bh[0], bh[1]);
                mma16816(c0[0], c0[1], c0[2], c0[3], al[0], al[1], al[2], al[3], bh[0], bh[1]);
                mma16816(c1[0], c1[1], c1[2], c1[3], ah[0], ah[1], ah[2], ah[3], bh[2], bh[3]);
                mma16816(c1[0], c1[1], c1[2], c1[3], al[0], al[1], al[2], al[3], bh[2], bh[3]);
            }
        }

        // ---- epilogue: bias + window-reverse scatter ----
        const int wbid = ci / 5, t = ci % 5;
        const int b = wbid >> 6, widx = wbid & 63;
        const int hw = widx >> 3, ww = widx & 7;
        #pragma unroll
        for (int hh = 0; hh < 2; ++hh) {
            const int s = m0 + g + 8 * hh;   // token 0..63
            const int hs = s >> 3, wsv = s & 7;
            const int h = (hw * 8 + hs + 4) & 63;
            const int w = (ww * 8 + wsv + 4) & 63;
            float* orow = out + ((size_t)((b * T_FRAMES + t) * 4096 + h * 64 + w)) * DIM;
            #pragma unroll
            for (int nt = 0; nt < 6; ++nt) {
                float2 v = make_float2(acc[nt][2 * hh]     + pbv[nt][0],
                                       acc[nt][2 * hh + 1] + pbv[nt][1]);
                *(float2*)(orow + n0 + nt * 8 + 2 * t4) = v;
            }
        }
    }
}

// ---------------- launch ----------------
extern "C" void kernel_launch(void* const* d_in, const int* in_sizes, int n_in,
                              void* d_out, int out_size)
{
    const float* qkv        = (const float*)d_in[0];
    const float* bias_table = (const float*)d_in[1];
    const float* pw         = (const float*)d_in[2];
    const float* pb         = (const float*)d_in[3];
    float* out = (float*)d_out;

    int B = in_sizes[0] / (T_FRAMES * 64 * 64 * 3 * DIM);
    if (B < 1) B = 1;
    if (B > 2) B = 2;   // scratch sized for B=2

    cudaFuncSetAttribute(attn_kernel, cudaFuncAttributeMaxDynamicSharedMemorySize, ATTN_SMEM);
    cudaFuncSetAttribute(proj_kernel, cudaFuncAttributeMaxDynamicSharedMemorySize, PROJ_SMEM);

    dim3 ag(B * 64, HEADS);
    attn_kernel<<<ag, 640, ATTN_SMEM>>>(qkv, bias_table);

    const int nchunks = B * 64 * T_FRAMES;
    int pgrid = nchunks < 148 ? nchunks : 148;
    proj_kernel<<<pgrid, 512, PROJ_SMEM>>>(pw, pb, out, nchunks);
}

// round 12
// speedup vs baseline: 4.3553x; 1.1967x over previous
#include <cuda_runtime.h>
#include <cuda_fp16.h>

typedef unsigned long long u64;
typedef unsigned int u32;

#define T_FRAMES 5
#define WS 8
#define HEADS 6
#define DIM 192
#define HDIM 32
#define NTOK 320

// scratch: per-window attention output, [wb][n][DIM], sized for B=2
__device__ float g_scratch[2 * 64 * NTOK * DIM];

// ---------------- small helpers ----------------
__device__ __forceinline__ float lds32f(u32 a) {
    float r; asm("ld.shared.b32 %0,[%1];" : "=f"(r) : "r"(a)); return r;
}
__device__ __forceinline__ void ldsm4(u32 &r0, u32 &r1, u32 &r2, u32 &r3, u32 a) {
    asm("ldmatrix.sync.aligned.m8n8.x4.shared.b16 {%0,%1,%2,%3},[%4];"
        : "=r"(r0), "=r"(r1), "=r"(r2), "=r"(r3) : "r"(a));
}
__device__ __forceinline__ void ldsm4v(u32 &r0, u32 &r1, u32 &r2, u32 &r3, u32 a) {
    asm volatile("ldmatrix.sync.aligned.m8n8.x4.shared.b16 {%0,%1,%2,%3},[%4];"
        : "=r"(r0), "=r"(r1), "=r"(r2), "=r"(r3) : "r"(a));
}
__device__ __forceinline__ void ldsm2(u32 &r0, u32 &r1, u32 a) {
    asm("ldmatrix.sync.aligned.m8n8.x2.shared.b16 {%0,%1},[%2];"
        : "=r"(r0), "=r"(r1) : "r"(a));
}
// fp16 mma m16n8k16, fp32 accumulate
__device__ __forceinline__ void mma16816(float &c0, float &c1, float &c2, float &c3,
                                         u32 a0, u32 a1, u32 a2, u32 a3,
                                         u32 b0, u32 b1) {
    asm("mma.sync.aligned.m16n8k16.row.col.f32.f16.f16.f32 "
        "{%0,%1,%2,%3},{%4,%5,%6,%7},{%8,%9},{%0,%1,%2,%3};"
        : "+f"(c0), "+f"(c1), "+f"(c2), "+f"(c3)
        : "r"(a0), "r"(a1), "r"(a2), "r"(a3), "r"(b0), "r"(b1));
}
// split f32 pair into f16x2 hi + f16x2 lo (residual)
__device__ __forceinline__ void split_pairh(float a, float b, u32 &h, u32 &l) {
    __half2 hv = __floats2half2_rn(a, b);
    h = *(u32*)&hv;
    float ra = a - __half2float(hv.x);
    float rb = b - __half2float(hv.y);
    __half2 lv = __floats2half2_rn(ra, rb);
    l = *(u32*)&lv;
}
__device__ __forceinline__ u32 packh2(float a, float b) {
    __half2 hv = __floats2half2_rn(a, b);
    return *(u32*)&hv;
}

// ---------------- attention kernel (fp16 hi-only, ldmatrix) ----------------
// 640 threads / 20 warps; warp owns 16 query rows.
// S = Qh·Kh ; PV = Ph·Vh   (all operands fp16 hi; fp32 accum)
#define ROWB 80
#define VTB  656
#define OFF_QH   0
#define OFF_KH   25600
#define OFF_VTH  51200
#define OFF_BIAS 72192
#define OFF_META 76932
#define ATTN_SMEM (78212)

__global__ void __launch_bounds__(640)
attn_kernel(const float* __restrict__ qkv, const float* __restrict__ bias_table)
{
    extern __shared__ char smc[];
    const u32 smb = (u32)__cvta_generic_to_shared(smc);
    int* meta_s = (int*)(smc + OFF_META);

    const int head = blockIdx.y;
    const int wb   = blockIdx.x;          // b*64 + widx
    const int b    = wb >> 6;
    const int widx = wb & 63;
    const int hw = widx >> 3, ww = widx & 7;

    const int tid  = threadIdx.x;         // 0..639
    const int lane = tid & 31;
    const int warp = tid >> 5;            // 0..19
    const int g    = lane >> 2;
    const int t4   = lane & 3;
    const int wr   = warp * 16;           // this warp's 16 query rows

    // staging: threads 0..319 handle Q+K of token tid; 320..639 handle V^T
    const bool qk_half = tid < 320;
    const int tok = qk_half ? tid : tid - 320;
    const int t   = tok >> 6;
    const int hs  = (tok >> 3) & 7;
    const int wsv = tok & 7;
    const int Hp = hw * 8 + hs;
    const int Wp = ww * 8 + wsv;
    const int h = (Hp + 4) & 63;
    const int w = (Wp + 4) & 63;
    const int rh = (Hp < 56) ? 0 : ((Hp < 60) ? 1 : 2);
    const int rw = (Wp < 56) ? 0 : ((Wp < 60) ? 1 : 2);
    if (qk_half)
        meta_s[tok] = (t * 15 + hs + wsv) | ((rh * 3 + rw) << 8);

    const int row = ((b * T_FRAMES + t) << 12) + (h << 6) + w;
    const float* qp = qkv + (size_t)row * (3 * DIM) + head * HDIM;

    const float LOG2E = 1.4426950408889634f;
    const float qs_f = 0.17677669529663687f * LOG2E;

    if (qk_half) {
        const float4* qv = (const float4*)qp;
        const float4* kv = (const float4*)(qp + DIM);
        #pragma unroll
        for (int m = 0; m < 8; ++m) {
            float4 f = qv[m];
            const int off = tok * ROWB + m * 8;
            *(u32*)(smc + OFF_QH + off)     = packh2(f.x * qs_f, f.y * qs_f);
            *(u32*)(smc + OFF_QH + off + 4) = packh2(f.z * qs_f, f.w * qs_f);
        }
        #pragma unroll
        for (int m = 0; m < 8; ++m) {
            float4 f = kv[m];
            const int off = tok * ROWB + m * 8;
            *(u32*)(smc + OFF_KH + off)     = packh2(f.x, f.y);
            *(u32*)(smc + OFF_KH + off + 4) = packh2(f.z, f.w);
        }
    } else {
        const float4* vv = (const float4*)(qp + 2 * DIM);
        #pragma unroll
        for (int m = 0; m < 8; ++m) {
            float4 f = vv[m];
            float vals[4] = {f.x, f.y, f.z, f.w};
            #pragma unroll
            for (int e = 0; e < 4; ++e) {
                const int d = m * 4 + e;
                *(__half*)(smc + OFF_VTH + d * VTB + tok * 2) = __float2half_rn(vals[e]);
            }
        }
    }
    for (int idx = tid; idx < 1185; idx += 640)
        *(float*)(smc + OFF_BIAS + idx * 4) = bias_table[idx * HEADS + head] * LOG2E;

    __syncthreads();

    int ai[2], ri[2];
    #pragma unroll
    for (int hh = 0; hh < 2; ++hh) {
        int mv = meta_s[wr + g + 8 * hh];
        ai[hh] = (mv & 255) + 112;
        ri[hh] = mv >> 8;
    }

    // ldmatrix per-lane address components
    const int l8  = lane & 7;
    const u32 krb = (u32)(l8 * ROWB + (lane >> 3) * 16);
    const u32 vrb = (u32)(l8 * VTB + (lane >> 3) * 16);
    const u32 qrb = (u32)((wr + l8 + ((lane >> 3) & 1) * 8) * ROWB + (lane >> 4) * 16);

    // Q A-fragments: [kt][4]
    u32 qa[2][4];
    #pragma unroll
    for (int kt = 0; kt < 2; ++kt)
        ldsm4(qa[kt][0], qa[kt][1], qa[kt][2], qa[kt][3],
              smb + OFF_QH + qrb + kt * 32);

    const u32 khb = smb + OFF_KH + krb;
    const u32 vhb = smb + OFF_VTH + vrb;
    const u32 bib = smb + OFF_BIAS;

    float oacc[4][4];
    #pragma unroll
    for (int n = 0; n < 4; ++n)
        #pragma unroll
        for (int e = 0; e < 4; ++e) oacc[n][e] = 0.f;
    float lsum[2] = {0.f, 0.f};

    float sacc[4][4];

    // ---- S block: S = Qh·Kh ----
    auto s_block = [&](int jb2) {
        #pragma unroll
        for (int n = 0; n < 4; ++n)
            #pragma unroll
            for (int e = 0; e < 4; ++e) sacc[n][e] = 0.f;
        #pragma unroll
        for (int n = 0; n < 4; ++n) {
            u32 kh[4];
            ldsm4(kh[0], kh[1], kh[2], kh[3], khb + (jb2 + 8 * n) * ROWB);
            float* c = sacc[n];
            mma16816(c[0], c[1], c[2], c[3],
                     qa[0][0], qa[0][1], qa[0][2], qa[0][3], kh[0], kh[1]);
            mma16816(c[0], c[1], c[2], c[3],
                     qa[1][0], qa[1][1], qa[1][2], qa[1][3], kh[2], kh[3]);
        }
    };

    // ---- softmax for one 8-key group n of block jb2 ----
    auto sm_n = [&](int jb2, int n) {
        const int j0 = jb2 + 8 * n + 2 * t4;
        const int mj0 = meta_s[j0], mj1 = meta_s[j0 + 1];
        const int b0i = mj0 & 255, b1i = mj1 & 255;
        const int rj0 = mj0 >> 8,  rj1 = mj1 >> 8;
        float* c = sacc[n];
        float s0 = c[0] + lds32f(bib + (ai[0] - b0i) * 4);
        float s1 = c[1] + lds32f(bib + (ai[0] - b1i) * 4);
        float s2 = c[2] + lds32f(bib + (ai[1] - b0i) * 4);
        float s3 = c[3] + lds32f(bib + (ai[1] - b1i) * 4);
        float p0, p1, p2, p3;
        asm("ex2.approx.ftz.f32 %0,%1;" : "=f"(p0) : "f"(s0));
        asm("ex2.approx.ftz.f32 %0,%1;" : "=f"(p1) : "f"(s1));
        asm("ex2.approx.ftz.f32 %0,%1;" : "=f"(p2) : "f"(s2));
        asm("ex2.approx.ftz.f32 %0,%1;" : "=f"(p3) : "f"(s3));
        p0 = (ri[0] == rj0) ? p0 : 0.f;
        p1 = (ri[0] == rj1) ? p1 : 0.f;
        p2 = (ri[1] == rj0) ? p2 : 0.f;
        p3 = (ri[1] == rj1) ? p3 : 0.f;
        c[0] = p0; c[1] = p1; c[2] = p2; c[3] = p3;
        lsum[0] += p0 + p1;
        lsum[1] += p2 + p3;
    };

    // ---- pack P fragments (fp16 hi only) for one kt half ----
    auto pack_kt = [&](int kt, u32* ph) {
        const float* cA = sacc[2 * kt];
        const float* cB = sacc[2 * kt + 1];
        ph[0] = packh2(cA[0], cA[1]);
        ph[1] = packh2(cA[2], cA[3]);
        ph[2] = packh2(cB[0], cB[1]);
        ph[3] = packh2(cB[2], cB[3]);
    };

    // ---- PV for one kt half: O += Ph·Vh ----
    auto pv_kt = [&](int jb2, int kt, const u32* ph) {
        #pragma unroll
        for (int n = 0; n < 4; ++n) {
            u32 vh0, vh1;
            ldsm2(vh0, vh1, vhb + (8 * n) * VTB + jb2 * 2 + kt * 32);
            float* c = oacc[n];
            mma16816(c[0], c[1], c[2], c[3], ph[0], ph[1], ph[2], ph[3], vh0, vh1);
        }
    };

    // ---- software-pipelined mainloop, half-jc interleave ----
    s_block(0);
    #pragma unroll 1
    for (int jc = 0; jc < 9; ++jc) {
        const int jb = jc * 32;
        sm_n(jb, 0);
        sm_n(jb, 1);
        u32 ph0[4];
        pack_kt(0, ph0);
        pv_kt(jb, 0, ph0);
        sm_n(jb, 2);
        sm_n(jb, 3);
        u32 ph1[4];
        pack_kt(1, ph1);
        s_block(jb + 32);
        pv_kt(jb, 1, ph1);
    }
    {
        const int jb = 288;
        sm_n(jb, 0); sm_n(jb, 1);
        u32 ph0[4];
        pack_kt(0, ph0);
        pv_kt(jb, 0, ph0);
        sm_n(jb, 2); sm_n(jb, 3);
        u32 ph1[4];
        pack_kt(1, ph1);
        pv_kt(jb, 1, ph1);
    }

    #pragma unroll
    for (int hh = 0; hh < 2; ++hh) {
        float v = lsum[hh];
        v += __shfl_xor_sync(0xffffffffu, v, 1);
        v += __shfl_xor_sync(0xffffffffu, v, 2);
        lsum[hh] = 1.0f / v;
    }

    #pragma unroll
    for (int hh = 0; hh < 2; ++hh) {
        const int r = wr + g + 8 * hh;
        float* orow = g_scratch + ((size_t)(wb * NTOK + r)) * DIM + head * HDIM;
        const float inv = lsum[hh];
        #pragma unroll
        for (int n = 0; n < 4; ++n) {
            float2 v = make_float2(oacc[n][2 * hh] * inv, oacc[n][2 * hh + 1] * inv);
            *(float2*)(orow + 8 * n + 2 * t4) = v;
        }
    }
}

// ---------------- projection kernel (fp16 2-term split, ldmatrix) ----------------
// 512 threads / 16 warps as 4(m) x 4(n). out = (Oh + Ol)·Wh. W stored hi-only.
#define PWROW 400                      // padded W/o row bytes (200 fp16)
#define OFF_PWH 0
#define OFF_POH 76800
#define OFF_POL 102400
#define PROJ_SMEM 128000

__global__ void __launch_bounds__(512)
proj_kernel(const float* __restrict__ pw, const float* __restrict__ pb,
            float* __restrict__ out, int nchunks)
{
    extern __shared__ char smc[];
    const u32 smb = (u32)__cvta_generic_to_shared(smc);
    const int tid = threadIdx.x, lane = tid & 31, warp = tid >> 5;
    const int g = lane >> 2, t4 = lane & 3;
    const int wm = warp >> 2, wn = warp & 3;   // 4 x 4
    const int m0 = wm * 16, n0 = wn * 48;

    // ---- stage W (fp16 hi only) once ----
    for (int idx = tid; idx < DIM * 96; idx += 512) {
        const int c = idx / 96, kp = idx % 96;
        float2 v = *(const float2*)(pw + c * DIM + kp * 2);
        *(u32*)(smc + OFF_PWH + c * PWROW + kp * 4) = packh2(v.x, v.y);
    }
    float pbv[6][2];
    #pragma unroll
    for (int nt = 0; nt < 6; ++nt) {
        float2 v = *(const float2*)(pb + n0 + nt * 8 + 2 * t4);
        pbv[nt][0] = v.x; pbv[nt][1] = v.y;
    }

    const int l8 = lane & 7;
    const u32 arb = (u32)((m0 + l8 + ((lane >> 3) & 1) * 8) * PWROW + (lane >> 4) * 16);
    const u32 brb = (u32)((l8 + (lane >> 4) * 8) * PWROW + ((lane >> 3) & 1) * 16);

    const u32 whb = smb + OFF_PWH + brb;
    const u32 ohb = smb + OFF_POH + arb, olb = smb + OFF_POL + arb;

    // prefetch buffer for double-buffered staging
    float2 pre[12];
    int ci = blockIdx.x;
    if (ci < nchunks) {
        const float* src = g_scratch + (size_t)ci * (64 * DIM);
        #pragma unroll
        for (int it = 0; it < 12; ++it) {
            const int idx = tid + it * 512;
            const int tok = idx / 96, kp = idx % 96;
            pre[it] = *(const float2*)(src + tok * DIM + kp * 2);
        }
    }

    #pragma unroll 1
    for (; ci < nchunks; ci += gridDim.x) {
        __syncthreads();   // W staged (first) / previous chunk's LDSMs done
        #pragma unroll
        for (int it = 0; it < 12; ++it) {
            const int idx = tid + it * 512;
            const int tok = idx / 96, kp = idx % 96;
            u32 hi, lo; split_pairh(pre[it].x, pre[it].y, hi, lo);
            *(u32*)(smc + OFF_POH + tok * PWROW + kp * 4) = hi;
            *(u32*)(smc + OFF_POL + tok * PWROW + kp * 4) = lo;
        }
        __syncthreads();

        // prefetch next chunk while this chunk computes
        const int cin = ci + gridDim.x;
        if (cin < nchunks) {
            const float* srcn = g_scratch + (size_t)cin * (64 * DIM);
            #pragma unroll
            for (int it = 0; it < 12; ++it) {
                const int idx = tid + it * 512;
                const int tok = idx / 96, kp = idx % 96;
                pre[it] = *(const float2*)(srcn + tok * DIM + kp * 2);
            }
        }

        float acc[6][4];
        #pragma unroll
        for (int nt = 0; nt < 6; ++nt)
            #pragma unroll
            for (int e = 0; e < 4; ++e) acc[nt][e] = 0.f;

        #pragma unroll
        for (int ki = 0; ki < 12; ++ki) {
            u32 ah[4], al[4];
            ldsm4v(ah[0], ah[1], ah[2], ah[3], ohb + ki * 32);
            ldsm4v(al[0], al[1], al[2], al[3], olb + ki * 32);
            #pragma unroll
            for (int p = 0; p < 3; ++p) {
                u32 bh[4];
                const u32 bo = (u32)((n0 + 16 * p) * PWROW) + ki * 32;
                ldsm4(bh[0], bh[1], bh[2], bh[3], whb + bo);
                float* c0 = acc[2 * p];
                float* c1 = acc[2 * p + 1];
                mma16816(c0[0], c0[1], c0[2], c0[3], ah[0], ah[1], ah[2], ah[3], bh[0], bh[1]);
                mma16816(c0[0], c0[1], c0[2], c0[3], al[0], al[1], al[2], al[3], bh[0], bh[1]);
                mma16816(c1[0], c1[1], c1[2], c1[3], ah[0], ah[1], ah[2], ah[3], bh[2], bh[3]);
                mma16816(c1[0], c1[1], c1[2], c1[3], al[0], al[1], al[2], al[3], bh[2], bh[3]);
            }
        }

        // ---- epilogue: bias + window-reverse scatter ----
        const int wbid = ci / 5, t = ci % 5;
        const int b = wbid >> 6, widx = wbid & 63;
        const int hw = widx >> 3, ww = widx & 7;
        #pragma unroll
        for (int hh = 0; hh < 2; ++hh) {
            const int s = m0 + g + 8 * hh;   // token 0..63
            const int hs = s >> 3, wsv = s & 7;
            const int h = (hw * 8 + hs + 4) & 63;
            const int w = (ww * 8 + wsv + 4) & 63;
            float* orow = out + ((size_t)((b * T_FRAMES + t) * 4096 + h * 64 + w)) * DIM;
            #pragma unroll
            for (int nt = 0; nt < 6; ++nt) {
                float2 v = make_float2(acc[nt][2 * hh]     + pbv[nt][0],
                                       acc[nt][2 * hh + 1] + pbv[nt][1]);
                *(float2*)(orow + n0 + nt * 8 + 2 * t4) = v;
            }
        }
    }
}

// ---------------- launch ----------------
extern "C" void kernel_launch(void* const* d_in, const int* in_sizes, int n_in,
                              void* d_out, int out_size)
{
    const float* qkv        = (const float*)d_in[0];
    const float* bias_table = (const float*)d_in[1];
    const float* pw         = (const float*)d_in[2];
    const float* pb         = (const float*)d_in[3];
    float* out = (float*)d_out;

    int B = in_sizes[0] / (T_FRAMES * 64 * 64 * 3 * DIM);
    if (B < 1) B = 1;
    if (B > 2) B = 2;   // scratch sized for B=2

    cudaFuncSetAttribute(attn_kernel, cudaFuncAttributeMaxDynamicSharedMemorySize, ATTN_SMEM);
    cudaFuncSetAttribute(proj_kernel, cudaFuncAttributeMaxDynamicSharedMemorySize, PROJ_SMEM);

    dim3 ag(B * 64, HEADS);
    attn_kernel<<<ag, 640, ATTN_SMEM>>>(qkv, bias_table);

    const int nchunks = B * 64 * T_FRAMES;
    int pgrid = nchunks < 148 ? nchunks : 148;
    proj_kernel<<<pgrid, 512, PROJ_SMEM>>>(pw, pb, out, nchunks);
}

// round 13
// speedup vs baseline: 4.4970x; 1.0325x over previous
#include <cuda_runtime.h>
#include <cuda_fp16.h>

typedef unsigned long long u64;
typedef unsigned int u32;

#define T_FRAMES 5
#define WS 8
#define HEADS 6
#define DIM 192
#define HDIM 32
#define NTOK 320

// scratch: per-window attention output, [wb][n][DIM], sized for B=2
__device__ float g_scratch[2 * 64 * NTOK * DIM];

// ---------------- small helpers ----------------
__device__ __forceinline__ float lds32f(u32 a) {
    float r; asm("ld.shared.b32 %0,[%1];" : "=f"(r) : "r"(a)); return r;
}
__device__ __forceinline__ void ldsm4(u32 &r0, u32 &r1, u32 &r2, u32 &r3, u32 a) {
    asm("ldmatrix.sync.aligned.m8n8.x4.shared.b16 {%0,%1,%2,%3},[%4];"
        : "=r"(r0), "=r"(r1), "=r"(r2), "=r"(r3) : "r"(a));
}
__device__ __forceinline__ void ldsm4v(u32 &r0, u32 &r1, u32 &r2, u32 &r3, u32 a) {
    asm volatile("ldmatrix.sync.aligned.m8n8.x4.shared.b16 {%0,%1,%2,%3},[%4];"
        : "=r"(r0), "=r"(r1), "=r"(r2), "=r"(r3) : "r"(a));
}
__device__ __forceinline__ void ldsm2(u32 &r0, u32 &r1, u32 a) {
    asm("ldmatrix.sync.aligned.m8n8.x2.shared.b16 {%0,%1},[%2];"
        : "=r"(r0), "=r"(r1) : "r"(a));
}
// fp16 mma m16n8k16, fp32 accumulate
__device__ __forceinline__ void mma16816(float &c0, float &c1, float &c2, float &c3,
                                         u32 a0, u32 a1, u32 a2, u32 a3,
                                         u32 b0, u32 b1) {
    asm("mma.sync.aligned.m16n8k16.row.col.f32.f16.f16.f32 "
        "{%0,%1,%2,%3},{%4,%5,%6,%7},{%8,%9},{%0,%1,%2,%3};"
        : "+f"(c0), "+f"(c1), "+f"(c2), "+f"(c3)
        : "r"(a0), "r"(a1), "r"(a2), "r"(a3), "r"(b0), "r"(b1));
}
__device__ __forceinline__ u32 packh2(float a, float b) {
    __half2 hv = __floats2half2_rn(a, b);
    return *(u32*)&hv;
}
// packed fp16 exp2
__device__ __forceinline__ u32 h2exp2(u32 s) {
    u32 r; asm("ex2.approx.f16x2 %0,%1;" : "=r"(r) : "r"(s)); return r;
}
__device__ __forceinline__ u32 hadd2(u32 a, u32 b) {
    u32 r; asm("add.rn.f16x2 %0,%1,%2;" : "=r"(r) : "r"(a), "r"(b)); return r;
}

// ---------------- attention kernel (fp16 hi-only, fused f16x2 softmax) ----------------
// 640 threads / 20 warps; warp owns 16 query rows.
#define ROWB 80
#define VTB  656
#define OFF_QH   0
#define OFF_KH   25600
#define OFF_VTH  51200
#define OFF_BIAS 72192
#define OFF_META 76932
#define ATTN_SMEM (78212)

__global__ void __launch_bounds__(640)
attn_kernel(const float* __restrict__ qkv, const float* __restrict__ bias_table)
{
    extern __shared__ char smc[];
    const u32 smb = (u32)__cvta_generic_to_shared(smc);
    int* meta_s = (int*)(smc + OFF_META);

    const int head = blockIdx.y;
    const int wb   = blockIdx.x;          // b*64 + widx
    const int b    = wb >> 6;
    const int widx = wb & 63;
    const int hw = widx >> 3, ww = widx & 7;

    const int tid  = threadIdx.x;         // 0..639
    const int lane = tid & 31;
    const int warp = tid >> 5;            // 0..19
    const int g    = lane >> 2;
    const int t4   = lane & 3;
    const int wr   = warp * 16;           // this warp's 16 query rows

    // staging: threads 0..319 handle Q+K of token tid; 320..639 handle V^T
    const bool qk_half = tid < 320;
    const int tok = qk_half ? tid : tid - 320;
    const int t   = tok >> 6;
    const int hs  = (tok >> 3) & 7;
    const int wsv = tok & 7;
    const int Hp = hw * 8 + hs;
    const int Wp = ww * 8 + wsv;
    const int h = (Hp + 4) & 63;
    const int w = (Wp + 4) & 63;
    const int rh = (Hp < 56) ? 0 : ((Hp < 60) ? 1 : 2);
    const int rw = (Wp < 56) ? 0 : ((Wp < 60) ? 1 : 2);
    if (qk_half)
        meta_s[tok] = (t * 15 + hs + wsv) | ((rh * 3 + rw) << 8);

    const int row = ((b * T_FRAMES + t) << 12) + (h << 6) + w;
    const float* qp = qkv + (size_t)row * (3 * DIM) + head * HDIM;

    const float LOG2E = 1.4426950408889634f;
    const float qs_f = 0.17677669529663687f * LOG2E;

    if (qk_half) {
        const float4* qv = (const float4*)qp;
        const float4* kv = (const float4*)(qp + DIM);
        #pragma unroll
        for (int m = 0; m < 8; ++m) {
            float4 f = qv[m];
            const int off = tok * ROWB + m * 8;
            *(u32*)(smc + OFF_QH + off)     = packh2(f.x * qs_f, f.y * qs_f);
            *(u32*)(smc + OFF_QH + off + 4) = packh2(f.z * qs_f, f.w * qs_f);
        }
        #pragma unroll
        for (int m = 0; m < 8; ++m) {
            float4 f = kv[m];
            const int off = tok * ROWB + m * 8;
            *(u32*)(smc + OFF_KH + off)     = packh2(f.x, f.y);
            *(u32*)(smc + OFF_KH + off + 4) = packh2(f.z, f.w);
        }
    } else {
        const float4* vv = (const float4*)(qp + 2 * DIM);
        #pragma unroll
        for (int m = 0; m < 8; ++m) {
            float4 f = vv[m];
            float vals[4] = {f.x, f.y, f.z, f.w};
            #pragma unroll
            for (int e = 0; e < 4; ++e) {
                const int d = m * 4 + e;
                *(__half*)(smc + OFF_VTH + d * VTB + tok * 2) = __float2half_rn(vals[e]);
            }
        }
    }
    for (int idx = tid; idx < 1185; idx += 640)
        *(float*)(smc + OFF_BIAS + idx * 4) = bias_table[idx * HEADS + head] * LOG2E;

    __syncthreads();

    int ai[2], ri[2];
    #pragma unroll
    for (int hh = 0; hh < 2; ++hh) {
        int mv = meta_s[wr + g + 8 * hh];
        ai[hh] = (mv & 255) + 112;
        ri[hh] = mv >> 8;
    }

    // ldmatrix per-lane address components
    const int l8  = lane & 7;
    const u32 krb = (u32)(l8 * ROWB + (lane >> 3) * 16);
    const u32 vrb = (u32)(l8 * VTB + (lane >> 3) * 16);
    const u32 qrb = (u32)((wr + l8 + ((lane >> 3) & 1) * 8) * ROWB + (lane >> 4) * 16);

    // Q A-fragments: [kt][4]
    u32 qa[2][4];
    #pragma unroll
    for (int kt = 0; kt < 2; ++kt)
        ldsm4(qa[kt][0], qa[kt][1], qa[kt][2], qa[kt][3],
              smb + OFF_QH + qrb + kt * 32);

    const u32 khb = smb + OFF_KH + krb;
    const u32 vhb = smb + OFF_VTH + vrb;
    const u32 bib = smb + OFF_BIAS;

    float oacc[4][4];
    #pragma unroll
    for (int n = 0; n < 4; ++n)
        #pragma unroll
        for (int e = 0; e < 4; ++e) oacc[n][e] = 0.f;
    float lsum[2] = {0.f, 0.f};

    float sacc[4][4];
    u32 ps[4][2];                         // packed fp16 P fragments [n][hh]

    // ---- S block: S = Qh·Kh ----
    auto s_block = [&](int jb2) {
        #pragma unroll
        for (int n = 0; n < 4; ++n)
            #pragma unroll
            for (int e = 0; e < 4; ++e) sacc[n][e] = 0.f;
        #pragma unroll
        for (int n = 0; n < 4; ++n) {
            u32 kh[4];
            ldsm4(kh[0], kh[1], kh[2], kh[3], khb + (jb2 + 8 * n) * ROWB);
            float* c = sacc[n];
            mma16816(c[0], c[1], c[2], c[3],
                     qa[0][0], qa[0][1], qa[0][2], qa[0][3], kh[0], kh[1]);
            mma16816(c[0], c[1], c[2], c[3],
                     qa[1][0], qa[1][1], qa[1][2], qa[1][3], kh[2], kh[3]);
        }
    };

    // ---- fused softmax for one 8-key group: bias + mask + pack + ex2.f16x2 ----
    auto sm_n = [&](int jb2, int n, u32& sum0, u32& sum1) {
        const int j0 = jb2 + 8 * n + 2 * t4;
        const int mj0 = meta_s[j0], mj1 = meta_s[j0 + 1];
        const int b0i = mj0 & 255, b1i = mj1 & 255;
        const int rj0 = mj0 >> 8,  rj1 = mj1 >> 8;
        float* c = sacc[n];
        float s0 = c[0] + lds32f(bib + (ai[0] - b0i) * 4);
        float s1 = c[1] + lds32f(bib + (ai[0] - b1i) * 4);
        float s2 = c[2] + lds32f(bib + (ai[1] - b0i) * 4);
        float s3 = c[3] + lds32f(bib + (ai[1] - b1i) * 4);
        s0 = (ri[0] == rj0) ? s0 : -1e4f;   // exp2(-1e4) == 0 in fp16
        s1 = (ri[0] == rj1) ? s1 : -1e4f;
        s2 = (ri[1] == rj0) ? s2 : -1e4f;
        s3 = (ri[1] == rj1) ? s3 : -1e4f;
        const u32 pk0 = h2exp2(packh2(s0, s1));   // row hh0, cols j0,j0+1
        const u32 pk1 = h2exp2(packh2(s2, s3));   // row hh1
        ps[n][0] = pk0;
        ps[n][1] = pk1;
        sum0 = hadd2(sum0, pk0);
        sum1 = hadd2(sum1, pk1);
    };

    // ---- PV for one kt half: O += Ph·Vh ----
    auto pv_kt = [&](int jb2, int kt) {
        const u32 a0 = ps[2 * kt][0], a1 = ps[2 * kt][1];
        const u32 a2 = ps[2 * kt + 1][0], a3 = ps[2 * kt + 1][1];
        #pragma unroll
        for (int n = 0; n < 4; ++n) {
            u32 vh0, vh1;
            ldsm2(vh0, vh1, vhb + (8 * n) * VTB + jb2 * 2 + kt * 32);
            float* c = oacc[n];
            mma16816(c[0], c[1], c[2], c[3], a0, a1, a2, a3, vh0, vh1);
        }
    };

    auto flush_sums = [&](u32 sum0, u32 sum1) {
        float2 f0 = __half22float2(*(__half2*)&sum0);
        float2 f1 = __half22float2(*(__half2*)&sum1);
        lsum[0] += f0.x + f0.y;
        lsum[1] += f1.x + f1.y;
    };

    // ---- software-pipelined mainloop, half-jc interleave ----
    s_block(0);
    #pragma unroll 1
    for (int jc = 0; jc < 9; ++jc) {
        const int jb = jc * 32;
        u32 sum0 = 0, sum1 = 0;
        sm_n(jb, 0, sum0, sum1);
        sm_n(jb, 1, sum0, sum1);
        pv_kt(jb, 0);
        sm_n(jb, 2, sum0, sum1);
        sm_n(jb, 3, sum0, sum1);
        s_block(jb + 32);
        pv_kt(jb, 1);
        flush_sums(sum0, sum1);
    }
    {
        const int jb = 288;
        u32 sum0 = 0, sum1 = 0;
        sm_n(jb, 0, sum0, sum1);
        sm_n(jb, 1, sum0, sum1);
        pv_kt(jb, 0);
        sm_n(jb, 2, sum0, sum1);
        sm_n(jb, 3, sum0, sum1);
        pv_kt(jb, 1);
        flush_sums(sum0, sum1);
    }

    #pragma unroll
    for (int hh = 0; hh < 2; ++hh) {
        float v = lsum[hh];
        v += __shfl_xor_sync(0xffffffffu, v, 1);
        v += __shfl_xor_sync(0xffffffffu, v, 2);
        lsum[hh] = 1.0f / v;
    }

    #pragma unroll
    for (int hh = 0; hh < 2; ++hh) {
        const int r = wr + g + 8 * hh;
        float* orow = g_scratch + ((size_t)(wb * NTOK + r)) * DIM + head * HDIM;
        const float inv = lsum[hh];
        #pragma unroll
        for (int n = 0; n < 4; ++n) {
            float2 v = make_float2(oacc[n][2 * hh] * inv, oacc[n][2 * hh + 1] * inv);
            *(float2*)(orow + 8 * n + 2 * t4) = v;
        }
    }
}

// ---------------- projection kernel (fp16 hi-only, ldmatrix) ----------------
// 512 threads / 16 warps as 4(m) x 4(n). out = Oh·Wh (all hi-only fp16).
#define PWROW 400                      // padded W/o row bytes (200 fp16)
#define OFF_PWH 0
#define OFF_POH 76800
#define PROJ_SMEM 102400

__global__ void __launch_bounds__(512)
proj_kernel(const float* __restrict__ pw, const float* __restrict__ pb,
            float* __restrict__ out, int nchunks)
{
    extern __shared__ char smc[];
    const u32 smb = (u32)__cvta_generic_to_shared(smc);
    const int tid = threadIdx.x, lane = tid & 31, warp = tid >> 5;
    const int g = lane >> 2, t4 = lane & 3;
    const int wm = warp >> 2, wn = warp & 3;   // 4 x 4
    const int m0 = wm * 16, n0 = wn * 48;

    // ---- stage W (fp16 hi only) once ----
    for (int idx = tid; idx < DIM * 96; idx += 512) {
        const int c = idx / 96, kp = idx % 96;
        float2 v = *(const float2*)(pw + c * DIM + kp * 2);
        *(u32*)(smc + OFF_PWH + c * PWROW + kp * 4) = packh2(v.x, v.y);
    }
    float pbv[6][2];
    #pragma unroll
    for (int nt = 0; nt < 6; ++nt) {
        float2 v = *(const float2*)(pb + n0 + nt * 8 + 2 * t4);
        pbv[nt][0] = v.x; pbv[nt][1] = v.y;
    }

    const int l8 = lane & 7;
    const u32 arb = (u32)((m0 + l8 + ((lane >> 3) & 1) * 8) * PWROW + (lane >> 4) * 16);
    const u32 brb = (u32)((l8 + (lane >> 4) * 8) * PWROW + ((lane >> 3) & 1) * 16);

    const u32 whb = smb + OFF_PWH + brb;
    const u32 ohb = smb + OFF_POH + arb;

    // prefetch buffer for double-buffered staging
    float2 pre[12];
    int ci = blockIdx.x;
    if (ci < nchunks) {
        const float* src = g_scratch + (size_t)ci * (64 * DIM);
        #pragma unroll
        for (int it = 0; it < 12; ++it) {
            const int idx = tid + it * 512;
            const int tok = idx / 96, kp = idx % 96;
            pre[it] = *(const float2*)(src + tok * DIM + kp * 2);
        }
    }

    #pragma unroll 1
    for (; ci < nchunks; ci += gridDim.x) {
        __syncthreads();   // W staged (first) / previous chunk's LDSMs done
        #pragma unroll
        for (int it = 0; it < 12; ++it) {
            const int idx = tid + it * 512;
            const int tok = idx / 96, kp = idx % 96;
            *(u32*)(smc + OFF_POH + tok * PWROW + kp * 4) = packh2(pre[it].x, pre[it].y);
        }
        __syncthreads();

        // prefetch next chunk while this chunk computes
        const int cin = ci + gridDim.x;
        if (cin < nchunks) {
            const float* srcn = g_scratch + (size_t)cin * (64 * DIM);
            #pragma unroll
            for (int it = 0; it < 12; ++it) {
                const int idx = tid + it * 512;
                const int tok = idx / 96, kp = idx % 96;
                pre[it] = *(const float2*)(srcn + tok * DIM + kp * 2);
            }
        }

        float acc[6][4];
        #pragma unroll
        for (int nt = 0; nt < 6; ++nt)
            #pragma unroll
            for (int e = 0; e < 4; ++e) acc[nt][e] = 0.f;

        #pragma unroll
        for (int ki = 0; ki < 12; ++ki) {
            u32 ah[4];
            ldsm4v(ah[0], ah[1], ah[2], ah[3], ohb + ki * 32);
            #pragma unroll
            for (int p = 0; p < 3; ++p) {
                u32 bh[4];
                const u32 bo = (u32)((n0 + 16 * p) * PWROW) + ki * 32;
                ldsm4(bh[0], bh[1], bh[2], bh[3], whb + bo);
                float* c0 = acc[2 * p];
                float* c1 = acc[2 * p + 1];
                mma16816(c0[0], c0[1], c0[2], c0[3], ah[0], ah[1], ah[2], ah[3], bh[0], bh[1]);
                mma16816(c1[0], c1[1], c1[2], c1[3], ah[0], ah[1], ah[2], ah[3], bh[2], bh[3]);
            }
        }

        // ---- epilogue: bias + window-reverse scatter ----
        const int wbid = ci / 5, t = ci % 5;
        const int b = wbid >> 6, widx = wbid & 63;
        const int hw = widx >> 3, ww = widx & 7;
        #pragma unroll
        for (int hh = 0; hh < 2; ++hh) {
            const int s = m0 + g + 8 * hh;   // token 0..63
            const int hs = s >> 3, wsv = s & 7;
            const int h = (hw * 8 + hs + 4) & 63;
            const int w = (ww * 8 + wsv + 4) & 63;
            float* orow = out + ((size_t)((b * T_FRAMES + t) * 4096 + h * 64 + w)) * DIM;
            #pragma unroll
            for (int nt = 0; nt < 6; ++nt) {
                float2 v = make_float2(acc[nt][2 * hh]     + pbv[nt][0],
                                       acc[nt][2 * hh + 1] + pbv[nt][1]);
                *(float2*)(orow + n0 + nt * 8 + 2 * t4) = v;
            }
        }
    }
}

// ---------------- launch ----------------
extern "C" void kernel_launch(void* const* d_in, const int* in_sizes, int n_in,
                              void* d_out, int out_size)
{
    const float* qkv        = (const float*)d_in[0];
    const float* bias_table = (const float*)d_in[1];
    const float* pw         = (const float*)d_in[2];
    const float* pb         = (const float*)d_in[3];
    float* out = (float*)d_out;

    int B = in_sizes[0] / (T_FRAMES * 64 * 64 * 3 * DIM);
    if (B < 1) B = 1;
    if (B > 2) B = 2;   // scratch sized for B=2

    cudaFuncSetAttribute(attn_kernel, cudaFuncAttributeMaxDynamicSharedMemorySize, ATTN_SMEM);
    cudaFuncSetAttribute(proj_kernel, cudaFuncAttributeMaxDynamicSharedMemorySize, PROJ_SMEM);

    dim3 ag(B * 64, HEADS);
    attn_kernel<<<ag, 640, ATTN_SMEM>>>(qkv, bias_table);

    const int nchunks = B * 64 * T_FRAMES;
    int pgrid = nchunks < 148 ? nchunks : 148;
    proj_kernel<<<pgrid, 512, PROJ_SMEM>>>(pw, pb, out, nchunks);
}

// round 14
// speedup vs baseline: 4.5047x; 1.0017x over previous
#include <cuda_runtime.h>
#include <cuda_fp16.h>

typedef unsigned long long u64;
typedef unsigned int u32;

#define T_FRAMES 5
#define WS 8
#define HEADS 6
#define DIM 192
#define HDIM 32
#define NTOK 320

// scratch: per-window attention output, [wb][n][DIM], sized for B=2
__device__ float g_scratch[2 * 64 * NTOK * DIM];

// ---------------- small helpers ----------------
__device__ __forceinline__ float lds32f(u32 a) {
    float r; asm("ld.shared.b32 %0,[%1];" : "=f"(r) : "r"(a)); return r;
}
__device__ __forceinline__ void ldsm4(u32 &r0, u32 &r1, u32 &r2, u32 &r3, u32 a) {
    asm("ldmatrix.sync.aligned.m8n8.x4.shared.b16 {%0,%1,%2,%3},[%4];"
        : "=r"(r0), "=r"(r1), "=r"(r2), "=r"(r3) : "r"(a));
}
__device__ __forceinline__ void ldsm4v(u32 &r0, u32 &r1, u32 &r2, u32 &r3, u32 a) {
    asm volatile("ldmatrix.sync.aligned.m8n8.x4.shared.b16 {%0,%1,%2,%3},[%4];"
        : "=r"(r0), "=r"(r1), "=r"(r2), "=r"(r3) : "r"(a));
}
__device__ __forceinline__ void ldsm2(u32 &r0, u32 &r1, u32 a) {
    asm("ldmatrix.sync.aligned.m8n8.x2.shared.b16 {%0,%1},[%2];"
        : "=r"(r0), "=r"(r1) : "r"(a));
}
// fp16 mma m16n8k16, fp32 accumulate
__device__ __forceinline__ void mma16816(float &c0, float &c1, float &c2, float &c3,
                                         u32 a0, u32 a1, u32 a2, u32 a3,
                                         u32 b0, u32 b1) {
    asm("mma.sync.aligned.m16n8k16.row.col.f32.f16.f16.f32 "
        "{%0,%1,%2,%3},{%4,%5,%6,%7},{%8,%9},{%0,%1,%2,%3};"
        : "+f"(c0), "+f"(c1), "+f"(c2), "+f"(c3)
        : "r"(a0), "r"(a1), "r"(a2), "r"(a3), "r"(b0), "r"(b1));
}
__device__ __forceinline__ u32 packh2(float a, float b) {
    __half2 hv = __floats2half2_rn(a, b);
    return *(u32*)&hv;
}
// packed fp16 exp2
__device__ __forceinline__ u32 h2exp2(u32 s) {
    u32 r; asm("ex2.approx.f16x2 %0,%1;" : "=r"(r) : "r"(s)); return r;
}
__device__ __forceinline__ u32 hadd2(u32 a, u32 b) {
    u32 r; asm("add.rn.f16x2 %0,%1,%2;" : "=r"(r) : "r"(a), "r"(b)); return r;
}

// ---------------- attention kernel (fp16 hi-only, bias-in-accumulator) ----------------
// 640 threads / 20 warps; warp owns 16 query rows.
// sacc initialized with masked bias -> softmax = pack + ex2 only.
#define ROWB 80
#define VTB  656
#define OFF_QH   0
#define OFF_KH   25600
#define OFF_VTH  51200
#define OFF_BIAS 72192
#define OFF_META 76932
#define ATTN_SMEM (78212)

__global__ void __launch_bounds__(640)
attn_kernel(const float* __restrict__ qkv, const float* __restrict__ bias_table)
{
    extern __shared__ char smc[];
    const u32 smb = (u32)__cvta_generic_to_shared(smc);
    int* meta_s = (int*)(smc + OFF_META);

    const int head = blockIdx.y;
    const int wb   = blockIdx.x;          // b*64 + widx
    const int b    = wb >> 6;
    const int widx = wb & 63;
    const int hw = widx >> 3, ww = widx & 7;

    const int tid  = threadIdx.x;         // 0..639
    const int lane = tid & 31;
    const int warp = tid >> 5;            // 0..19
    const int g    = lane >> 2;
    const int t4   = lane & 3;
    const int wr   = warp * 16;           // this warp's 16 query rows

    // staging: threads 0..319 handle Q+K of token tid; 320..639 handle V^T
    const bool qk_half = tid < 320;
    const int tok = qk_half ? tid : tid - 320;
    const int t   = tok >> 6;
    const int hs  = (tok >> 3) & 7;
    const int wsv = tok & 7;
    const int Hp = hw * 8 + hs;
    const int Wp = ww * 8 + wsv;
    const int h = (Hp + 4) & 63;
    const int w = (Wp + 4) & 63;
    const int rh = (Hp < 56) ? 0 : ((Hp < 60) ? 1 : 2);
    const int rw = (Wp < 56) ? 0 : ((Wp < 60) ? 1 : 2);
    if (qk_half)
        meta_s[tok] = (t * 15 + hs + wsv) | ((rh * 3 + rw) << 8);

    const int row = ((b * T_FRAMES + t) << 12) + (h << 6) + w;
    const float* qp = qkv + (size_t)row * (3 * DIM) + head * HDIM;

    const float LOG2E = 1.4426950408889634f;
    const float qs_f = 0.17677669529663687f * LOG2E;

    if (qk_half) {
        const float4* qv = (const float4*)qp;
        const float4* kv = (const float4*)(qp + DIM);
        #pragma unroll
        for (int m = 0; m < 8; ++m) {
            float4 f = qv[m];
            const int off = tok * ROWB + m * 8;
            *(u32*)(smc + OFF_QH + off)     = packh2(f.x * qs_f, f.y * qs_f);
            *(u32*)(smc + OFF_QH + off + 4) = packh2(f.z * qs_f, f.w * qs_f);
        }
        #pragma unroll
        for (int m = 0; m < 8; ++m) {
            float4 f = kv[m];
            const int off = tok * ROWB + m * 8;
            *(u32*)(smc + OFF_KH + off)     = packh2(f.x, f.y);
            *(u32*)(smc + OFF_KH + off + 4) = packh2(f.z, f.w);
        }
    } else {
        const float4* vv = (const float4*)(qp + 2 * DIM);
        #pragma unroll
        for (int m = 0; m < 8; ++m) {
            float4 f = vv[m];
            float vals[4] = {f.x, f.y, f.z, f.w};
            #pragma unroll
            for (int e = 0; e < 4; ++e) {
                const int d = m * 4 + e;
                *(__half*)(smc + OFF_VTH + d * VTB + tok * 2) = __float2half_rn(vals[e]);
            }
        }
    }
    for (int idx = tid; idx < 1185; idx += 640)
        *(float*)(smc + OFF_BIAS + idx * 4) = bias_table[idx * HEADS + head] * LOG2E;

    __syncthreads();

    int ai[2], ri[2];
    #pragma unroll
    for (int hh = 0; hh < 2; ++hh) {
        int mv = meta_s[wr + g + 8 * hh];
        ai[hh] = (mv & 255) + 112;
        ri[hh] = mv >> 8;
    }

    // ldmatrix per-lane address components
    const int l8  = lane & 7;
    const u32 krb = (u32)(l8 * ROWB + (lane >> 3) * 16);
    const u32 vrb = (u32)(l8 * VTB + (lane >> 3) * 16);
    const u32 qrb = (u32)((wr + l8 + ((lane >> 3) & 1) * 8) * ROWB + (lane >> 4) * 16);

    // Q A-fragments: [kt][4]
    u32 qa[2][4];
    #pragma unroll
    for (int kt = 0; kt < 2; ++kt)
        ldsm4(qa[kt][0], qa[kt][1], qa[kt][2], qa[kt][3],
              smb + OFF_QH + qrb + kt * 32);

    const u32 khb = smb + OFF_KH + krb;
    const u32 vhb = smb + OFF_VTH + vrb;
    const u32 bib = smb + OFF_BIAS;

    float oacc[4][4];
    #pragma unroll
    for (int n = 0; n < 4; ++n)
        #pragma unroll
        for (int e = 0; e < 4; ++e) oacc[n][e] = 0.f;
    float lsum[2] = {0.f, 0.f};

    float sacc[4][4];
    u32 ps[4][2];                         // packed fp16 P fragments [n][hh]

    // ---- S block: sacc = masked_bias; sacc += Qh·Kh ----
    // bias/mask LDS+SEL latency hides behind the K LDSMs + 8 MMAs here,
    // a full half-jc ahead of the softmax consumer.
    auto s_block = [&](int jb2) {
        #pragma unroll
        for (int n = 0; n < 4; ++n) {
            const int j0 = jb2 + 8 * n + 2 * t4;
            const int mj0 = meta_s[j0], mj1 = meta_s[j0 + 1];
            const int b0i = mj0 & 255, b1i = mj1 & 255;
            const int rj0 = mj0 >> 8,  rj1 = mj1 >> 8;
            float* c = sacc[n];
            c[0] = (ri[0] == rj0) ? lds32f(bib + (ai[0] - b0i) * 4) : -1e4f;
            c[1] = (ri[0] == rj1) ? lds32f(bib + (ai[0] - b1i) * 4) : -1e4f;
            c[2] = (ri[1] == rj0) ? lds32f(bib + (ai[1] - b0i) * 4) : -1e4f;
            c[3] = (ri[1] == rj1) ? lds32f(bib + (ai[1] - b1i) * 4) : -1e4f;
        }
        #pragma unroll
        for (int n = 0; n < 4; ++n) {
            u32 kh[4];
            ldsm4(kh[0], kh[1], kh[2], kh[3], khb + (jb2 + 8 * n) * ROWB);
            float* c = sacc[n];
            mma16816(c[0], c[1], c[2], c[3],
                     qa[0][0], qa[0][1], qa[0][2], qa[0][3], kh[0], kh[1]);
            mma16816(c[0], c[1], c[2], c[3],
                     qa[1][0], qa[1][1], qa[1][2], qa[1][3], kh[2], kh[3]);
        }
    };

    // ---- softmax for one 8-key group: just pack + ex2.f16x2 + sum ----
    auto sm_n = [&](int n, u32& sum0, u32& sum1) {
        float* c = sacc[n];
        const u32 pk0 = h2exp2(packh2(c[0], c[1]));   // row hh0
        const u32 pk1 = h2exp2(packh2(c[2], c[3]));   // row hh1
        ps[n][0] = pk0;
        ps[n][1] = pk1;
        sum0 = hadd2(sum0, pk0);
        sum1 = hadd2(sum1, pk1);
    };

    // ---- PV for one kt half: O += Ph·Vh ----
    auto pv_kt = [&](int jb2, int kt) {
        const u32 a0 = ps[2 * kt][0], a1 = ps[2 * kt][1];
        const u32 a2 = ps[2 * kt + 1][0], a3 = ps[2 * kt + 1][1];
        #pragma unroll
        for (int n = 0; n < 4; ++n) {
            u32 vh0, vh1;
            ldsm2(vh0, vh1, vhb + (8 * n) * VTB + jb2 * 2 + kt * 32);
            float* c = oacc[n];
            mma16816(c[0], c[1], c[2], c[3], a0, a1, a2, a3, vh0, vh1);
        }
    };

    auto flush_sums = [&](u32 sum0, u32 sum1) {
        float2 f0 = __half22float2(*(__half2*)&sum0);
        float2 f1 = __half22float2(*(__half2*)&sum1);
        lsum[0] += f0.x + f0.y;
        lsum[1] += f1.x + f1.y;
    };

    // ---- software-pipelined mainloop, half-jc interleave ----
    s_block(0);
    #pragma unroll 1
    for (int jc = 0; jc < 9; ++jc) {
        const int jb = jc * 32;
        u32 sum0 = 0, sum1 = 0;
        sm_n(0, sum0, sum1);
        sm_n(1, sum0, sum1);
        pv_kt(jb, 0);
        sm_n(2, sum0, sum1);
        sm_n(3, sum0, sum1);
        s_block(jb + 32);
        pv_kt(jb, 1);
        flush_sums(sum0, sum1);
    }
    {
        const int jb = 288;
        u32 sum0 = 0, sum1 = 0;
        sm_n(0, sum0, sum1);
        sm_n(1, sum0, sum1);
        pv_kt(jb, 0);
        sm_n(2, sum0, sum1);
        sm_n(3, sum0, sum1);
        pv_kt(jb, 1);
        flush_sums(sum0, sum1);
    }

    #pragma unroll
    for (int hh = 0; hh < 2; ++hh) {
        float v = lsum[hh];
        v += __shfl_xor_sync(0xffffffffu, v, 1);
        v += __shfl_xor_sync(0xffffffffu, v, 2);
        lsum[hh] = 1.0f / v;
    }

    #pragma unroll
    for (int hh = 0; hh < 2; ++hh) {
        const int r = wr + g + 8 * hh;
        float* orow = g_scratch + ((size_t)(wb * NTOK + r)) * DIM + head * HDIM;
        const float inv = lsum[hh];
        #pragma unroll
        for (int n = 0; n < 4; ++n) {
            float2 v = make_float2(oacc[n][2 * hh] * inv, oacc[n][2 * hh + 1] * inv);
            *(float2*)(orow + 8 * n + 2 * t4) = v;
        }
    }
}

// ---------------- projection kernel (fp16 hi-only, double-buffered smem) ----------------
// 512 threads / 16 warps as 4(m) x 4(n). out = Oh·Wh. One barrier per chunk.
#define PWROW 400                      // padded W/o row bytes (200 fp16)
#define OFF_PWH  0
#define OFF_POH0 76800
#define OFF_POH1 102400
#define PROJ_SMEM 128000

__global__ void __launch_bounds__(512)
proj_kernel(const float* __restrict__ pw, const float* __restrict__ pb,
            float* __restrict__ out, int nchunks)
{
    extern __shared__ char smc[];
    const u32 smb = (u32)__cvta_generic_to_shared(smc);
    const int tid = threadIdx.x, lane = tid & 31, warp = tid >> 5;
    const int g = lane >> 2, t4 = lane & 3;
    const int wm = warp >> 2, wn = warp & 3;   // 4 x 4
    const int m0 = wm * 16, n0 = wn * 48;

    // ---- stage W (fp16 hi only) once ----
    for (int idx = tid; idx < DIM * 96; idx += 512) {
        const int c = idx / 96, kp = idx % 96;
        float2 v = *(const float2*)(pw + c * DIM + kp * 2);
        *(u32*)(smc + OFF_PWH + c * PWROW + kp * 4) = packh2(v.x, v.y);
    }
    float pbv[6][2];
    #pragma unroll
    for (int nt = 0; nt < 6; ++nt) {
        float2 v = *(const float2*)(pb + n0 + nt * 8 + 2 * t4);
        pbv[nt][0] = v.x; pbv[nt][1] = v.y;
    }

    const int l8 = lane & 7;
    const u32 arb = (u32)((m0 + l8 + ((lane >> 3) & 1) * 8) * PWROW + (lane >> 4) * 16);
    const u32 brb = (u32)((l8 + (lane >> 4) * 8) * PWROW + ((lane >> 3) & 1) * 16);

    const u32 whb  = smb + OFF_PWH + brb;
    const u32 ohb0 = smb + OFF_POH0 + arb;
    const u32 ohb1 = smb + OFF_POH1 + arb;

    // per-thread STS target offsets within a buffer
    // (idx = tid + it*512 -> tok, kp)
    auto sts_chunk = [&](int bufsel, const float2* pre) {
        const u32 base = bufsel ? (u32)OFF_POH1 : (u32)OFF_POH0;
        #pragma unroll
        for (int it = 0; it < 12; ++it) {
            const int idx = tid + it * 512;
            const int tok = idx / 96, kp = idx % 96;
            *(u32*)(smc + base + tok * PWROW + kp * 4) = packh2(pre[it].x, pre[it].y);
        }
    };
    auto ldg_chunk = [&](int c, float2* pre) {
        const float* src = g_scratch + (size_t)c * (64 * DIM);
        #pragma unroll
        for (int it = 0; it < 12; ++it) {
            const int idx = tid + it * 512;
            const int tok = idx / 96, kp = idx % 96;
            pre[it] = *(const float2*)(src + tok * DIM + kp * 2);
        }
    };

    const int stride = gridDim.x;
    float2 pre[12];
    int ci = blockIdx.x;
    if (ci < nchunks) {
        ldg_chunk(ci, pre);
        sts_chunk(0, pre);
        if (ci + stride < nchunks) ldg_chunk(ci + stride, pre);
    }
    __syncthreads();

    int bufsel = 0;
    #pragma unroll 1
    for (; ci < nchunks; ci += stride) {
        // stage NEXT chunk into the other buffer (overlaps compute below)
        if (ci + stride < nchunks) {
            sts_chunk(bufsel ^ 1, pre);
            if (ci + 2 * stride < nchunks) ldg_chunk(ci + 2 * stride, pre);
        }

        float acc[6][4];
        #pragma unroll
        for (int nt = 0; nt < 6; ++nt)
            #pragma unroll
            for (int e = 0; e < 4; ++e) acc[nt][e] = 0.f;

        const u32 ohb = bufsel ? ohb1 : ohb0;
        #pragma unroll
        for (int ki = 0; ki < 12; ++ki) {
            u32 ah[4];
            ldsm4v(ah[0], ah[1], ah[2], ah[3], ohb + ki * 32);
            #pragma unroll
            for (int p = 0; p < 3; ++p) {
                u32 bh[4];
                const u32 bo = (u32)((n0 + 16 * p) * PWROW) + ki * 32;
                ldsm4(bh[0], bh[1], bh[2], bh[3], whb + bo);
                float* c0 = acc[2 * p];
                float* c1 = acc[2 * p + 1];
                mma16816(c0[0], c0[1], c0[2], c0[3], ah[0], ah[1], ah[2], ah[3], bh[0], bh[1]);
                mma16816(c1[0], c1[1], c1[2], c1[3], ah[0], ah[1], ah[2], ah[3], bh[2], bh[3]);
            }
        }
        __syncthreads();   // all reads of buf[bufsel] and writes of buf[bufsel^1] done

        // ---- epilogue: bias + window-reverse scatter (registers only) ----
        const int wbid = ci / 5, t = ci % 5;
        const int b = wbid >> 6, widx = wbid & 63;
        const int hw = widx >> 3, ww = widx & 7;
        #pragma unroll
        for (int hh = 0; hh < 2; ++hh) {
            const int s = m0 + g + 8 * hh;   // token 0..63
            const int hs = s >> 3, wsv = s & 7;
            const int h = (hw * 8 + hs + 4) & 63;
            const int w = (ww * 8 + wsv + 4) & 63;
            float* orow = out + ((size_t)((b * T_FRAMES + t) * 4096 + h * 64 + w)) * DIM;
            #pragma unroll
            for (int nt = 0; nt < 6; ++nt) {
                float2 v = make_float2(acc[nt][2 * hh]     + pbv[nt][0],
                                       acc[nt][2 * hh + 1] + pbv[nt][1]);
                *(float2*)(orow + n0 + nt * 8 + 2 * t4) = v;
            }
        }
        bufsel ^= 1;
    }
}

// ---------------- launch ----------------
extern "C" void kernel_launch(void* const* d_in, const int* in_sizes, int n_in,
                              void* d_out, int out_size)
{
    const float* qkv        = (const float*)d_in[0];
    const float* bias_table = (const float*)d_in[1];
    const float* pw         = (const float*)d_in[2];
    const float* pb         = (const float*)d_in[3];
    float* out = (float*)d_out;

    int B = in_sizes[0] / (T_FRAMES * 64 * 64 * 3 * DIM);
    if (B < 1) B = 1;
    if (B > 2) B = 2;   // scratch sized for B=2

    cudaFuncSetAttribute(attn_kernel, cudaFuncAttributeMaxDynamicSharedMemorySize, ATTN_SMEM);
    cudaFuncSetAttribute(proj_kernel, cudaFuncAttributeMaxDynamicSharedMemorySize, PROJ_SMEM);

    dim3 ag(B * 64, HEADS);
    attn_kernel<<<ag, 640, ATTN_SMEM>>>(qkv, bias_table);

    const int nchunks = B * 64 * T_FRAMES;
    int pgrid = nchunks < 148 ? nchunks : 148;
    proj_kernel<<<pgrid, 512, PROJ_SMEM>>>(pw, pb, out, nchunks);
}

// round 15
// speedup vs baseline: 4.6783x; 1.0386x over previous
#include <cuda_runtime.h>
#include <cuda_fp16.h>

typedef unsigned long long u64;
typedef unsigned int u32;

#define T_FRAMES 5
#define WS 8
#define HEADS 6
#define DIM 192
#define HDIM 32
#define NTOK 320

// scratch: per-window attention output, fp16 (half2 packed in u32), [wb][n][DIM]
__device__ u32 g_scratch[2 * 64 * NTOK * DIM / 2];

// ---------------- small helpers ----------------
__device__ __forceinline__ float lds32f(u32 a) {
    float r; asm("ld.shared.b32 %0,[%1];" : "=f"(r) : "r"(a)); return r;
}
__device__ __forceinline__ void ldsm4(u32 &r0, u32 &r1, u32 &r2, u32 &r3, u32 a) {
    asm("ldmatrix.sync.aligned.m8n8.x4.shared.b16 {%0,%1,%2,%3},[%4];"
        : "=r"(r0), "=r"(r1), "=r"(r2), "=r"(r3) : "r"(a));
}
__device__ __forceinline__ void ldsm4t(u32 &r0, u32 &r1, u32 &r2, u32 &r3, u32 a) {
    asm("ldmatrix.sync.aligned.m8n8.x4.trans.shared.b16 {%0,%1,%2,%3},[%4];"
        : "=r"(r0), "=r"(r1), "=r"(r2), "=r"(r3) : "r"(a));
}
__device__ __forceinline__ void ldsm4v(u32 &r0, u32 &r1, u32 &r2, u32 &r3, u32 a) {
    asm volatile("ldmatrix.sync.aligned.m8n8.x4.shared.b16 {%0,%1,%2,%3},[%4];"
        : "=r"(r0), "=r"(r1), "=r"(r2), "=r"(r3) : "r"(a));
}
// fp16 mma m16n8k16, fp32 accumulate
__device__ __forceinline__ void mma16816(float &c0, float &c1, float &c2, float &c3,
                                         u32 a0, u32 a1, u32 a2, u32 a3,
                                         u32 b0, u32 b1) {
    asm("mma.sync.aligned.m16n8k16.row.col.f32.f16.f16.f32 "
        "{%0,%1,%2,%3},{%4,%5,%6,%7},{%8,%9},{%0,%1,%2,%3};"
        : "+f"(c0), "+f"(c1), "+f"(c2), "+f"(c3)
        : "r"(a0), "r"(a1), "r"(a2), "r"(a3), "r"(b0), "r"(b1));
}
__device__ __forceinline__ u32 packh2(float a, float b) {
    __half2 hv = __floats2half2_rn(a, b);
    return *(u32*)&hv;
}
// packed fp16 exp2
__device__ __forceinline__ u32 h2exp2(u32 s) {
    u32 r; asm("ex2.approx.f16x2 %0,%1;" : "=r"(r) : "r"(s)); return r;
}
__device__ __forceinline__ u32 hadd2(u32 a, u32 b) {
    u32 r; asm("add.rn.f16x2 %0,%1,%2;" : "=r"(r) : "r"(a), "r"(b)); return r;
}

// ---------------- attention kernel (fp16 hi-only, bias-in-accumulator) ----------------
// 640 threads / 20 warps; warp owns 16 query rows.
// Q,K,V all row-major 80B rows; V fragments via ldmatrix.trans.
#define ROWB 80
#define OFF_QH   0
#define OFF_KH   25600
#define OFF_VH   51200
#define OFF_BIAS 76800
#define OFF_META 81540
#define ATTN_SMEM (82820)

__global__ void __launch_bounds__(640)
attn_kernel(const float* __restrict__ qkv, const float* __restrict__ bias_table)
{
    extern __shared__ char smc[];
    const u32 smb = (u32)__cvta_generic_to_shared(smc);
    int* meta_s = (int*)(smc + OFF_META);

    const int head = blockIdx.y;
    const int wb   = blockIdx.x;          // b*64 + widx
    const int b    = wb >> 6;
    const int widx = wb & 63;
    const int hw = widx >> 3, ww = widx & 7;

    const int tid  = threadIdx.x;         // 0..639
    const int lane = tid & 31;
    const int warp = tid >> 5;            // 0..19
    const int g    = lane >> 2;
    const int t4   = lane & 3;
    const int wr   = warp * 16;           // this warp's 16 query rows

    // staging: threads 0..319 handle Q+K of token tid; 320..639 handle V
    const bool qk_half = tid < 320;
    const int tok = qk_half ? tid : tid - 320;
    const int t   = tok >> 6;
    const int hs  = (tok >> 3) & 7;
    const int wsv = tok & 7;
    const int Hp = hw * 8 + hs;
    const int Wp = ww * 8 + wsv;
    const int h = (Hp + 4) & 63;
    const int w = (Wp + 4) & 63;
    const int rh = (Hp < 56) ? 0 : ((Hp < 60) ? 1 : 2);
    const int rw = (Wp < 56) ? 0 : ((Wp < 60) ? 1 : 2);
    if (qk_half)
        meta_s[tok] = (t * 15 + hs + wsv) | ((rh * 3 + rw) << 8);

    const int row = ((b * T_FRAMES + t) << 12) + (h << 6) + w;
    const float* qp = qkv + (size_t)row * (3 * DIM) + head * HDIM;

    const float LOG2E = 1.4426950408889634f;
    const float qs_f = 0.17677669529663687f * LOG2E;

    if (qk_half) {
        const float4* qv = (const float4*)qp;
        const float4* kv = (const float4*)(qp + DIM);
        #pragma unroll
        for (int m = 0; m < 8; ++m) {
            float4 f = qv[m];
            const int off = tok * ROWB + m * 8;
            *(u32*)(smc + OFF_QH + off)     = packh2(f.x * qs_f, f.y * qs_f);
            *(u32*)(smc + OFF_QH + off + 4) = packh2(f.z * qs_f, f.w * qs_f);
        }
        #pragma unroll
        for (int m = 0; m < 8; ++m) {
            float4 f = kv[m];
            const int off = tok * ROWB + m * 8;
            *(u32*)(smc + OFF_KH + off)     = packh2(f.x, f.y);
            *(u32*)(smc + OFF_KH + off + 4) = packh2(f.z, f.w);
        }
    } else {
        const float4* vv = (const float4*)(qp + 2 * DIM);
        #pragma unroll
        for (int m = 0; m < 8; ++m) {
            float4 f = vv[m];
            const int off = tok * ROWB + m * 8;
            *(u32*)(smc + OFF_VH + off)     = packh2(f.x, f.y);
            *(u32*)(smc + OFF_VH + off + 4) = packh2(f.z, f.w);
        }
    }
    for (int idx = tid; idx < 1185; idx += 640)
        *(float*)(smc + OFF_BIAS + idx * 4) = bias_table[idx * HEADS + head] * LOG2E;

    __syncthreads();

    int ai[2], ri[2];
    #pragma unroll
    for (int hh = 0; hh < 2; ++hh) {
        int mv = meta_s[wr + g + 8 * hh];
        ai[hh] = (mv & 255) + 112;
        ri[hh] = mv >> 8;
    }

    // ldmatrix per-lane address components
    const int l8  = lane & 7;
    const u32 krb = (u32)(l8 * ROWB + (lane >> 3) * 16);               // K A/B-style x4
    const u32 qrb = (u32)((wr + l8 + ((lane >> 3) & 1) * 8) * ROWB + (lane >> 4) * 16);
    const u32 vtb = smb + OFF_VH + (u32)(lane * ROWB);                 // V trans: lane = key row

    // Q A-fragments: [kt][4]
    u32 qa[2][4];
    #pragma unroll
    for (int kt = 0; kt < 2; ++kt)
        ldsm4(qa[kt][0], qa[kt][1], qa[kt][2], qa[kt][3],
              smb + OFF_QH + qrb + kt * 32);

    const u32 khb = smb + OFF_KH + krb;
    const u32 bib = smb + OFF_BIAS;

    float oacc[4][4];
    #pragma unroll
    for (int n = 0; n < 4; ++n)
        #pragma unroll
        for (int e = 0; e < 4; ++e) oacc[n][e] = 0.f;
    float lsum[2] = {0.f, 0.f};

    float sacc[4][4];
    u32 ps[4][2];                         // packed fp16 P fragments [n][hh]

    // ---- S block: sacc = masked_bias; sacc += Qh·Kh ----
    auto s_block = [&](int jb2) {
        #pragma unroll
        for (int n = 0; n < 4; ++n) {
            const int j0 = jb2 + 8 * n + 2 * t4;
            const int mj0 = meta_s[j0], mj1 = meta_s[j0 + 1];
            const int b0i = mj0 & 255, b1i = mj1 & 255;
            const int rj0 = mj0 >> 8,  rj1 = mj1 >> 8;
            float* c = sacc[n];
            c[0] = (ri[0] == rj0) ? lds32f(bib + (ai[0] - b0i) * 4) : -1e4f;
            c[1] = (ri[0] == rj1) ? lds32f(bib + (ai[0] - b1i) * 4) : -1e4f;
            c[2] = (ri[1] == rj0) ? lds32f(bib + (ai[1] - b0i) * 4) : -1e4f;
            c[3] = (ri[1] == rj1) ? lds32f(bib + (ai[1] - b1i) * 4) : -1e4f;
        }
        #pragma unroll
        for (int n = 0; n < 4; ++n) {
            u32 kh[4];
            ldsm4(kh[0], kh[1], kh[2], kh[3], khb + (jb2 + 8 * n) * ROWB);
            float* c = sacc[n];
            mma16816(c[0], c[1], c[2], c[3],
                     qa[0][0], qa[0][1], qa[0][2], qa[0][3], kh[0], kh[1]);
            mma16816(c[0], c[1], c[2], c[3],
                     qa[1][0], qa[1][1], qa[1][2], qa[1][3], kh[2], kh[3]);
        }
    };

    // ---- softmax for one 8-key group: pack + ex2.f16x2 + sum ----
    auto sm_n = [&](int n, u32& sum0, u32& sum1) {
        float* c = sacc[n];
        const u32 pk0 = h2exp2(packh2(c[0], c[1]));   // row hh0
        const u32 pk1 = h2exp2(packh2(c[2], c[3]));   // row hh1
        ps[n][0] = pk0;
        ps[n][1] = pk1;
        sum0 = hadd2(sum0, pk0);
        sum1 = hadd2(sum1, pk1);
    };

    // ---- PV for full 32-key block: V tiles via ldmatrix.trans.x4 ----
    auto pv_all = [&](int jb2) {
        const u32 vb = vtb + (u32)(jb2 * ROWB);
        #pragma unroll
        for (int n = 0; n < 4; ++n) {
            u32 vt[4];
            ldsm4t(vt[0], vt[1], vt[2], vt[3], vb + n * 16);
            float* c = oacc[n];
            mma16816(c[0], c[1], c[2], c[3],
                     ps[0][0], ps[0][1], ps[1][0], ps[1][1], vt[0], vt[1]);
            mma16816(c[0], c[1], c[2], c[3],
                     ps[2][0], ps[2][1], ps[3][0], ps[3][1], vt[2], vt[3]);
        }
    };

    auto flush_sums = [&](u32 sum0, u32 sum1) {
        float2 f0 = __half22float2(*(__half2*)&sum0);
        float2 f1 = __half22float2(*(__half2*)&sum1);
        lsum[0] += f0.x + f0.y;
        lsum[1] += f1.x + f1.y;
    };

    // ---- software-pipelined mainloop ----
    s_block(0);
    #pragma unroll 1
    for (int jc = 0; jc < 9; ++jc) {
        const int jb = jc * 32;
        u32 sum0 = 0, sum1 = 0;
        sm_n(0, sum0, sum1);
        sm_n(1, sum0, sum1);
        sm_n(2, sum0, sum1);
        sm_n(3, sum0, sum1);
        s_block(jb + 32);          // next S: tensor work covers softmax latency
        pv_all(jb);
        flush_sums(sum0, sum1);
    }
    {
        u32 sum0 = 0, sum1 = 0;
        sm_n(0, sum0, sum1);
        sm_n(1, sum0, sum1);
        sm_n(2, sum0, sum1);
        sm_n(3, sum0, sum1);
        pv_all(288);
        flush_sums(sum0, sum1);
    }

    #pragma unroll
    for (int hh = 0; hh < 2; ++hh) {
        float v = lsum[hh];
        v += __shfl_xor_sync(0xffffffffu, v, 1);
        v += __shfl_xor_sync(0xffffffffu, v, 2);
        lsum[hh] = 1.0f / v;
    }

    // fp16 scratch write (same rounding point as old proj-staging packh2)
    #pragma unroll
    for (int hh = 0; hh < 2; ++hh) {
        const int r = wr + g + 8 * hh;
        u32* orow = g_scratch + (((size_t)(wb * NTOK + r)) * DIM + head * HDIM) / 2;
        const float inv = lsum[hh];
        #pragma unroll
        for (int n = 0; n < 4; ++n)
            orow[(8 * n + 2 * t4) >> 1] = packh2(oacc[n][2 * hh] * inv,
                                                 oacc[n][2 * hh + 1] * inv);
    }
}

// ---------------- projection kernel (fp16 hi-only, double-buffered smem) ----------------
// 512 threads / 16 warps as 4(m) x 4(n). out = Oh·Wh. Scratch already fp16.
#define PWROW 400                      // padded W/o row bytes (200 fp16)
#define OFF_PWH  0
#define OFF_POH0 76800
#define OFF_POH1 102400
#define PROJ_SMEM 128000

__global__ void __launch_bounds__(512)
proj_kernel(const float* __restrict__ pw, const float* __restrict__ pb,
            float* __restrict__ out, int nchunks)
{
    extern __shared__ char smc[];
    const u32 smb = (u32)__cvta_generic_to_shared(smc);
    const int tid = threadIdx.x, lane = tid & 31, warp = tid >> 5;
    const int g = lane >> 2, t4 = lane & 3;
    const int wm = warp >> 2, wn = warp & 3;   // 4 x 4
    const int m0 = wm * 16, n0 = wn * 48;

    // ---- stage W (fp16 hi only) once ----
    for (int idx = tid; idx < DIM * 96; idx += 512) {
        const int c = idx / 96, kp = idx % 96;
        float2 v = *(const float2*)(pw + c * DIM + kp * 2);
        *(u32*)(smc + OFF_PWH + c * PWROW + kp * 4) = packh2(v.x, v.y);
    }
    float pbv[6][2];
    #pragma unroll
    for (int nt = 0; nt < 6; ++nt) {
        float2 v = *(const float2*)(pb + n0 + nt * 8 + 2 * t4);
        pbv[nt][0] = v.x; pbv[nt][1] = v.y;
    }

    const int l8 = lane & 7;
    const u32 arb = (u32)((m0 + l8 + ((lane >> 3) & 1) * 8) * PWROW + (lane >> 4) * 16);
    const u32 brb = (u32)((l8 + (lane >> 4) * 8) * PWROW + ((lane >> 3) & 1) * 16);

    const u32 whb  = smb + OFF_PWH + brb;
    const u32 ohb0 = smb + OFF_POH0 + arb;
    const u32 ohb1 = smb + OFF_POH1 + arb;

    auto sts_chunk = [&](int bufsel, const u32* pre) {
        const u32 base = bufsel ? (u32)OFF_POH1 : (u32)OFF_POH0;
        #pragma unroll
        for (int it = 0; it < 12; ++it) {
            const int idx = tid + it * 512;
            const int tok = idx / 96, kp = idx % 96;
            *(u32*)(smc + base + tok * PWROW + kp * 4) = pre[it];
        }
    };
    auto ldg_chunk = [&](int c, u32* pre) {
        const u32* src = g_scratch + (size_t)c * (64 * 96);   // 96 u32 per token
        #pragma unroll
        for (int it = 0; it < 12; ++it)
            pre[it] = src[tid + it * 512];
    };

    const int stride = gridDim.x;
    u32 pre[12];
    int ci = blockIdx.x;
    if (ci < nchunks) {
        ldg_chunk(ci, pre);
        sts_chunk(0, pre);
        if (ci + stride < nchunks) ldg_chunk(ci + stride, pre);
    }
    __syncthreads();

    int bufsel = 0;
    #pragma unroll 1
    for (; ci < nchunks; ci += stride) {
        // stage NEXT chunk into the other buffer (overlaps compute below)
        if (ci + stride < nchunks) {
            sts_chunk(bufsel ^ 1, pre);
            if (ci + 2 * stride < nchunks) ldg_chunk(ci + 2 * stride, pre);
        }

        float acc[6][4];
        #pragma unroll
        for (int nt = 0; nt < 6; ++nt)
            #pragma unroll
            for (int e = 0; e < 4; ++e) acc[nt][e] = 0.f;

        const u32 ohb = bufsel ? ohb1 : ohb0;
        #pragma unroll
        for (int ki = 0; ki < 12; ++ki) {
            u32 ah[4];
            ldsm4v(ah[0], ah[1], ah[2], ah[3], ohb + ki * 32);
            #pragma unroll
            for (int p = 0; p < 3; ++p) {
                u32 bh[4];
                const u32 bo = (u32)((n0 + 16 * p) * PWROW) + ki * 32;
                ldsm4(bh[0], bh[1], bh[2], bh[3], whb + bo);
                float* c0 = acc[2 * p];
                float* c1 = acc[2 * p + 1];
                mma16816(c0[0], c0[1], c0[2], c0[3], ah[0], ah[1], ah[2], ah[3], bh[0], bh[1]);
                mma16816(c1[0], c1[1], c1[2], c1[3], ah[0], ah[1], ah[2], ah[3], bh[2], bh[3]);
            }
        }
        __syncthreads();   // all reads of buf[bufsel] and writes of buf[bufsel^1] done

        // ---- epilogue: bias + window-reverse scatter ----
        const int wbid = ci / 5, t = ci % 5;
        const int b = wbid >> 6, widx = wbid & 63;
        const int hw = widx >> 3, ww = widx & 7;
        #pragma unroll
        for (int hh = 0; hh < 2; ++hh) {
            const int s = m0 + g + 8 * hh;   // token 0..63
            const int hs = s >> 3, wsv = s & 7;
            const int h = (hw * 8 + hs + 4) & 63;
            const int w = (ww * 8 + wsv + 4) & 63;
            float* orow = out + ((size_t)((b * T_FRAMES + t) * 4096 + h * 64 + w)) * DIM;
            #pragma unroll
            for (int nt = 0; nt < 6; ++nt) {
                float2 v = make_float2(acc[nt][2 * hh]     + pbv[nt][0],
                                       acc[nt][2 * hh + 1] + pbv[nt][1]);
                *(float2*)(orow + n0 + nt * 8 + 2 * t4) = v;
            }
        }
        bufsel ^= 1;
    }
}

// ---------------- launch ----------------
extern "C" void kernel_launch(void* const* d_in, const int* in_sizes, int n_in,
                              void* d_out, int out_size)
{
    const float* qkv        = (const float*)d_in[0];
    const float* bias_table = (const float*)d_in[1];
    const float* pw         = (const float*)d_in[2];
    const float* pb         = (const float*)d_in[3];
    float* out = (float*)d_out;

    int B = in_sizes[0] / (T_FRAMES * 64 * 64 * 3 * DIM);
    if (B < 1) B = 1;
    if (B > 2) B = 2;   // scratch sized for B=2

    cudaFuncSetAttribute(attn_kernel, cudaFuncAttributeMaxDynamicSharedMemorySize, ATTN_SMEM);
    cudaFuncSetAttribute(proj_kernel, cudaFuncAttributeMaxDynamicSharedMemorySize, PROJ_SMEM);

    dim3 ag(B * 64, HEADS);
    attn_kernel<<<ag, 640, ATTN_SMEM>>>(qkv, bias_table);

    const int nchunks = B * 64 * T_FRAMES;
    int pgrid = nchunks < 148 ? nchunks : 148;
    proj_kernel<<<pgrid, 512, PROJ_SMEM>>>(pw, pb, out, nchunks);
}